// round 1
// baseline (speedup 1.0000x reference)
#include <cuda_runtime.h>
#include <math.h>

#define Bn 8
#define CINc 128
#define COUTc 128
#define Hh 64
#define Ww 64
#define HWn 4096
#define KKn 9
#define OFFC 18

// scratch (static device globals — no allocation)
__device__ float g_xt[Bn * HWn * CINc];      // x transposed to NHWC, 16.8 MB
__device__ float g_off[Bn * OFFC * HWn];     // offset conv result, 2.36 MB
__device__ float g_scale[COUTc];
__device__ float g_shift[COUTc];

// ---------------------------------------------------------------------------
// Kernel 1: NCHW -> NHWC transpose of x (per batch, [CIN, HW] -> [HW, CIN])
// ---------------------------------------------------------------------------
__global__ void k_transpose(const float* __restrict__ x) {
    __shared__ float tile[32][33];
    int b  = blockIdx.z;
    int p0 = blockIdx.x * 32;   // spatial
    int c0 = blockIdx.y * 32;   // channel
    const float* xb  = x    + (size_t)b * CINc * HWn;
    float*       xtb = g_xt + (size_t)b * HWn * CINc;
    int tx = threadIdx.x, ty = threadIdx.y;
    #pragma unroll
    for (int j = 0; j < 32; j += 8)
        tile[ty + j][tx] = xb[(size_t)(c0 + ty + j) * HWn + p0 + tx];
    __syncthreads();
    #pragma unroll
    for (int j = 0; j < 32; j += 8)
        xtb[(size_t)(p0 + ty + j) * CINc + c0 + tx] = tile[tx][ty + j];
}

// ---------------------------------------------------------------------------
// Kernel 2: offset conv. One thread per (b, hw); each thread computes all 18
// offset channels. Weights staged in smem as [cin_local][kk][oc].
// ---------------------------------------------------------------------------
__global__ void k_offset(const float* __restrict__ x,
                         const float* __restrict__ w_off) {
    __shared__ float ws[32 * KKn * OFFC];  // 5184 floats = 20.7 KB
    int t  = blockIdx.x * 256 + threadIdx.x;   // 0 .. 32767
    int b  = t >> 12;
    int hw = t & 4095;
    int y  = hw >> 6;
    int xx = hw & 63;

    float acc[OFFC];
    #pragma unroll
    for (int i = 0; i < OFFC; i++) acc[i] = 0.f;

    const float* xb = x + (size_t)b * CINc * HWn;

    for (int c0 = 0; c0 < CINc; c0 += 32) {
        __syncthreads();
        for (int i = threadIdx.x; i < 32 * KKn * OFFC; i += 256) {
            int cl = i / (KKn * OFFC);
            int r  = i % (KKn * OFFC);
            int kk = r / OFFC;
            int oc = r % OFFC;
            ws[i] = w_off[(size_t)(oc * CINc + c0 + cl) * KKn + kk];
        }
        __syncthreads();

        for (int cl = 0; cl < 32; cl++) {
            const float* xp = xb + (size_t)(c0 + cl) * HWn;
            #pragma unroll
            for (int ky = 0; ky < 3; ky++) {
                int yy = y + ky - 1;
                if (yy < 0 || yy >= Hh) continue;
                #pragma unroll
                for (int kx = 0; kx < 3; kx++) {
                    int xc = xx + kx - 1;
                    if (xc < 0 || xc >= Ww) continue;
                    float v = xp[yy * Ww + xc];
                    const float* wrow = &ws[(cl * KKn + ky * 3 + kx) * OFFC];
                    #pragma unroll
                    for (int oc = 0; oc < OFFC; oc++)
                        acc[oc] += v * wrow[oc];
                }
            }
        }
    }

    float* ob = g_off + (size_t)b * OFFC * HWn + hw;
    #pragma unroll
    for (int oc = 0; oc < OFFC; oc++)
        ob[(size_t)oc * HWn] = acc[oc];
}

// ---------------------------------------------------------------------------
// Kernel 3: fused deform-gather + main conv.
// Block = 128 threads (thread = cout), tile = 32 contiguous pixels (one half-row).
// ---------------------------------------------------------------------------
struct __align__(16) Meta {
    int   i0, i1, i2, i3;     // base offsets into NHWC x (in floats, channel 0)
    float w0, w1, w2, w3;     // bilinear weights (0 if corner invalid)
};

__global__ __launch_bounds__(128, 5) void k_deform(
    const float* __restrict__ w_def, float* __restrict__ out) {

    __shared__ Meta  meta[KKn][32];        // 9216 B
    __shared__ float smem_s[4][KKn][32];   // 4608 B
    __shared__ float wsm[COUTc * 37];      // 18944 B (stride 37: conflict-free)

    int b   = blockIdx.y;
    int hw0 = blockIdx.x * 32;
    int y   = hw0 >> 6;
    int co  = threadIdx.x;

    // --- phase 0: bilinear metadata for the 9 taps x 32 pixels ---
    const float* offb = g_off + (size_t)b * OFFC * HWn;
    for (int t = threadIdx.x; t < KKn * 32; t += 128) {
        int kk = t >> 5;
        int p  = t & 31;
        int hw = hw0 + p;
        int xx = hw & 63;
        float dy = offb[(size_t)(kk * 2 + 0) * HWn + hw];
        float dx = offb[(size_t)(kk * 2 + 1) * HWn + hw];
        float ys = (float)(y  - 1 + kk / 3) + dy;
        float xs = (float)(xx - 1 + kk % 3) + dx;
        float y0f = floorf(ys), x0f = floorf(xs);
        float wy = ys - y0f,    wx = xs - x0f;
        int y0 = (int)y0f, x0 = (int)x0f;
        bool vy0 = (y0 >= 0)     && (y0 < Hh);
        bool vy1 = (y0 + 1 >= 0) && (y0 + 1 < Hh);
        bool vx0 = (x0 >= 0)     && (x0 < Ww);
        bool vx1 = (x0 + 1 >= 0) && (x0 + 1 < Ww);
        Meta m;
        m.w0 = (vy0 && vx0) ? (1.f - wy) * (1.f - wx) : 0.f;
        m.w1 = (vy0 && vx1) ? (1.f - wy) * wx         : 0.f;
        m.w2 = (vy1 && vx0) ? wy * (1.f - wx)         : 0.f;
        m.w3 = (vy1 && vx1) ? wy * wx                 : 0.f;
        m.i0 = (vy0 && vx0) ? (y0 * Ww + x0) * CINc             : 0;
        m.i1 = (vy0 && vx1) ? (y0 * Ww + x0 + 1) * CINc         : 0;
        m.i2 = (vy1 && vx0) ? ((y0 + 1) * Ww + x0) * CINc       : 0;
        m.i3 = (vy1 && vx1) ? ((y0 + 1) * Ww + x0 + 1) * CINc   : 0;
        meta[kk][p] = m;
    }
    __syncthreads();

    const float* xtb = g_xt + (size_t)b * HWn * CINc;

    float4 acc[8];
    #pragma unroll
    for (int i = 0; i < 8; i++) acc[i] = make_float4(0.f, 0.f, 0.f, 0.f);

    for (int c0 = 0; c0 < CINc; c0 += 4) {
        // stage weights for this 4-channel chunk: wsm[co][c*9+kk], pad 37
        for (int i = threadIdx.x; i < COUTc * 36; i += 128) {
            int row = i / 36, col = i % 36;
            wsm[row * 37 + col] = w_def[(size_t)row * (CINc * KKn) + c0 * KKn + col];
        }
        __syncthreads();  // also protects smem_s from previous iteration

        // gather sampled[4][9][32] (float4 over channels)
        for (int t = threadIdx.x; t < KKn * 32; t += 128) {
            int kk = t >> 5;
            int p  = t & 31;
            Meta m = meta[kk][p];
            const float* base = xtb + c0;
            float4 a = *(const float4*)(base + m.i0);
            float4 bb = *(const float4*)(base + m.i1);
            float4 cc = *(const float4*)(base + m.i2);
            float4 dd = *(const float4*)(base + m.i3);
            float sx = m.w0 * a.x + m.w1 * bb.x + m.w2 * cc.x + m.w3 * dd.x;
            float sy = m.w0 * a.y + m.w1 * bb.y + m.w2 * cc.y + m.w3 * dd.y;
            float sz = m.w0 * a.z + m.w1 * bb.z + m.w2 * cc.z + m.w3 * dd.z;
            float sw = m.w0 * a.w + m.w1 * bb.w + m.w2 * cc.w + m.w3 * dd.w;
            smem_s[0][kk][p] = sx;
            smem_s[1][kk][p] = sy;
            smem_s[2][kk][p] = sz;
            smem_s[3][kk][p] = sw;
        }
        __syncthreads();

        // outer-product accumulate: acc[pix] += w[co][c][kk] * s[c][kk][pix]
        const float* wrow = &wsm[co * 37];
        #pragma unroll
        for (int c = 0; c < 4; c++) {
            #pragma unroll
            for (int kk = 0; kk < KKn; kk++) {
                float w = wrow[c * 9 + kk];
                const float4* sp = (const float4*)&smem_s[c][kk][0];
                #pragma unroll
                for (int p4 = 0; p4 < 8; p4++) {
                    float4 s = sp[p4];
                    acc[p4].x += w * s.x;
                    acc[p4].y += w * s.y;
                    acc[p4].z += w * s.z;
                    acc[p4].w += w * s.w;
                }
            }
        }
        __syncthreads();
    }

    // store conv result (bias b_def is exactly absorbed by batch-norm; skip it)
    float4* op = (float4*)(out + (size_t)b * COUTc * HWn + (size_t)co * HWn + hw0);
    #pragma unroll
    for (int p4 = 0; p4 < 8; p4++) op[p4] = acc[p4];
}

// ---------------------------------------------------------------------------
// Kernel 4: per-channel mean/var -> scale/shift
// ---------------------------------------------------------------------------
__global__ void k_stats(const float* __restrict__ out,
                        const float* __restrict__ gamma,
                        const float* __restrict__ beta) {
    int co = blockIdx.x;
    float s = 0.f, sq = 0.f;
    for (int b = 0; b < Bn; b++) {
        const float* p = out + (size_t)b * COUTc * HWn + (size_t)co * HWn;
        for (int i = threadIdx.x; i < HWn; i += 256) {
            float v = p[i];
            s += v; sq += v * v;
        }
    }
    __shared__ float rs[256], rq[256];
    rs[threadIdx.x] = s; rq[threadIdx.x] = sq;
    __syncthreads();
    for (int st = 128; st > 0; st >>= 1) {
        if (threadIdx.x < st) {
            rs[threadIdx.x] += rs[threadIdx.x + st];
            rq[threadIdx.x] += rq[threadIdx.x + st];
        }
        __syncthreads();
    }
    if (threadIdx.x == 0) {
        const float inv_n = 1.f / (float)(Bn * HWn);
        float mean = rs[0] * inv_n;
        float var  = rq[0] * inv_n - mean * mean;
        float sc   = gamma[co] * rsqrtf(var + 1e-5f);
        g_scale[co] = sc;
        g_shift[co] = beta[co] - mean * sc;
    }
}

// ---------------------------------------------------------------------------
// Kernel 5: normalize + SiLU, in place (float4)
// ---------------------------------------------------------------------------
__global__ void k_norm(float* __restrict__ out) {
    int idx = blockIdx.x * 256 + threadIdx.x;
    const int n4 = Bn * COUTc * HWn / 4;
    if (idx >= n4) return;
    int co = (idx >> 10) & 127;
    float sc = g_scale[co], sh = g_shift[co];
    float4* o4 = (float4*)out;
    float4 v = o4[idx];
    float u;
    u = v.x * sc + sh; v.x = u / (1.f + expf(-u));
    u = v.y * sc + sh; v.y = u / (1.f + expf(-u));
    u = v.z * sc + sh; v.z = u / (1.f + expf(-u));
    u = v.w * sc + sh; v.w = u / (1.f + expf(-u));
    o4[idx] = v;
}

// ---------------------------------------------------------------------------
extern "C" void kernel_launch(void* const* d_in, const int* in_sizes, int n_in,
                              void* d_out, int out_size) {
    const float* x     = (const float*)d_in[0];
    const float* w_off = (const float*)d_in[1];
    const float* w_def = (const float*)d_in[2];
    // d_in[3] = b_def: exactly absorbed by batch-norm mean subtraction
    const float* gamma = (const float*)d_in[4];
    const float* beta  = (const float*)d_in[5];
    float* out = (float*)d_out;

    dim3 tb(32, 8);
    dim3 tg(HWn / 32, CINc / 32, Bn);
    k_transpose<<<tg, tb>>>(x);

    k_offset<<<(Bn * HWn) / 256, 256>>>(x, w_off);

    dim3 dg(HWn / 32, Bn);
    k_deform<<<dg, 128>>>(w_def, out);

    k_stats<<<COUTc, 256>>>(out, gamma, beta);

    k_norm<<<(Bn * COUTc * HWn / 4 + 255) / 256, 256>>>(out);
}

// round 3
// speedup vs baseline: 2.2995x; 2.2995x over previous
#include <cuda_runtime.h>
#include <math.h>
#include <stdint.h>

#define Bn 8
#define CINc 128
#define COUTc 128
#define Hh 64
#define Ww 64
#define HWn 4096
#define KKn 9
#define OFFC 18
#define Kdim 1152            // CIN * KK
#define NPIX 32768           // B * HW
#define TILE_N 256           // pixels per GEMM CTA
#define NCHUNK 36            // Kdim / 32
#define AS_STRIDE 136        // floats per k-row (128 + pad 8)
#define BS_STRIDE 36         // floats per pix-row (32 + pad 4)
#define AS_FLOATS (32 * AS_STRIDE)   // 4352 per stage
#define BS_FLOATS (TILE_N * BS_STRIDE) // 9216 per stage
#define GEMM_SMEM ((2 * AS_FLOATS + 2 * BS_FLOATS) * 4)  // 108544 B

// ---------------- static scratch ----------------
__device__ float g_xt[Bn * HWn * CINc];         // x NHWC (16.8 MB)
__device__ float g_off[Bn * OFFC * HWn];        // offset conv out
__device__ float g_wt[Kdim * COUTc];            // w_def as [k][co], tf32-rounded
__device__ float g_im2col[(size_t)NPIX * Kdim]; // sampled im2col [pix][k] (151 MB)
__device__ float g_psum[COUTc * 128];
__device__ float g_psq [COUTc * 128];
__device__ float g_scale[COUTc];
__device__ float g_shift[COUTc];

// ---------------- helpers ----------------
__device__ __forceinline__ uint32_t smem_u32(const void* p) {
    uint32_t a;
    asm("{ .reg .u64 t; cvta.to.shared.u64 t, %1; cvt.u32.u64 %0, t; }" : "=r"(a) : "l"(p));
    return a;
}
__device__ __forceinline__ float tf32r(float x) {
    uint32_t u;
    asm("cvt.rna.tf32.f32 %0, %1;" : "=r"(u) : "f"(x));
    return __uint_as_float(u);
}
__device__ __forceinline__ void cp16(uint32_t dst, const void* src) {
    asm volatile("cp.async.cg.shared.global [%0], [%1], 16;" :: "r"(dst), "l"(src));
}

// ---------------------------------------------------------------------------
// Kernel 1: NCHW -> NHWC transpose
// ---------------------------------------------------------------------------
__global__ void k_transpose(const float* __restrict__ x) {
    __shared__ float tile[32][33];
    int b = blockIdx.z, p0 = blockIdx.x * 32, c0 = blockIdx.y * 32;
    const float* xb = x + (size_t)b * CINc * HWn;
    float* xtb = g_xt + (size_t)b * HWn * CINc;
    int tx = threadIdx.x, ty = threadIdx.y;
    #pragma unroll
    for (int j = 0; j < 32; j += 8)
        tile[ty + j][tx] = xb[(size_t)(c0 + ty + j) * HWn + p0 + tx];
    __syncthreads();
    #pragma unroll
    for (int j = 0; j < 32; j += 8)
        xtb[(size_t)(p0 + ty + j) * CINc + c0 + tx] = tile[tx][ty + j];
}

// ---------------------------------------------------------------------------
// Kernel 2: weights -> g_wt[k][co] = tf32(w_def[co][c][kk]),  k = kk*128 + c
// ---------------------------------------------------------------------------
__global__ void k_wprep(const float* __restrict__ w_def) {
    int idx = blockIdx.x * 256 + threadIdx.x;
    if (idx >= Kdim * COUTc) return;
    int co = idx & 127, k = idx >> 7;
    int kk = k >> 7, c = k & 127;
    g_wt[idx] = tf32r(w_def[(size_t)(co * CINc + c) * KKn + kk]);
}

// ---------------------------------------------------------------------------
// Kernel 3: offset conv (scalar, 18 output channels)
// ---------------------------------------------------------------------------
__global__ void k_offset(const float* __restrict__ x, const float* __restrict__ w_off) {
    __shared__ float ws[32 * KKn * OFFC];
    int t = blockIdx.x * 256 + threadIdx.x;
    int b = t >> 12, hw = t & 4095, y = hw >> 6, xx = hw & 63;
    float acc[OFFC];
    #pragma unroll
    for (int i = 0; i < OFFC; i++) acc[i] = 0.f;
    const float* xb = x + (size_t)b * CINc * HWn;
    for (int c0 = 0; c0 < CINc; c0 += 32) {
        __syncthreads();
        for (int i = threadIdx.x; i < 32 * KKn * OFFC; i += 256) {
            int cl = i / (KKn * OFFC), r = i % (KKn * OFFC);
            int kk = r / OFFC, oc = r % OFFC;
            ws[i] = w_off[(size_t)(oc * CINc + c0 + cl) * KKn + kk];
        }
        __syncthreads();
        for (int cl = 0; cl < 32; cl++) {
            const float* xp = xb + (size_t)(c0 + cl) * HWn;
            #pragma unroll
            for (int ky = 0; ky < 3; ky++) {
                int yy = y + ky - 1;
                if (yy < 0 || yy >= Hh) continue;
                #pragma unroll
                for (int kx = 0; kx < 3; kx++) {
                    int xc = xx + kx - 1;
                    if (xc < 0 || xc >= Ww) continue;
                    float v = xp[yy * Ww + xc];
                    const float* wrow = &ws[(cl * KKn + ky * 3 + kx) * OFFC];
                    #pragma unroll
                    for (int oc = 0; oc < OFFC; oc++) acc[oc] += v * wrow[oc];
                }
            }
        }
    }
    float* ob = g_off + (size_t)b * OFFC * HWn + hw;
    #pragma unroll
    for (int oc = 0; oc < OFFC; oc++) ob[(size_t)oc * HWn] = acc[oc];
}

// ---------------------------------------------------------------------------
// Kernel 4: bilinear gather -> im2col [pix][kk*128+c], tf32-rounded
// ---------------------------------------------------------------------------
struct __align__(16) Meta {
    int   i0, i1, i2, i3;
    float w0, w1, w2, w3;
};

__global__ __launch_bounds__(256) void k_gather() {
    __shared__ Meta meta[KKn][32];
    int bpix = blockIdx.x * 32;
    int b = bpix >> 12, hw0 = bpix & 4095, y = hw0 >> 6;

    const float* offb = g_off + (size_t)b * OFFC * HWn;
    for (int t = threadIdx.x; t < KKn * 32; t += 256) {
        int kk = t >> 5, p = t & 31;
        int hw = hw0 + p, xx = hw & 63;
        float dy = offb[(size_t)(kk * 2 + 0) * HWn + hw];
        float dx = offb[(size_t)(kk * 2 + 1) * HWn + hw];
        float ys = (float)(y - 1 + kk / 3) + dy;
        float xs = (float)(xx - 1 + kk % 3) + dx;
        float y0f = floorf(ys), x0f = floorf(xs);
        float wy = ys - y0f, wx = xs - x0f;
        int y0 = (int)y0f, x0 = (int)x0f;
        bool vy0 = (y0 >= 0) && (y0 < Hh);
        bool vy1 = (y0 + 1 >= 0) && (y0 + 1 < Hh);
        bool vx0 = (x0 >= 0) && (x0 < Ww);
        bool vx1 = (x0 + 1 >= 0) && (x0 + 1 < Ww);
        Meta m;
        m.w0 = (vy0 && vx0) ? (1.f - wy) * (1.f - wx) : 0.f;
        m.w1 = (vy0 && vx1) ? (1.f - wy) * wx : 0.f;
        m.w2 = (vy1 && vx0) ? wy * (1.f - wx) : 0.f;
        m.w3 = (vy1 && vx1) ? wy * wx : 0.f;
        m.i0 = (vy0 && vx0) ? (y0 * Ww + x0) * CINc : 0;
        m.i1 = (vy0 && vx1) ? (y0 * Ww + x0 + 1) * CINc : 0;
        m.i2 = (vy1 && vx0) ? ((y0 + 1) * Ww + x0) * CINc : 0;
        m.i3 = (vy1 && vx1) ? ((y0 + 1) * Ww + x0 + 1) * CINc : 0;
        meta[kk][p] = m;
    }
    __syncthreads();

    const float* xtb = g_xt + (size_t)b * HWn * CINc;
    int wid = threadIdx.x >> 5, lane = threadIdx.x & 31;
    for (int u = wid; u < KKn * 32; u += 8) {
        int kk = u >> 5, p = u & 31;
        Meta m = meta[kk][p];
        const float* base = xtb + 4 * lane;
        float4 a  = *(const float4*)(base + m.i0);
        float4 bb = *(const float4*)(base + m.i1);
        float4 cc = *(const float4*)(base + m.i2);
        float4 dd = *(const float4*)(base + m.i3);
        float4 s;
        s.x = tf32r(m.w0 * a.x + m.w1 * bb.x + m.w2 * cc.x + m.w3 * dd.x);
        s.y = tf32r(m.w0 * a.y + m.w1 * bb.y + m.w2 * cc.y + m.w3 * dd.y);
        s.z = tf32r(m.w0 * a.z + m.w1 * bb.z + m.w2 * cc.z + m.w3 * dd.z);
        s.w = tf32r(m.w0 * a.w + m.w1 * bb.w + m.w2 * cc.w + m.w3 * dd.w);
        size_t pix = (size_t)(bpix + p);
        *(float4*)(g_im2col + pix * Kdim + kk * 128 + 4 * lane) = s;
    }
}

// ---------------------------------------------------------------------------
// Kernel 5: tf32 mma.sync GEMM  D[128co, 256pix] = W[128, K] x S[K, 256]
// 512 threads = 16 warps (2m x 8n), warp tile 64co x 32pix, m16n8k8.
// ---------------------------------------------------------------------------
__global__ __launch_bounds__(512, 1) void k_gemm(float* __restrict__ out) {
    extern __shared__ float smem[];
    // layout: As[2][32][136] then Bs[2][256][36]
    const uint32_t sbase = smem_u32(smem);
    const uint32_t sA = sbase;
    const uint32_t sB = sbase + 2 * AS_FLOATS * 4;
    float* As = smem;
    float* Bs = smem + 2 * AS_FLOATS;

    const int tid = threadIdx.x;
    const int wid = tid >> 5, lane = tid & 31;
    const int wm = wid >> 3, wn = wid & 7;
    const int ar = lane >> 2, ac = lane & 3;
    const int tilebase = blockIdx.x * TILE_N;

    float acc[4][4][4];
    #pragma unroll
    for (int mt = 0; mt < 4; mt++)
        #pragma unroll
        for (int nt = 0; nt < 4; nt++)
            #pragma unroll
            for (int r = 0; r < 4; r++) acc[mt][nt][r] = 0.f;

    // ---- async stage loader: 3072 cp16 per stage, 6 per thread ----
    auto load_stage = [&](int chunk, int st) {
        #pragma unroll
        for (int m = 0; m < 6; m++) {
            int idx = tid + m * 512;
            if (idx < 1024) {
                int k = idx >> 5, j = idx & 31;
                cp16(sA + (st * AS_FLOATS + k * AS_STRIDE + j * 4) * 4,
                     g_wt + (size_t)chunk * 4096 + k * 128 + j * 4);
            } else {
                int i2 = idx - 1024;
                int row = i2 >> 3, j = i2 & 7;
                cp16(sB + (st * BS_FLOATS + row * BS_STRIDE + j * 4) * 4,
                     g_im2col + (size_t)(tilebase + row) * Kdim + chunk * 32 + j * 4);
            }
        }
    };

    load_stage(0, 0);
    asm volatile("cp.async.commit_group;" ::: "memory");

    for (int i = 0; i < NCHUNK; i++) {
        int st = i & 1;
        if (i + 1 < NCHUNK) {
            load_stage(i + 1, st ^ 1);
            asm volatile("cp.async.commit_group;" ::: "memory");
            asm volatile("cp.async.wait_group 1;" ::: "memory");
        } else {
            asm volatile("cp.async.wait_group 0;" ::: "memory");
        }
        __syncthreads();

        const float* as = As + st * AS_FLOATS;
        const float* bs = Bs + st * BS_FLOATS;
        #pragma unroll
        for (int ks = 0; ks < 4; ks++) {
            uint32_t a[4][4];
            #pragma unroll
            for (int mt = 0; mt < 4; mt++) {
                const float* ap = as + (ks * 8 + ac) * AS_STRIDE + wm * 64 + mt * 16 + ar;
                a[mt][0] = __float_as_uint(ap[0]);
                a[mt][1] = __float_as_uint(ap[8]);
                a[mt][2] = __float_as_uint(ap[4 * AS_STRIDE]);
                a[mt][3] = __float_as_uint(ap[4 * AS_STRIDE + 8]);
            }
            #pragma unroll
            for (int nt = 0; nt < 4; nt++) {
                const float* bp = bs + (wn * 32 + nt * 8 + ar) * BS_STRIDE + ks * 8 + ac;
                uint32_t b0 = __float_as_uint(bp[0]);
                uint32_t b1 = __float_as_uint(bp[4]);
                #pragma unroll
                for (int mt = 0; mt < 4; mt++) {
                    asm volatile(
                        "mma.sync.aligned.m16n8k8.row.col.f32.tf32.tf32.f32 "
                        "{%0,%1,%2,%3}, {%4,%5,%6,%7}, {%8,%9}, {%0,%1,%2,%3};"
                        : "+f"(acc[mt][nt][0]), "+f"(acc[mt][nt][1]),
                          "+f"(acc[mt][nt][2]), "+f"(acc[mt][nt][3])
                        : "r"(a[mt][0]), "r"(a[mt][1]), "r"(a[mt][2]), "r"(a[mt][3]),
                          "r"(b0), "r"(b1));
                }
            }
        }
        __syncthreads();
    }

    // ---- store results (float2 per fragment row) ----
    const int b = tilebase >> 12, hw0 = tilebase & 4095;
    #pragma unroll
    for (int mt = 0; mt < 4; mt++) {
        #pragma unroll
        for (int nt = 0; nt < 4; nt++) {
            int pix = hw0 + wn * 32 + nt * 8 + ac * 2;
            int co0 = wm * 64 + mt * 16 + ar;
            float2 v0 = make_float2(acc[mt][nt][0], acc[mt][nt][1]);
            float2 v1 = make_float2(acc[mt][nt][2], acc[mt][nt][3]);
            *(float2*)&out[((size_t)b * COUTc + co0) * HWn + pix] = v0;
            *(float2*)&out[((size_t)b * COUTc + co0 + 8) * HWn + pix] = v1;
        }
    }

    // ---- deterministic BN partials ----
    float s[8], q[8];
    #pragma unroll
    for (int i = 0; i < 8; i++) { s[i] = 0.f; q[i] = 0.f; }
    #pragma unroll
    for (int mt = 0; mt < 4; mt++)
        #pragma unroll
        for (int r = 0; r < 2; r++) {
            int sl = mt * 2 + r;
            #pragma unroll
            for (int nt = 0; nt < 4; nt++) {
                float v0 = acc[mt][nt][r * 2], v1 = acc[mt][nt][r * 2 + 1];
                s[sl] += v0 + v1;
                q[sl] += v0 * v0 + v1 * v1;
            }
        }
    #pragma unroll
    for (int m = 1; m <= 2; m <<= 1)
        #pragma unroll
        for (int i = 0; i < 8; i++) {
            s[i] += __shfl_xor_sync(0xFFFFFFFF, s[i], m);
            q[i] += __shfl_xor_sync(0xFFFFFFFF, q[i], m);
        }

    __syncthreads();               // done with As/Bs; reuse smem
    float* sb = smem;              // [16][64]
    float* qb = smem + 1024;       // [16][64]
    if (ac == 0) {
        #pragma unroll
        for (int mt = 0; mt < 4; mt++)
            #pragma unroll
            for (int r = 0; r < 2; r++) {
                int cl = mt * 16 + r * 8 + ar;
                sb[wid * 64 + cl] = s[mt * 2 + r];
                qb[wid * 64 + cl] = q[mt * 2 + r];
            }
    }
    __syncthreads();
    if (tid < COUTc) {
        int co = tid;
        float ss = 0.f, qq = 0.f;
        #pragma unroll
        for (int w = 0; w < 8; w++) {
            ss += sb[((co >> 6) * 8 + w) * 64 + (co & 63)];
            qq += qb[((co >> 6) * 8 + w) * 64 + (co & 63)];
        }
        g_psum[co * 128 + blockIdx.x] = ss;
        g_psq [co * 128 + blockIdx.x] = qq;
    }
}

// ---------------------------------------------------------------------------
// Kernel 6: finalize BN stats
// ---------------------------------------------------------------------------
__global__ void k_statsfin(const float* __restrict__ gamma, const float* __restrict__ beta) {
    int co = threadIdx.x;
    float s = 0.f, q = 0.f;
    for (int j = 0; j < 128; j++) { s += g_psum[co * 128 + j]; q += g_psq[co * 128 + j]; }
    const float inv_n = 1.f / (float)NPIX;
    float mean = s * inv_n;
    float var  = q * inv_n - mean * mean;
    float sc   = gamma[co] * rsqrtf(var + 1e-5f);
    g_scale[co] = sc;
    g_shift[co] = beta[co] - mean * sc;
}

// ---------------------------------------------------------------------------
// Kernel 7: normalize + SiLU (in place)
// ---------------------------------------------------------------------------
__global__ void k_norm(float* __restrict__ out) {
    int idx = blockIdx.x * 256 + threadIdx.x;
    const int n4 = Bn * COUTc * HWn / 4;
    if (idx >= n4) return;
    int co = (idx >> 10) & 127;
    float sc = g_scale[co], sh = g_shift[co];
    float4* o4 = (float4*)out;
    float4 v = o4[idx];
    float u;
    u = v.x * sc + sh; v.x = u / (1.f + expf(-u));
    u = v.y * sc + sh; v.y = u / (1.f + expf(-u));
    u = v.z * sc + sh; v.z = u / (1.f + expf(-u));
    u = v.w * sc + sh; v.w = u / (1.f + expf(-u));
    o4[idx] = v;
}

// ---------------------------------------------------------------------------
extern "C" void kernel_launch(void* const* d_in, const int* in_sizes, int n_in,
                              void* d_out, int out_size) {
    const float* x     = (const float*)d_in[0];
    const float* w_off = (const float*)d_in[1];
    const float* w_def = (const float*)d_in[2];
    // d_in[3] = b_def: exactly absorbed by batch-norm mean subtraction
    const float* gamma = (const float*)d_in[4];
    const float* beta  = (const float*)d_in[5];
    float* out = (float*)d_out;

    cudaFuncSetAttribute(k_gemm, cudaFuncAttributeMaxDynamicSharedMemorySize, GEMM_SMEM);

    dim3 tb(32, 8);
    dim3 tg(HWn / 32, CINc / 32, Bn);
    k_transpose<<<tg, tb>>>(x);

    k_wprep<<<(Kdim * COUTc + 255) / 256, 256>>>(w_def);

    k_offset<<<(Bn * HWn) / 256, 256>>>(x, w_off);

    k_gather<<<NPIX / 32, 256>>>();

    k_gemm<<<NPIX / TILE_N, 512, GEMM_SMEM>>>(out);

    k_statsfin<<<1, 128>>>(gamma, beta);

    k_norm<<<(Bn * COUTc * HWn / 4 + 255) / 256, 256>>>(out);
}

// round 4
// speedup vs baseline: 3.7567x; 1.6337x over previous
#include <cuda_runtime.h>
#include <math.h>
#include <stdint.h>

#define Bn 8
#define CINc 128
#define COUTc 128
#define Hh 64
#define Ww 64
#define HWn 4096
#define KKn 9
#define OFFC 18
#define Kdim 1152            // CIN * KK
#define NPIX 32768           // B * HW
#define TILE_N 256           // pixels per GEMM CTA
#define NCHUNK 36            // Kdim / 32
#define AS_STRIDE 136        // floats per k-row (128 + pad 8) -> banks (8ac+ar)
#define BS_STRIDE 36         // floats per pix-row (32 + pad 4) -> banks (4ar+ac)
#define AS_FLOATS (32 * AS_STRIDE)      // 4352 per stage
#define BS_FLOATS (TILE_N * BS_STRIDE)  // 9216 per stage
#define STG_FLOATS (AS_FLOATS + BS_FLOATS)
#define GEMM_SMEM (3 * STG_FLOATS * 4)  // 162816 B (3-stage)

// offset implicit-GEMM tiles
#define OAS_STRIDE 40        // 32 oc + pad 8 -> banks (8ac+ar)
#define OAS_FLOATS (32 * OAS_STRIDE)    // 1280
#define OBS_FLOATS (256 * BS_STRIDE)    // 9216
#define OSTG_FLOATS (OAS_FLOATS + OBS_FLOATS)
#define OFF_SMEM (3 * OSTG_FLOATS * 4)  // 125952 B

// ---------------- static scratch ----------------
__device__ float g_xt[Bn * HWn * CINc];         // x NHWC (16.8 MB)
__device__ float g_off[Bn * OFFC * HWn];        // offset conv out
__device__ float g_wt[Kdim * COUTc];            // w_def as [k][co], tf32
__device__ float g_woff2[Kdim * 32];            // w_off as [k][oc32pad], tf32
__device__ float g_im2col[(size_t)NPIX * Kdim]; // im2col [pix][k] (151 MB)
__device__ float g_psum[COUTc * 128];
__device__ float g_psq [COUTc * 128];
__device__ float g_scale[COUTc];
__device__ float g_shift[COUTc];

// ---------------- helpers ----------------
__device__ __forceinline__ float tf32r(float x) {
    uint32_t u;
    asm("cvt.rna.tf32.f32 %0, %1;" : "=r"(u) : "f"(x));
    return __uint_as_float(u);
}
__device__ __forceinline__ void mma_tf32(float* d, const uint32_t* a,
                                         uint32_t b0, uint32_t b1) {
    asm volatile(
        "mma.sync.aligned.m16n8k8.row.col.f32.tf32.tf32.f32 "
        "{%0,%1,%2,%3}, {%4,%5,%6,%7}, {%8,%9}, {%0,%1,%2,%3};"
        : "+f"(d[0]), "+f"(d[1]), "+f"(d[2]), "+f"(d[3])
        : "r"(a[0]), "r"(a[1]), "r"(a[2]), "r"(a[3]), "r"(b0), "r"(b1));
}

// ---------------------------------------------------------------------------
// Kernel 1: NCHW -> NHWC transpose
// ---------------------------------------------------------------------------
__global__ void k_transpose(const float* __restrict__ x) {
    __shared__ float tile[32][33];
    int b = blockIdx.z, p0 = blockIdx.x * 32, c0 = blockIdx.y * 32;
    const float* xb = x + (size_t)b * CINc * HWn;
    float* xtb = g_xt + (size_t)b * HWn * CINc;
    int tx = threadIdx.x, ty = threadIdx.y;
    #pragma unroll
    for (int j = 0; j < 32; j += 8)
        tile[ty + j][tx] = xb[(size_t)(c0 + ty + j) * HWn + p0 + tx];
    __syncthreads();
    #pragma unroll
    for (int j = 0; j < 32; j += 8)
        xtb[(size_t)(p0 + ty + j) * CINc + c0 + tx] = tile[tx][ty + j];
}

// ---------------------------------------------------------------------------
// Kernel 2a: w_def -> g_wt[k][co], k = kk*128+c, tf32
// ---------------------------------------------------------------------------
__global__ void k_wprep(const float* __restrict__ w_def) {
    int idx = blockIdx.x * 256 + threadIdx.x;
    if (idx >= Kdim * COUTc) return;
    int co = idx & 127, k = idx >> 7;
    int kk = k >> 7, c = k & 127;
    g_wt[idx] = tf32r(w_def[(size_t)(co * CINc + c) * KKn + kk]);
}

// Kernel 2b: w_off -> g_woff2[k][oc32], zero-padded 18->32, tf32
__global__ void k_wprep2(const float* __restrict__ w_off) {
    int idx = blockIdx.x * 256 + threadIdx.x;
    if (idx >= Kdim * 32) return;
    int oc = idx & 31, k = idx >> 5;
    int kk = k >> 7, c = k & 127;
    g_woff2[idx] = (oc < OFFC)
        ? tf32r(w_off[(size_t)(oc * CINc + c) * KKn + kk]) : 0.f;
}

// ---------------------------------------------------------------------------
// Kernel 3: offset conv as implicit GEMM  D[32oc, 256pix] = Woff x im2col_reg
// 256 threads = 8 warps, warp tile 32oc x 32pix, m16n8k8 tf32.
// B tile built from g_xt with predicated LDG (zero outside image).
// ---------------------------------------------------------------------------
__global__ __launch_bounds__(256, 1) void k_offset2() {
    extern __shared__ float smem[];
    const int tid = threadIdx.x;
    const int wid = tid >> 5, lane = tid & 31;
    const int wn = wid;                    // 8 n-warps
    const int ar = lane >> 2, ac = lane & 3;

    const int tile = blockIdx.x;           // 0..127
    const int b = tile >> 4;
    const int hw0 = (tile & 15) * 256;     // 4 rows of 64
    const int y0 = hw0 >> 6;
    const float* xtb = g_xt + (size_t)b * HWn * CINc;

    // per-thread B-load coords: 8 float4/chunk; e = tid + j*256
    // pix = e>>3 (0..255), cq = e&7
    float4 bufB[8];
    float4 bufA;                           // 1 float4/chunk: k=tid>>3, ocq=tid&7

    float acc[2][4][4];
    #pragma unroll
    for (int mt = 0; mt < 2; mt++)
        #pragma unroll
        for (int nt = 0; nt < 4; nt++)
            #pragma unroll
            for (int r = 0; r < 4; r++) acc[mt][nt][r] = 0.f;

    auto ldg_chunk = [&](int i) {
        int kk = i >> 2, c0 = (i & 3) * 32;
        int ky = kk / 3 - 1, kx = kk % 3 - 1;
        #pragma unroll
        for (int j = 0; j < 8; j++) {
            int e = tid + j * 256;
            int p = e >> 3, cq = e & 7;
            int y = y0 + (p >> 6), xx = p & 63;
            int ys = y + ky, xs = xx + kx;
            bool valid = ((unsigned)ys < Hh) && ((unsigned)xs < Ww);
            bufB[j] = valid
                ? *(const float4*)(xtb + (size_t)(ys * Ww + xs) * CINc + c0 + cq * 4)
                : make_float4(0.f, 0.f, 0.f, 0.f);
        }
        bufA = *(const float4*)(g_woff2 + (size_t)(i * 32 + (tid >> 3)) * 32 + (tid & 7) * 4);
    };
    auto sts_chunk = [&](int st) {
        float* As = smem + st * OSTG_FLOATS;
        float* Bs = As + OAS_FLOATS;
        #pragma unroll
        for (int j = 0; j < 8; j++) {
            int e = tid + j * 256;
            int p = e >> 3, cq = e & 7;
            *(float4*)(Bs + p * BS_STRIDE + cq * 4) = bufB[j];
        }
        *(float4*)(As + (tid >> 3) * OAS_STRIDE + (tid & 7) * 4) = bufA;
    };

    ldg_chunk(0); sts_chunk(0);
    ldg_chunk(1); sts_chunk(1);
    __syncthreads();

    for (int i = 0; i < NCHUNK; i++) {
        if (i + 2 < NCHUNK) ldg_chunk(i + 2);
        const float* As = smem + (i % 3) * OSTG_FLOATS;
        const float* Bs = As + OAS_FLOATS;
        #pragma unroll
        for (int ks = 0; ks < 4; ks++) {
            uint32_t a[2][4];
            #pragma unroll
            for (int mt = 0; mt < 2; mt++) {
                const float* ap = As + (ks * 8 + ac) * OAS_STRIDE + mt * 16 + ar;
                a[mt][0] = __float_as_uint(ap[0]);
                a[mt][1] = __float_as_uint(ap[8]);
                a[mt][2] = __float_as_uint(ap[4 * OAS_STRIDE]);
                a[mt][3] = __float_as_uint(ap[4 * OAS_STRIDE + 8]);
            }
            #pragma unroll
            for (int nt = 0; nt < 4; nt++) {
                const float* bp = Bs + (wn * 32 + nt * 8 + ar) * BS_STRIDE + ks * 8 + ac;
                uint32_t b0 = __float_as_uint(bp[0]);
                uint32_t b1 = __float_as_uint(bp[4]);
                #pragma unroll
                for (int mt = 0; mt < 2; mt++)
                    mma_tf32(acc[mt][nt], a[mt], b0, b1);
            }
        }
        if (i + 2 < NCHUNK) sts_chunk((i + 2) % 3);
        __syncthreads();
    }

    // store rows < 18 to g_off[b][oc][hw]
    float* ob = g_off + (size_t)b * OFFC * HWn;
    #pragma unroll
    for (int mt = 0; mt < 2; mt++) {
        #pragma unroll
        for (int nt = 0; nt < 4; nt++) {
            int pix = hw0 + wn * 32 + nt * 8 + ac * 2;
            int r0 = mt * 16 + ar, r1 = r0 + 8;
            if (r0 < OFFC)
                *(float2*)&ob[(size_t)r0 * HWn + pix] =
                    make_float2(acc[mt][nt][0], acc[mt][nt][1]);
            if (r1 < OFFC)
                *(float2*)&ob[(size_t)r1 * HWn + pix] =
                    make_float2(acc[mt][nt][2], acc[mt][nt][3]);
        }
    }
}

// ---------------------------------------------------------------------------
// Kernel 4: bilinear gather -> im2col [pix][kk*128+c], tf32-rounded
// ---------------------------------------------------------------------------
struct __align__(16) Meta {
    int   i0, i1, i2, i3;
    float w0, w1, w2, w3;
};

__global__ __launch_bounds__(256) void k_gather() {
    __shared__ Meta meta[KKn][32];
    int bpix = blockIdx.x * 32;
    int b = bpix >> 12, hw0 = bpix & 4095, y = hw0 >> 6;

    const float* offb = g_off + (size_t)b * OFFC * HWn;
    for (int t = threadIdx.x; t < KKn * 32; t += 256) {
        int kk = t >> 5, p = t & 31;
        int hw = hw0 + p, xx = hw & 63;
        float dy = offb[(size_t)(kk * 2 + 0) * HWn + hw];
        float dx = offb[(size_t)(kk * 2 + 1) * HWn + hw];
        float ys = (float)(y - 1 + kk / 3) + dy;
        float xs = (float)(xx - 1 + kk % 3) + dx;
        float y0f = floorf(ys), x0f = floorf(xs);
        float wy = ys - y0f, wx = xs - x0f;
        int y0 = (int)y0f, x0 = (int)x0f;
        bool vy0 = (y0 >= 0) && (y0 < Hh);
        bool vy1 = (y0 + 1 >= 0) && (y0 + 1 < Hh);
        bool vx0 = (x0 >= 0) && (x0 < Ww);
        bool vx1 = (x0 + 1 >= 0) && (x0 + 1 < Ww);
        Meta m;
        m.w0 = (vy0 && vx0) ? (1.f - wy) * (1.f - wx) : 0.f;
        m.w1 = (vy0 && vx1) ? (1.f - wy) * wx : 0.f;
        m.w2 = (vy1 && vx0) ? wy * (1.f - wx) : 0.f;
        m.w3 = (vy1 && vx1) ? wy * wx : 0.f;
        m.i0 = (vy0 && vx0) ? (y0 * Ww + x0) * CINc : 0;
        m.i1 = (vy0 && vx1) ? (y0 * Ww + x0 + 1) * CINc : 0;
        m.i2 = (vy1 && vx0) ? ((y0 + 1) * Ww + x0) * CINc : 0;
        m.i3 = (vy1 && vx1) ? ((y0 + 1) * Ww + x0 + 1) * CINc : 0;
        meta[kk][p] = m;
    }
    __syncthreads();

    const float* xtb = g_xt + (size_t)b * HWn * CINc;
    int wid = threadIdx.x >> 5, lane = threadIdx.x & 31;
    for (int u = wid; u < KKn * 32; u += 8) {
        int kk = u >> 5, p = u & 31;
        Meta m = meta[kk][p];
        const float* base = xtb + 4 * lane;
        float4 a  = *(const float4*)(base + m.i0);
        float4 bb = *(const float4*)(base + m.i1);
        float4 cc = *(const float4*)(base + m.i2);
        float4 dd = *(const float4*)(base + m.i3);
        float4 s;
        s.x = tf32r(m.w0 * a.x + m.w1 * bb.x + m.w2 * cc.x + m.w3 * dd.x);
        s.y = tf32r(m.w0 * a.y + m.w1 * bb.y + m.w2 * cc.y + m.w3 * dd.y);
        s.z = tf32r(m.w0 * a.z + m.w1 * bb.z + m.w2 * cc.z + m.w3 * dd.z);
        s.w = tf32r(m.w0 * a.w + m.w1 * bb.w + m.w2 * cc.w + m.w3 * dd.w);
        size_t pix = (size_t)(bpix + p);
        *(float4*)(g_im2col + pix * Kdim + kk * 128 + 4 * lane) = s;
    }
}

// ---------------------------------------------------------------------------
// Kernel 5: tf32 mma.sync GEMM  D[128co, 256pix] = W[128, K] x S[K, 256]
// 512 threads = 16 warps (2m x 8n); LDG.128 -> regs -> STS.128, 3-stage ring.
// ---------------------------------------------------------------------------
__global__ __launch_bounds__(512, 1) void k_gemm(float* __restrict__ out) {
    extern __shared__ float smem[];
    const int tid = threadIdx.x;
    const int wid = tid >> 5, lane = tid & 31;
    const int wm = wid >> 3, wn = wid & 7;
    const int ar = lane >> 2, ac = lane & 3;
    const int tilebase = blockIdx.x * TILE_N;

    float acc[4][4][4];
    #pragma unroll
    for (int mt = 0; mt < 4; mt++)
        #pragma unroll
        for (int nt = 0; nt < 4; nt++)
            #pragma unroll
            for (int r = 0; r < 4; r++) acc[mt][nt][r] = 0.f;

    // per-thread staging: A 2 float4 (e=tid+m*512: k=e>>5, j=e&31),
    //                     B 4 float4 (e=tid+m*512: row=e>>3, j=e&7)
    float4 bufA[2], bufB[4];

    auto ldg_chunk = [&](int i) {
        #pragma unroll
        for (int m = 0; m < 2; m++) {
            int e = tid + m * 512;
            bufA[m] = *(const float4*)(g_wt + (size_t)i * 4096 + (e >> 5) * 128 + (e & 31) * 4);
        }
        #pragma unroll
        for (int m = 0; m < 4; m++) {
            int e = tid + m * 512;
            bufB[m] = *(const float4*)(g_im2col +
                (size_t)(tilebase + (e >> 3)) * Kdim + i * 32 + (e & 7) * 4);
        }
    };
    auto sts_chunk = [&](int st) {
        float* As = smem + st * STG_FLOATS;
        float* Bs = As + AS_FLOATS;
        #pragma unroll
        for (int m = 0; m < 2; m++) {
            int e = tid + m * 512;
            *(float4*)(As + (e >> 5) * AS_STRIDE + (e & 31) * 4) = bufA[m];
        }
        #pragma unroll
        for (int m = 0; m < 4; m++) {
            int e = tid + m * 512;
            *(float4*)(Bs + (e >> 3) * BS_STRIDE + (e & 7) * 4) = bufB[m];
        }
    };

    ldg_chunk(0); sts_chunk(0);
    ldg_chunk(1); sts_chunk(1);
    __syncthreads();

    for (int i = 0; i < NCHUNK; i++) {
        if (i + 2 < NCHUNK) ldg_chunk(i + 2);

        const float* As = smem + (i % 3) * STG_FLOATS;
        const float* Bs = As + AS_FLOATS;
        #pragma unroll
        for (int ks = 0; ks < 4; ks++) {
            uint32_t a[4][4];
            #pragma unroll
            for (int mt = 0; mt < 4; mt++) {
                const float* ap = As + (ks * 8 + ac) * AS_STRIDE + wm * 64 + mt * 16 + ar;
                a[mt][0] = __float_as_uint(ap[0]);
                a[mt][1] = __float_as_uint(ap[8]);
                a[mt][2] = __float_as_uint(ap[4 * AS_STRIDE]);
                a[mt][3] = __float_as_uint(ap[4 * AS_STRIDE + 8]);
            }
            #pragma unroll
            for (int nt = 0; nt < 4; nt++) {
                const float* bp = Bs + (wn * 32 + nt * 8 + ar) * BS_STRIDE + ks * 8 + ac;
                uint32_t b0 = __float_as_uint(bp[0]);
                uint32_t b1 = __float_as_uint(bp[4]);
                #pragma unroll
                for (int mt = 0; mt < 4; mt++)
                    mma_tf32(acc[mt][nt], a[mt], b0, b1);
            }
        }
        if (i + 2 < NCHUNK) sts_chunk((i + 2) % 3);
        __syncthreads();
    }

    // ---- store results ----
    const int b = tilebase >> 12, hw0 = tilebase & 4095;
    #pragma unroll
    for (int mt = 0; mt < 4; mt++) {
        #pragma unroll
        for (int nt = 0; nt < 4; nt++) {
            int pix = hw0 + wn * 32 + nt * 8 + ac * 2;
            int co0 = wm * 64 + mt * 16 + ar;
            *(float2*)&out[((size_t)b * COUTc + co0) * HWn + pix] =
                make_float2(acc[mt][nt][0], acc[mt][nt][1]);
            *(float2*)&out[((size_t)b * COUTc + co0 + 8) * HWn + pix] =
                make_float2(acc[mt][nt][2], acc[mt][nt][3]);
        }
    }

    // ---- deterministic BN partials ----
    float s[8], q[8];
    #pragma unroll
    for (int i = 0; i < 8; i++) { s[i] = 0.f; q[i] = 0.f; }
    #pragma unroll
    for (int mt = 0; mt < 4; mt++)
        #pragma unroll
        for (int r = 0; r < 2; r++) {
            int sl = mt * 2 + r;
            #pragma unroll
            for (int nt = 0; nt < 4; nt++) {
                float v0 = acc[mt][nt][r * 2], v1 = acc[mt][nt][r * 2 + 1];
                s[sl] += v0 + v1;
                q[sl] += v0 * v0 + v1 * v1;
            }
        }
    #pragma unroll
    for (int m = 1; m <= 2; m <<= 1)
        #pragma unroll
        for (int i = 0; i < 8; i++) {
            s[i] += __shfl_xor_sync(0xFFFFFFFF, s[i], m);
            q[i] += __shfl_xor_sync(0xFFFFFFFF, q[i], m);
        }

    __syncthreads();
    float* sb = smem;
    float* qb = smem + 1024;
    if (ac == 0) {
        #pragma unroll
        for (int mt = 0; mt < 4; mt++)
            #pragma unroll
            for (int r = 0; r < 2; r++) {
                int cl = mt * 16 + r * 8 + ar;
                sb[wid * 64 + cl] = s[mt * 2 + r];
                qb[wid * 64 + cl] = q[mt * 2 + r];
            }
    }
    __syncthreads();
    if (tid < COUTc) {
        int co = tid;
        float ss = 0.f, qq = 0.f;
        #pragma unroll
        for (int w = 0; w < 8; w++) {
            ss += sb[((co >> 6) * 8 + w) * 64 + (co & 63)];
            qq += qb[((co >> 6) * 8 + w) * 64 + (co & 63)];
        }
        g_psum[co * 128 + blockIdx.x] = ss;
        g_psq [co * 128 + blockIdx.x] = qq;
    }
}

// ---------------------------------------------------------------------------
// Kernel 6: finalize BN stats
// ---------------------------------------------------------------------------
__global__ void k_statsfin(const float* __restrict__ gamma, const float* __restrict__ beta) {
    int co = threadIdx.x;
    float s = 0.f, q = 0.f;
    for (int j = 0; j < 128; j++) { s += g_psum[co * 128 + j]; q += g_psq[co * 128 + j]; }
    const float inv_n = 1.f / (float)NPIX;
    float mean = s * inv_n;
    float var  = q * inv_n - mean * mean;
    float sc   = gamma[co] * rsqrtf(var + 1e-5f);
    g_scale[co] = sc;
    g_shift[co] = beta[co] - mean * sc;
}

// ---------------------------------------------------------------------------
// Kernel 7: normalize + SiLU (in place)
// ---------------------------------------------------------------------------
__global__ void k_norm(float* __restrict__ out) {
    int idx = blockIdx.x * 256 + threadIdx.x;
    const int n4 = Bn * COUTc * HWn / 4;
    if (idx >= n4) return;
    int co = (idx >> 10) & 127;
    float sc = g_scale[co], sh = g_shift[co];
    float4* o4 = (float4*)out;
    float4 v = o4[idx];
    float u;
    u = v.x * sc + sh; v.x = u / (1.f + expf(-u));
    u = v.y * sc + sh; v.y = u / (1.f + expf(-u));
    u = v.z * sc + sh; v.z = u / (1.f + expf(-u));
    u = v.w * sc + sh; v.w = u / (1.f + expf(-u));
    o4[idx] = v;
}

// ---------------------------------------------------------------------------
extern "C" void kernel_launch(void* const* d_in, const int* in_sizes, int n_in,
                              void* d_out, int out_size) {
    const float* x     = (const float*)d_in[0];
    const float* w_off = (const float*)d_in[1];
    const float* w_def = (const float*)d_in[2];
    // d_in[3] = b_def: exactly absorbed by batch-norm mean subtraction
    const float* gamma = (const float*)d_in[4];
    const float* beta  = (const float*)d_in[5];
    float* out = (float*)d_out;

    cudaFuncSetAttribute(k_gemm, cudaFuncAttributeMaxDynamicSharedMemorySize, GEMM_SMEM);
    cudaFuncSetAttribute(k_offset2, cudaFuncAttributeMaxDynamicSharedMemorySize, OFF_SMEM);

    dim3 tb(32, 8);
    dim3 tg(HWn / 32, CINc / 32, Bn);
    k_transpose<<<tg, tb>>>(x);

    k_wprep<<<(Kdim * COUTc + 255) / 256, 256>>>(w_def);
    k_wprep2<<<(Kdim * 32 + 255) / 256, 256>>>(w_off);

    k_offset2<<<128, 256, OFF_SMEM>>>();

    k_gather<<<NPIX / 32, 256>>>();

    k_gemm<<<NPIX / TILE_N, 512, GEMM_SMEM>>>(out);

    k_statsfin<<<1, 128>>>(gamma, beta);

    k_norm<<<(Bn * COUTc * HWn / 4 + 255) / 256, 256>>>(out);
}

// round 5
// speedup vs baseline: 4.2193x; 1.1231x over previous
#include <cuda_runtime.h>
#include <cuda_fp16.h>
#include <math.h>
#include <stdint.h>

#define Bn 8
#define CINc 128
#define COUTc 128
#define Hh 64
#define Ww 64
#define HWn 4096
#define KKn 9
#define OFFC 18
#define Kdim 1152            // CIN * KK
#define NPIX 32768           // B * HW
#define TILE_N 256           // pixels per main-GEMM CTA
#define NCHUNK 36            // Kdim / 32
#define SRH 40               // smem row stride in halves (32 + pad 8)

// main gemm smem (halves)
#define A_H (128 * SRH)      // 5120
#define B_H (TILE_N * SRH)   // 10240
#define STG_H (A_H + B_H)    // 15360
#define GEMM_SMEM (3 * STG_H * 2)   // 92160 B

// offset gemm smem (halves)
#define OA_H (32 * SRH)      // 1280
#define OB_H (128 * SRH)     // 5120
#define OSTG_H (OA_H + OB_H) // 6400
#define OFF_SMEM (3 * OSTG_H * 2)   // 38400 B

// ---------------- static scratch ----------------
__device__ float  g_xt[Bn * HWn * CINc];          // x NHWC fp32 (16.8 MB)
__device__ float  g_off[Bn * OFFC * HWn];         // offset conv out fp32
__device__ __half g_wtp[NCHUNK * 4096];           // w_def packed [chunk][co][32k]
__device__ __half g_woffp[NCHUNK * 1024];         // w_off packed [chunk][oc32][32k]
__device__ __half g_im2colh[(size_t)NPIX * Kdim]; // im2col half [pix][k] (75 MB)
__device__ float  g_psum[COUTc * 128];
__device__ float  g_psq [COUTc * 128];
__device__ float  g_scale[COUTc];
__device__ float  g_shift[COUTc];

// ---------------- helpers ----------------
__device__ __forceinline__ void mma_f16(float* d, const uint32_t* a,
                                        uint32_t b0, uint32_t b1) {
    asm volatile(
        "mma.sync.aligned.m16n8k16.row.col.f32.f16.f16.f32 "
        "{%0,%1,%2,%3}, {%4,%5,%6,%7}, {%8,%9}, {%0,%1,%2,%3};"
        : "+f"(d[0]), "+f"(d[1]), "+f"(d[2]), "+f"(d[3])
        : "r"(a[0]), "r"(a[1]), "r"(a[2]), "r"(a[3]), "r"(b0), "r"(b1));
}
__device__ __forceinline__ uint32_t pkh2(float a, float b) {
    __half2 h = __floats2half2_rn(a, b);
    return *(uint32_t*)&h;
}

// ---------------------------------------------------------------------------
// Kernel 1: NCHW -> NHWC transpose (fp32)
// ---------------------------------------------------------------------------
__global__ void k_transpose(const float* __restrict__ x) {
    __shared__ float tile[32][33];
    int b = blockIdx.z, p0 = blockIdx.x * 32, c0 = blockIdx.y * 32;
    const float* xb = x + (size_t)b * CINc * HWn;
    float* xtb = g_xt + (size_t)b * HWn * CINc;
    int tx = threadIdx.x, ty = threadIdx.y;
    #pragma unroll
    for (int j = 0; j < 32; j += 8)
        tile[ty + j][tx] = xb[(size_t)(c0 + ty + j) * HWn + p0 + tx];
    __syncthreads();
    #pragma unroll
    for (int j = 0; j < 32; j += 8)
        xtb[(size_t)(p0 + ty + j) * CINc + c0 + tx] = tile[tx][ty + j];
}

// ---------------------------------------------------------------------------
// Kernel 2a: pack w_def -> g_wtp[chunk][co][kloc], k = chunk*32 + kloc,
//            k maps as kk = k>>7, c = k&127 (k-order = kk*128 + c)
// ---------------------------------------------------------------------------
__global__ void k_wprep(const float* __restrict__ w_def) {
    int idx = blockIdx.x * 256 + threadIdx.x;
    if (idx >= NCHUNK * 4096) return;
    int chunk = idx >> 12, r = idx & 4095;
    int co = r >> 5, kloc = r & 31;
    int k = chunk * 32 + kloc;
    int kk = k >> 7, c = k & 127;
    g_wtp[idx] = __float2half(w_def[(size_t)(co * CINc + c) * KKn + kk]);
}

// Kernel 2b: pack w_off -> g_woffp[chunk][oc32][kloc]; chunk order kk-major:
//            kk = chunk>>2, c = (chunk&3)*32 + kloc. oc >= 18 zero-padded.
__global__ void k_wprep2(const float* __restrict__ w_off) {
    int idx = blockIdx.x * 256 + threadIdx.x;
    if (idx >= NCHUNK * 1024) return;
    int chunk = idx >> 10, r = idx & 1023;
    int oc = r >> 5, kloc = r & 31;
    int kk = chunk >> 2, c = (chunk & 3) * 32 + kloc;
    g_woffp[idx] = (oc < OFFC)
        ? __float2half(w_off[(size_t)(oc * CINc + c) * KKn + kk])
        : __float2half(0.f);
}

// ---------------------------------------------------------------------------
// Kernel 3: offset conv, fp16 implicit GEMM. 256 CTAs, 256 thr (8 warps).
// CTA tile: 32oc x 128pix. Warp: 32oc x 16pix. m16n8k16.
// ---------------------------------------------------------------------------
__global__ __launch_bounds__(256) void k_offset2() {
    extern __shared__ __half smh[];
    const int tid = threadIdx.x;
    const int wid = tid >> 5, lane = tid & 31;
    const int g = lane >> 2, tc = lane & 3;
    const int wn = wid;

    const int tile = blockIdx.x;          // 0..255
    const int b = tile >> 5;
    const int hw0 = (tile & 31) * 128;    // 2 rows of 64
    const int y0 = hw0 >> 6;
    const float* xtb = g_xt + (size_t)b * HWn * CINc;

    uint4 bufA;         // tid < 128 only
    uint4 bufB[2];

    float acc[2][2][4];
    #pragma unroll
    for (int mt = 0; mt < 2; mt++)
        #pragma unroll
        for (int nt = 0; nt < 2; nt++)
            #pragma unroll
            for (int r = 0; r < 4; r++) acc[mt][nt][r] = 0.f;

    auto ldg_chunk = [&](int i) {
        int kk = i >> 2, c0 = (i & 3) * 32;
        int ky = kk / 3 - 1, kx = kk % 3 - 1;
        #pragma unroll
        for (int m = 0; m < 2; m++) {
            int e = tid + m * 256;
            int pix = e >> 2, j = e & 3;
            int y = y0 + (pix >> 6), xx = pix & 63;
            int ys = y + ky, xs = xx + kx;
            bool valid = ((unsigned)ys < Hh) && ((unsigned)xs < Ww);
            float4 f0, f1;
            if (valid) {
                const float* p = xtb + (size_t)(ys * Ww + xs) * CINc + c0 + j * 8;
                f0 = *(const float4*)p;
                f1 = *(const float4*)(p + 4);
            } else {
                f0 = make_float4(0.f, 0.f, 0.f, 0.f);
                f1 = f0;
            }
            bufB[m] = make_uint4(pkh2(f0.x, f0.y), pkh2(f0.z, f0.w),
                                 pkh2(f1.x, f1.y), pkh2(f1.z, f1.w));
        }
        if (tid < 128)
            bufA = *(const uint4*)(g_woffp + (size_t)i * 1024 + tid * 8);
    };
    auto sts_chunk = [&](int st) {
        __half* As = smh + st * OSTG_H;
        __half* Bs = As + OA_H;
        #pragma unroll
        for (int m = 0; m < 2; m++) {
            int e = tid + m * 256;
            int pix = e >> 2, j = e & 3;
            *(uint4*)(Bs + pix * SRH + j * 8) = bufB[m];
        }
        if (tid < 128)
            *(uint4*)(As + (tid >> 2) * SRH + (tid & 3) * 8) = bufA;
    };

    ldg_chunk(0); sts_chunk(0);
    ldg_chunk(1); sts_chunk(1);
    __syncthreads();

    for (int i = 0; i < NCHUNK; i++) {
        if (i + 2 < NCHUNK) ldg_chunk(i + 2);
        const __half* As = smh + (i % 3) * OSTG_H;
        const __half* Bs = As + OA_H;
        #pragma unroll
        for (int ks = 0; ks < 2; ks++) {
            uint32_t a[2][4];
            #pragma unroll
            for (int mt = 0; mt < 2; mt++) {
                const __half* ap = As + (mt * 16 + g) * SRH + ks * 16 + tc * 2;
                a[mt][0] = *(const uint32_t*)(ap);
                a[mt][1] = *(const uint32_t*)(ap + 8 * SRH);
                a[mt][2] = *(const uint32_t*)(ap + 8);
                a[mt][3] = *(const uint32_t*)(ap + 8 * SRH + 8);
            }
            #pragma unroll
            for (int nt = 0; nt < 2; nt++) {
                const __half* bp = Bs + (wn * 16 + nt * 8 + g) * SRH + ks * 16 + tc * 2;
                uint32_t b0 = *(const uint32_t*)(bp);
                uint32_t b1 = *(const uint32_t*)(bp + 8);
                #pragma unroll
                for (int mt = 0; mt < 2; mt++)
                    mma_f16(acc[mt][nt], a[mt], b0, b1);
            }
        }
        if (i + 2 < NCHUNK) sts_chunk((i + 2) % 3);
        __syncthreads();
    }

    float* ob = g_off + (size_t)b * OFFC * HWn;
    #pragma unroll
    for (int mt = 0; mt < 2; mt++) {
        #pragma unroll
        for (int nt = 0; nt < 2; nt++) {
            int pix = hw0 + wn * 16 + nt * 8 + tc * 2;
            int r0 = mt * 16 + g, r1 = r0 + 8;
            if (r0 < OFFC)
                *(float2*)&ob[(size_t)r0 * HWn + pix] =
                    make_float2(acc[mt][nt][0], acc[mt][nt][1]);
            if (r1 < OFFC)
                *(float2*)&ob[(size_t)r1 * HWn + pix] =
                    make_float2(acc[mt][nt][2], acc[mt][nt][3]);
        }
    }
}

// ---------------------------------------------------------------------------
// Kernel 4: bilinear gather (fp32 math) -> im2col half [pix][kk*128+c]
// ---------------------------------------------------------------------------
struct __align__(16) Meta {
    int   i0, i1, i2, i3;
    float w0, w1, w2, w3;
};

__global__ __launch_bounds__(256) void k_gather() {
    __shared__ Meta meta[KKn][32];
    int bpix = blockIdx.x * 32;
    int b = bpix >> 12, hw0 = bpix & 4095, y = hw0 >> 6;

    const float* offb = g_off + (size_t)b * OFFC * HWn;
    for (int t = threadIdx.x; t < KKn * 32; t += 256) {
        int kk = t >> 5, p = t & 31;
        int hw = hw0 + p, xx = hw & 63;
        float dy = offb[(size_t)(kk * 2 + 0) * HWn + hw];
        float dx = offb[(size_t)(kk * 2 + 1) * HWn + hw];
        float ys = (float)(y - 1 + kk / 3) + dy;
        float xs = (float)(xx - 1 + kk % 3) + dx;
        float y0f = floorf(ys), x0f = floorf(xs);
        float wy = ys - y0f, wx = xs - x0f;
        int y0 = (int)y0f, x0 = (int)x0f;
        bool vy0 = (y0 >= 0) && (y0 < Hh);
        bool vy1 = (y0 + 1 >= 0) && (y0 + 1 < Hh);
        bool vx0 = (x0 >= 0) && (x0 < Ww);
        bool vx1 = (x0 + 1 >= 0) && (x0 + 1 < Ww);
        Meta m;
        m.w0 = (vy0 && vx0) ? (1.f - wy) * (1.f - wx) : 0.f;
        m.w1 = (vy0 && vx1) ? (1.f - wy) * wx : 0.f;
        m.w2 = (vy1 && vx0) ? wy * (1.f - wx) : 0.f;
        m.w3 = (vy1 && vx1) ? wy * wx : 0.f;
        m.i0 = (vy0 && vx0) ? (y0 * Ww + x0) * CINc : 0;
        m.i1 = (vy0 && vx1) ? (y0 * Ww + x0 + 1) * CINc : 0;
        m.i2 = (vy1 && vx0) ? ((y0 + 1) * Ww + x0) * CINc : 0;
        m.i3 = (vy1 && vx1) ? ((y0 + 1) * Ww + x0 + 1) * CINc : 0;
        meta[kk][p] = m;
    }
    __syncthreads();

    const float* xtb = g_xt + (size_t)b * HWn * CINc;
    int wid = threadIdx.x >> 5, lane = threadIdx.x & 31;
    for (int u = wid; u < KKn * 32; u += 8) {
        int kk = u >> 5, p = u & 31;
        Meta m = meta[kk][p];
        const float* base = xtb + 4 * lane;
        float4 a  = *(const float4*)(base + m.i0);
        float4 bb = *(const float4*)(base + m.i1);
        float4 cc = *(const float4*)(base + m.i2);
        float4 dd = *(const float4*)(base + m.i3);
        float sx = m.w0 * a.x + m.w1 * bb.x + m.w2 * cc.x + m.w3 * dd.x;
        float sy = m.w0 * a.y + m.w1 * bb.y + m.w2 * cc.y + m.w3 * dd.y;
        float sz = m.w0 * a.z + m.w1 * bb.z + m.w2 * cc.z + m.w3 * dd.z;
        float sw = m.w0 * a.w + m.w1 * bb.w + m.w2 * cc.w + m.w3 * dd.w;
        size_t pix = (size_t)(bpix + p);
        uint2 u2 = make_uint2(pkh2(sx, sy), pkh2(sz, sw));
        *(uint2*)(g_im2colh + pix * Kdim + kk * 128 + 4 * lane) = u2;
    }
}

// ---------------------------------------------------------------------------
// Kernel 5: fp16 mma GEMM  D[128co, 256pix] = W x S. 512 thr (16 warps 2m x 8n),
// warp 64co x 32pix, m16n8k16. LDG->reg->STS 3-stage ring.
// ---------------------------------------------------------------------------
__global__ __launch_bounds__(512, 1) void k_gemm(float* __restrict__ out) {
    extern __shared__ __half smh[];
    const int tid = threadIdx.x;
    const int wid = tid >> 5, lane = tid & 31;
    const int wm = wid >> 3, wn = wid & 7;
    const int g = lane >> 2, tc = lane & 3;
    const int tilebase = blockIdx.x * TILE_N;

    float acc[4][4][4];
    #pragma unroll
    for (int mt = 0; mt < 4; mt++)
        #pragma unroll
        for (int nt = 0; nt < 4; nt++)
            #pragma unroll
            for (int r = 0; r < 4; r++) acc[mt][nt][r] = 0.f;

    uint4 bufA, bufB[2];

    auto ldg_chunk = [&](int i) {
        bufA = *(const uint4*)(g_wtp + (size_t)i * 4096 + tid * 8);
        #pragma unroll
        for (int m = 0; m < 2; m++) {
            int e = tid + m * 512;
            int pix = e >> 2, j = e & 3;
            bufB[m] = *(const uint4*)(g_im2colh +
                (size_t)(tilebase + pix) * Kdim + i * 32 + j * 8);
        }
    };
    auto sts_chunk = [&](int st) {
        __half* As = smh + st * STG_H;
        __half* Bs = As + A_H;
        *(uint4*)(As + (tid >> 2) * SRH + (tid & 3) * 8) = bufA;
        #pragma unroll
        for (int m = 0; m < 2; m++) {
            int e = tid + m * 512;
            int pix = e >> 2, j = e & 3;
            *(uint4*)(Bs + pix * SRH + j * 8) = bufB[m];
        }
    };

    ldg_chunk(0); sts_chunk(0);
    ldg_chunk(1); sts_chunk(1);
    __syncthreads();

    for (int i = 0; i < NCHUNK; i++) {
        if (i + 2 < NCHUNK) ldg_chunk(i + 2);

        const __half* As = smh + (i % 3) * STG_H;
        const __half* Bs = As + A_H;
        #pragma unroll
        for (int ks = 0; ks < 2; ks++) {
            uint32_t a[4][4];
            #pragma unroll
            for (int mt = 0; mt < 4; mt++) {
                const __half* ap = As + (wm * 64 + mt * 16 + g) * SRH + ks * 16 + tc * 2;
                a[mt][0] = *(const uint32_t*)(ap);
                a[mt][1] = *(const uint32_t*)(ap + 8 * SRH);
                a[mt][2] = *(const uint32_t*)(ap + 8);
                a[mt][3] = *(const uint32_t*)(ap + 8 * SRH + 8);
            }
            #pragma unroll
            for (int nt = 0; nt < 4; nt++) {
                const __half* bp = Bs + (wn * 32 + nt * 8 + g) * SRH + ks * 16 + tc * 2;
                uint32_t b0 = *(const uint32_t*)(bp);
                uint32_t b1 = *(const uint32_t*)(bp + 8);
                #pragma unroll
                for (int mt = 0; mt < 4; mt++)
                    mma_f16(acc[mt][nt], a[mt], b0, b1);
            }
        }
        if (i + 2 < NCHUNK) sts_chunk((i + 2) % 3);
        __syncthreads();
    }

    // ---- store results ----
    const int b = tilebase >> 12, hw0 = tilebase & 4095;
    #pragma unroll
    for (int mt = 0; mt < 4; mt++) {
        #pragma unroll
        for (int nt = 0; nt < 4; nt++) {
            int pix = hw0 + wn * 32 + nt * 8 + tc * 2;
            int co0 = wm * 64 + mt * 16 + g;
            *(float2*)&out[((size_t)b * COUTc + co0) * HWn + pix] =
                make_float2(acc[mt][nt][0], acc[mt][nt][1]);
            *(float2*)&out[((size_t)b * COUTc + co0 + 8) * HWn + pix] =
                make_float2(acc[mt][nt][2], acc[mt][nt][3]);
        }
    }

    // ---- deterministic BN partials ----
    float s[8], q[8];
    #pragma unroll
    for (int i = 0; i < 8; i++) { s[i] = 0.f; q[i] = 0.f; }
    #pragma unroll
    for (int mt = 0; mt < 4; mt++)
        #pragma unroll
        for (int r = 0; r < 2; r++) {
            int sl = mt * 2 + r;
            #pragma unroll
            for (int nt = 0; nt < 4; nt++) {
                float v0 = acc[mt][nt][r * 2], v1 = acc[mt][nt][r * 2 + 1];
                s[sl] += v0 + v1;
                q[sl] += v0 * v0 + v1 * v1;
            }
        }
    #pragma unroll
    for (int m = 1; m <= 2; m <<= 1)
        #pragma unroll
        for (int i = 0; i < 8; i++) {
            s[i] += __shfl_xor_sync(0xFFFFFFFF, s[i], m);
            q[i] += __shfl_xor_sync(0xFFFFFFFF, q[i], m);
        }

    __syncthreads();
    float* sb = (float*)smh;
    float* qb = sb + 1024;
    if (tc == 0) {
        #pragma unroll
        for (int mt = 0; mt < 4; mt++)
            #pragma unroll
            for (int r = 0; r < 2; r++) {
                int cl = mt * 16 + r * 8 + g;
                sb[wid * 64 + cl] = s[mt * 2 + r];
                qb[wid * 64 + cl] = q[mt * 2 + r];
            }
    }
    __syncthreads();
    if (tid < COUTc) {
        int co = tid;
        float ss = 0.f, qq = 0.f;
        #pragma unroll
        for (int w = 0; w < 8; w++) {
            ss += sb[((co >> 6) * 8 + w) * 64 + (co & 63)];
            qq += qb[((co >> 6) * 8 + w) * 64 + (co & 63)];
        }
        g_psum[co * 128 + blockIdx.x] = ss;
        g_psq [co * 128 + blockIdx.x] = qq;
    }
}

// ---------------------------------------------------------------------------
// Kernel 6: finalize BN stats
// ---------------------------------------------------------------------------
__global__ void k_statsfin(const float* __restrict__ gamma, const float* __restrict__ beta) {
    int co = threadIdx.x;
    float s = 0.f, q = 0.f;
    for (int j = 0; j < 128; j++) { s += g_psum[co * 128 + j]; q += g_psq[co * 128 + j]; }
    const float inv_n = 1.f / (float)NPIX;
    float mean = s * inv_n;
    float var  = q * inv_n - mean * mean;
    float sc   = gamma[co] * rsqrtf(var + 1e-5f);
    g_scale[co] = sc;
    g_shift[co] = beta[co] - mean * sc;
}

// ---------------------------------------------------------------------------
// Kernel 7: normalize + SiLU (in place)
// ---------------------------------------------------------------------------
__global__ void k_norm(float* __restrict__ out) {
    int idx = blockIdx.x * 256 + threadIdx.x;
    const int n4 = Bn * COUTc * HWn / 4;
    if (idx >= n4) return;
    int co = (idx >> 10) & 127;
    float sc = g_scale[co], sh = g_shift[co];
    float4* o4 = (float4*)out;
    float4 v = o4[idx];
    float u;
    u = v.x * sc + sh; v.x = u / (1.f + expf(-u));
    u = v.y * sc + sh; v.y = u / (1.f + expf(-u));
    u = v.z * sc + sh; v.z = u / (1.f + expf(-u));
    u = v.w * sc + sh; v.w = u / (1.f + expf(-u));
    o4[idx] = v;
}

// ---------------------------------------------------------------------------
extern "C" void kernel_launch(void* const* d_in, const int* in_sizes, int n_in,
                              void* d_out, int out_size) {
    const float* x     = (const float*)d_in[0];
    const float* w_off = (const float*)d_in[1];
    const float* w_def = (const float*)d_in[2];
    // d_in[3] = b_def: exactly absorbed by batch-norm mean subtraction
    const float* gamma = (const float*)d_in[4];
    const float* beta  = (const float*)d_in[5];
    float* out = (float*)d_out;

    cudaFuncSetAttribute(k_gemm, cudaFuncAttributeMaxDynamicSharedMemorySize, GEMM_SMEM);
    cudaFuncSetAttribute(k_offset2, cudaFuncAttributeMaxDynamicSharedMemorySize, OFF_SMEM);

    dim3 tb(32, 8);
    dim3 tg(HWn / 32, CINc / 32, Bn);
    k_transpose<<<tg, tb>>>(x);

    k_wprep<<<(NCHUNK * 4096 + 255) / 256, 256>>>(w_def);
    k_wprep2<<<(NCHUNK * 1024 + 255) / 256, 256>>>(w_off);

    k_offset2<<<256, 256, OFF_SMEM>>>();

    k_gather<<<NPIX / 32, 256>>>();

    k_gemm<<<NPIX / TILE_N, 512, GEMM_SMEM>>>(out);

    k_statsfin<<<1, 128>>>(gamma, beta);

    k_norm<<<(Bn * COUTc * HWn / 4 + 255) / 256, 256>>>(out);
}

// round 6
// speedup vs baseline: 4.3773x; 1.0375x over previous
#include <cuda_runtime.h>
#include <cuda_fp16.h>
#include <math.h>
#include <stdint.h>

#define Bn 8
#define CINc 128
#define COUTc 128
#define Hh 64
#define Ww 64
#define HWn 4096
#define KKn 9
#define OFFC 18
#define Kdim 1152            // CIN * KK
#define NPIX 32768           // B * HW
#define TILE_N 128           // pixels per main-GEMM CTA
#define NCH64 18             // Kdim / 64
#define SRH 72               // smem row stride in halves (64 + pad 8)

// main gemm smem (halves): A 128x72, B 128x72 per stage, 2 stages
#define GA_H (128 * SRH)         // 9216
#define GB_H (128 * SRH)         // 9216
#define GSTG_H (GA_H + GB_H)     // 18432
#define GEMM_SMEM (2 * GSTG_H * 2)   // 73728 B

// offset gemm smem (halves): A 32x72, B 128x72 per stage, 2 stages
#define OA_H (32 * SRH)          // 2304
#define OB_H (128 * SRH)         // 9216
#define OSTG_H (OA_H + OB_H)     // 11520
#define OFF_SMEM (2 * OSTG_H * 2)    // 46080 B

// ---------------- static scratch ----------------
__device__ __half g_xh[Bn * HWn * CINc];          // x NHWC fp16 (8.4 MB)
__device__ float  g_off[Bn * OFFC * HWn];         // offset conv out fp32
__device__ __half g_wtp[NCH64 * 8192];            // w_def packed [ch64][co][64k]
__device__ __half g_woffp[NCH64 * 2048];          // w_off packed [ch64][oc32][64k]
__device__ __half g_im2colh[(size_t)NPIX * Kdim]; // im2col half [pix][k] (75 MB)
__device__ float  g_psum[COUTc * 256];
__device__ float  g_psq [COUTc * 256];
__device__ float  g_scale[COUTc];
__device__ float  g_shift[COUTc];

// ---------------- helpers ----------------
__device__ __forceinline__ void mma_f16(float* d, const uint32_t* a,
                                        uint32_t b0, uint32_t b1) {
    asm volatile(
        "mma.sync.aligned.m16n8k16.row.col.f32.f16.f16.f32 "
        "{%0,%1,%2,%3}, {%4,%5,%6,%7}, {%8,%9}, {%0,%1,%2,%3};"
        : "+f"(d[0]), "+f"(d[1]), "+f"(d[2]), "+f"(d[3])
        : "r"(a[0]), "r"(a[1]), "r"(a[2]), "r"(a[3]), "r"(b0), "r"(b1));
}
__device__ __forceinline__ uint32_t pkh2(float a, float b) {
    __half2 h = __floats2half2_rn(a, b);
    return *(uint32_t*)&h;
}

// ---------------------------------------------------------------------------
// Kernel 1: NCHW fp32 -> NHWC fp16 transpose
// ---------------------------------------------------------------------------
__global__ void k_transpose(const float* __restrict__ x) {
    __shared__ float tile[32][33];   // [channel_local][pixel_local]
    int b = blockIdx.z, p0 = blockIdx.x * 32, c0 = blockIdx.y * 32;
    const float* xb = x + (size_t)b * CINc * HWn;
    __half* xtb = g_xh + (size_t)b * HWn * CINc;
    int tx = threadIdx.x, ty = threadIdx.y;
    int tid = ty * 32 + tx;
    #pragma unroll
    for (int j = 0; j < 32; j += 8)
        tile[ty + j][tx] = xb[(size_t)(c0 + ty + j) * HWn + p0 + tx];
    __syncthreads();
    // write half2: 32 pixels x 16 channel-pairs = 512 units, 2 per thread
    #pragma unroll
    for (int m = 0; m < 2; m++) {
        int u = tid + m * 256;
        int pl = u >> 4, cp = u & 15;
        __half2 v = __floats2half2_rn(tile[cp * 2][pl], tile[cp * 2 + 1][pl]);
        *(__half2*)(xtb + (size_t)(p0 + pl) * CINc + c0 + cp * 2) = v;
    }
}

// ---------------------------------------------------------------------------
// Kernel 2a: pack w_def -> g_wtp[ch64][co][kloc64]; k = ch*64+kloc,
//            kk = k>>7, c = k&127
// ---------------------------------------------------------------------------
__global__ void k_wprep(const float* __restrict__ w_def) {
    int idx = blockIdx.x * 256 + threadIdx.x;
    if (idx >= NCH64 * 8192) return;
    int chunk = idx >> 13, r = idx & 8191;
    int co = r >> 6, kloc = r & 63;
    int k = chunk * 64 + kloc;
    int kk = k >> 7, c = k & 127;
    g_wtp[idx] = __float2half(w_def[(size_t)(co * CINc + c) * KKn + kk]);
}

// Kernel 2b: pack w_off -> g_woffp[ch64][oc32][kloc64];
//            kk = chunk>>1, c = (chunk&1)*64 + kloc; oc >= 18 zero
__global__ void k_wprep2(const float* __restrict__ w_off) {
    int idx = blockIdx.x * 256 + threadIdx.x;
    if (idx >= NCH64 * 2048) return;
    int chunk = idx >> 11, r = idx & 2047;
    int oc = r >> 6, kloc = r & 63;
    int kk = chunk >> 1, c = (chunk & 1) * 64 + kloc;
    g_woffp[idx] = (oc < OFFC)
        ? __float2half(w_off[(size_t)(oc * CINc + c) * KKn + kk])
        : __float2half(0.f);
}

// ---------------------------------------------------------------------------
// Kernel 3: offset conv, fp16 implicit GEMM. 256 CTAs, 256 thr (8 warps).
// CTA tile 32oc x 128pix, warp 32oc x 16pix, 64-k chunks (18 iters).
// ---------------------------------------------------------------------------
__global__ __launch_bounds__(256) void k_offset2() {
    extern __shared__ __half smh[];
    const int tid = threadIdx.x;
    const int wid = tid >> 5, lane = tid & 31;
    const int g = lane >> 2, tc = lane & 3;
    const int wn = wid;

    const int tile = blockIdx.x;          // 0..255
    const int b = tile >> 5;
    const int hw0 = (tile & 31) * 128;
    const int y0 = hw0 >> 6;
    const __half* xhb = g_xh + (size_t)b * HWn * CINc;

    uint4 bufA;          // tid < 32*64/8 = 256 -> 1 per thread
    uint4 bufB[4];       // 1024 units / 256 thr

    float acc[2][2][4];
    #pragma unroll
    for (int mt = 0; mt < 2; mt++)
        #pragma unroll
        for (int nt = 0; nt < 2; nt++)
            #pragma unroll
            for (int r = 0; r < 4; r++) acc[mt][nt][r] = 0.f;

    auto ldg_chunk = [&](int i) {
        int kk = i >> 1, c0 = (i & 1) * 64;
        int ky = kk / 3 - 1, kx = kk % 3 - 1;
        #pragma unroll
        for (int m = 0; m < 4; m++) {
            int e = tid + m * 256;
            int pix = e >> 3, j = e & 7;
            int y = y0 + (pix >> 6), xx = pix & 63;
            int ys = y + ky, xs = xx + kx;
            bool valid = ((unsigned)ys < Hh) && ((unsigned)xs < Ww);
            bufB[m] = valid
                ? *(const uint4*)(xhb + (size_t)(ys * Ww + xs) * CINc + c0 + j * 8)
                : make_uint4(0u, 0u, 0u, 0u);
        }
        bufA = *(const uint4*)(g_woffp + (size_t)i * 2048 + tid * 8);
    };
    auto sts_chunk = [&](int st) {
        __half* As = smh + st * OSTG_H;
        __half* Bs = As + OA_H;
        #pragma unroll
        for (int m = 0; m < 4; m++) {
            int e = tid + m * 256;
            int pix = e >> 3, j = e & 7;
            *(uint4*)(Bs + pix * SRH + j * 8) = bufB[m];
        }
        *(uint4*)(As + (tid >> 3) * SRH + (tid & 7) * 8) = bufA;
    };

    ldg_chunk(0); sts_chunk(0);
    ldg_chunk(1);
    __syncthreads();

    for (int i = 0; i < NCH64; i++) {
        if (i + 1 < NCH64) sts_chunk((i + 1) & 1);
        if (i + 2 < NCH64) ldg_chunk(i + 2);
        const __half* As = smh + (i & 1) * OSTG_H;
        const __half* Bs = As + OA_H;
        #pragma unroll
        for (int ks = 0; ks < 4; ks++) {
            uint32_t a[2][4];
            #pragma unroll
            for (int mt = 0; mt < 2; mt++) {
                const __half* ap = As + (mt * 16 + g) * SRH + ks * 16 + tc * 2;
                a[mt][0] = *(const uint32_t*)(ap);
                a[mt][1] = *(const uint32_t*)(ap + 8 * SRH);
                a[mt][2] = *(const uint32_t*)(ap + 8);
                a[mt][3] = *(const uint32_t*)(ap + 8 * SRH + 8);
            }
            #pragma unroll
            for (int nt = 0; nt < 2; nt++) {
                const __half* bp = Bs + (wn * 16 + nt * 8 + g) * SRH + ks * 16 + tc * 2;
                uint32_t b0 = *(const uint32_t*)(bp);
                uint32_t b1 = *(const uint32_t*)(bp + 8);
                #pragma unroll
                for (int mt = 0; mt < 2; mt++)
                    mma_f16(acc[mt][nt], a[mt], b0, b1);
            }
        }
        __syncthreads();
    }

    float* ob = g_off + (size_t)b * OFFC * HWn;
    #pragma unroll
    for (int mt = 0; mt < 2; mt++) {
        #pragma unroll
        for (int nt = 0; nt < 2; nt++) {
            int pix = hw0 + wn * 16 + nt * 8 + tc * 2;
            int r0 = mt * 16 + g, r1 = r0 + 8;
            if (r0 < OFFC)
                *(float2*)&ob[(size_t)r0 * HWn + pix] =
                    make_float2(acc[mt][nt][0], acc[mt][nt][1]);
            if (r1 < OFFC)
                *(float2*)&ob[(size_t)r1 * HWn + pix] =
                    make_float2(acc[mt][nt][2], acc[mt][nt][3]);
        }
    }
}

// ---------------------------------------------------------------------------
// Kernel 4: bilinear gather (fp32 math, fp16 x) -> im2col half [pix][kk*128+c]
// ---------------------------------------------------------------------------
struct __align__(16) Meta {
    int   i0, i1, i2, i3;
    float w0, w1, w2, w3;
};

__global__ __launch_bounds__(256) void k_gather() {
    __shared__ Meta meta[KKn][32];
    int bpix = blockIdx.x * 32;
    int b = bpix >> 12, hw0 = bpix & 4095, y = hw0 >> 6;

    const float* offb = g_off + (size_t)b * OFFC * HWn;
    for (int t = threadIdx.x; t < KKn * 32; t += 256) {
        int kk = t >> 5, p = t & 31;
        int hw = hw0 + p, xx = hw & 63;
        float dy = offb[(size_t)(kk * 2 + 0) * HWn + hw];
        float dx = offb[(size_t)(kk * 2 + 1) * HWn + hw];
        float ys = (float)(y - 1 + kk / 3) + dy;
        float xs = (float)(xx - 1 + kk % 3) + dx;
        float y0f = floorf(ys), x0f = floorf(xs);
        float wy = ys - y0f, wx = xs - x0f;
        int y0 = (int)y0f, x0 = (int)x0f;
        bool vy0 = (y0 >= 0) && (y0 < Hh);
        bool vy1 = (y0 + 1 >= 0) && (y0 + 1 < Hh);
        bool vx0 = (x0 >= 0) && (x0 < Ww);
        bool vx1 = (x0 + 1 >= 0) && (x0 + 1 < Ww);
        Meta m;
        m.w0 = (vy0 && vx0) ? (1.f - wy) * (1.f - wx) : 0.f;
        m.w1 = (vy0 && vx1) ? (1.f - wy) * wx : 0.f;
        m.w2 = (vy1 && vx0) ? wy * (1.f - wx) : 0.f;
        m.w3 = (vy1 && vx1) ? wy * wx : 0.f;
        m.i0 = (vy0 && vx0) ? (y0 * Ww + x0) * CINc : 0;
        m.i1 = (vy0 && vx1) ? (y0 * Ww + x0 + 1) * CINc : 0;
        m.i2 = (vy1 && vx0) ? ((y0 + 1) * Ww + x0) * CINc : 0;
        m.i3 = (vy1 && vx1) ? ((y0 + 1) * Ww + x0 + 1) * CINc : 0;
        meta[kk][p] = m;
    }
    __syncthreads();

    const __half* xhb = g_xh + (size_t)b * HWn * CINc;
    int wid = threadIdx.x >> 5, lane = threadIdx.x & 31;
    for (int u = wid; u < KKn * 32; u += 8) {
        int kk = u >> 5, p = u & 31;
        Meta m = meta[kk][p];
        const __half* base = xhb + 4 * lane;
        __half2 a0 = *(const __half2*)(base + m.i0);
        __half2 a1 = *(const __half2*)(base + m.i0 + 2);
        __half2 b0 = *(const __half2*)(base + m.i1);
        __half2 b1 = *(const __half2*)(base + m.i1 + 2);
        __half2 c0 = *(const __half2*)(base + m.i2);
        __half2 c1 = *(const __half2*)(base + m.i2 + 2);
        __half2 d0 = *(const __half2*)(base + m.i3);
        __half2 d1 = *(const __half2*)(base + m.i3 + 2);
        float2 af0 = __half22float2(a0), af1 = __half22float2(a1);
        float2 bf0 = __half22float2(b0), bf1 = __half22float2(b1);
        float2 cf0 = __half22float2(c0), cf1 = __half22float2(c1);
        float2 df0 = __half22float2(d0), df1 = __half22float2(d1);
        float sx = m.w0 * af0.x + m.w1 * bf0.x + m.w2 * cf0.x + m.w3 * df0.x;
        float sy = m.w0 * af0.y + m.w1 * bf0.y + m.w2 * cf0.y + m.w3 * df0.y;
        float sz = m.w0 * af1.x + m.w1 * bf1.x + m.w2 * cf1.x + m.w3 * df1.x;
        float sw = m.w0 * af1.y + m.w1 * bf1.y + m.w2 * cf1.y + m.w3 * df1.y;
        size_t pix = (size_t)(bpix + p);
        uint2 u2 = make_uint2(pkh2(sx, sy), pkh2(sz, sw));
        *(uint2*)(g_im2colh + pix * Kdim + kk * 128 + 4 * lane) = u2;
    }
}

// ---------------------------------------------------------------------------
// Kernel 5: fp16 mma GEMM  D[128co, 128pix] per CTA, 256 CTAs.
// 512 thr = 16 warps (2m x 8n), warp 64co x 16pix, 64-k chunks (18 iters).
// ---------------------------------------------------------------------------
__global__ __launch_bounds__(512, 1) void k_gemm(float* __restrict__ out) {
    extern __shared__ __half smh[];
    const int tid = threadIdx.x;
    const int wid = tid >> 5, lane = tid & 31;
    const int wm = wid >> 3, wn = wid & 7;
    const int g = lane >> 2, tc = lane & 3;
    const int tilebase = blockIdx.x * TILE_N;

    float acc[4][2][4];
    #pragma unroll
    for (int mt = 0; mt < 4; mt++)
        #pragma unroll
        for (int nt = 0; nt < 2; nt++)
            #pragma unroll
            for (int r = 0; r < 4; r++) acc[mt][nt][r] = 0.f;

    uint4 bufA[2], bufB[2];

    auto ldg_chunk = [&](int i) {
        #pragma unroll
        for (int m = 0; m < 2; m++) {
            int e = tid + m * 512;
            bufA[m] = *(const uint4*)(g_wtp + (size_t)i * 8192 + e * 8);
        }
        #pragma unroll
        for (int m = 0; m < 2; m++) {
            int e = tid + m * 512;
            int pix = e >> 3, j = e & 7;
            bufB[m] = *(const uint4*)(g_im2colh +
                (size_t)(tilebase + pix) * Kdim + i * 64 + j * 8);
        }
    };
    auto sts_chunk = [&](int st) {
        __half* As = smh + st * GSTG_H;
        __half* Bs = As + GA_H;
        #pragma unroll
        for (int m = 0; m < 2; m++) {
            int e = tid + m * 512;
            *(uint4*)(As + (e >> 3) * SRH + (e & 7) * 8) = bufA[m];
        }
        #pragma unroll
        for (int m = 0; m < 2; m++) {
            int e = tid + m * 512;
            *(uint4*)(Bs + (e >> 3) * SRH + (e & 7) * 8) = bufB[m];
        }
    };

    ldg_chunk(0); sts_chunk(0);
    ldg_chunk(1);
    __syncthreads();

    for (int i = 0; i < NCH64; i++) {
        if (i + 1 < NCH64) sts_chunk((i + 1) & 1);
        if (i + 2 < NCH64) ldg_chunk(i + 2);

        const __half* As = smh + (i & 1) * GSTG_H;
        const __half* Bs = As + GA_H;
        #pragma unroll
        for (int ks = 0; ks < 4; ks++) {
            uint32_t a[4][4];
            #pragma unroll
            for (int mt = 0; mt < 4; mt++) {
                const __half* ap = As + (wm * 64 + mt * 16 + g) * SRH + ks * 16 + tc * 2;
                a[mt][0] = *(const uint32_t*)(ap);
                a[mt][1] = *(const uint32_t*)(ap + 8 * SRH);
                a[mt][2] = *(const uint32_t*)(ap + 8);
                a[mt][3] = *(const uint32_t*)(ap + 8 * SRH + 8);
            }
            #pragma unroll
            for (int nt = 0; nt < 2; nt++) {
                const __half* bp = Bs + (wn * 16 + nt * 8 + g) * SRH + ks * 16 + tc * 2;
                uint32_t b0 = *(const uint32_t*)(bp);
                uint32_t b1 = *(const uint32_t*)(bp + 8);
                #pragma unroll
                for (int mt = 0; mt < 4; mt++)
                    mma_f16(acc[mt][nt], a[mt], b0, b1);
            }
        }
        __syncthreads();
    }

    // ---- store results ----
    const int b = tilebase >> 12, hw0 = tilebase & 4095;
    #pragma unroll
    for (int mt = 0; mt < 4; mt++) {
        #pragma unroll
        for (int nt = 0; nt < 2; nt++) {
            int pix = hw0 + wn * 16 + nt * 8 + tc * 2;
            int co0 = wm * 64 + mt * 16 + g;
            *(float2*)&out[((size_t)b * COUTc + co0) * HWn + pix] =
                make_float2(acc[mt][nt][0], acc[mt][nt][1]);
            *(float2*)&out[((size_t)b * COUTc + co0 + 8) * HWn + pix] =
                make_float2(acc[mt][nt][2], acc[mt][nt][3]);
        }
    }

    // ---- deterministic BN partials ----
    float s[8], q[8];
    #pragma unroll
    for (int i = 0; i < 8; i++) { s[i] = 0.f; q[i] = 0.f; }
    #pragma unroll
    for (int mt = 0; mt < 4; mt++)
        #pragma unroll
        for (int r = 0; r < 2; r++) {
            int sl = mt * 2 + r;
            #pragma unroll
            for (int nt = 0; nt < 2; nt++) {
                float v0 = acc[mt][nt][r * 2], v1 = acc[mt][nt][r * 2 + 1];
                s[sl] += v0 + v1;
                q[sl] += v0 * v0 + v1 * v1;
            }
        }
    #pragma unroll
    for (int m = 1; m <= 2; m <<= 1)
        #pragma unroll
        for (int i = 0; i < 8; i++) {
            s[i] += __shfl_xor_sync(0xFFFFFFFF, s[i], m);
            q[i] += __shfl_xor_sync(0xFFFFFFFF, q[i], m);
        }

    __syncthreads();
    float* sb = (float*)smh;
    float* qb = sb + 1024;
    if (tc == 0) {
        #pragma unroll
        for (int mt = 0; mt < 4; mt++)
            #pragma unroll
            for (int r = 0; r < 2; r++) {
                int cl = mt * 16 + r * 8 + g;
                sb[wid * 64 + cl] = s[mt * 2 + r];
                qb[wid * 64 + cl] = q[mt * 2 + r];
            }
    }
    __syncthreads();
    if (tid < COUTc) {
        int co = tid;
        float ss = 0.f, qq = 0.f;
        #pragma unroll
        for (int w = 0; w < 8; w++) {
            ss += sb[((co >> 6) * 8 + w) * 64 + (co & 63)];
            qq += qb[((co >> 6) * 8 + w) * 64 + (co & 63)];
        }
        g_psum[co * 256 + blockIdx.x] = ss;
        g_psq [co * 256 + blockIdx.x] = qq;
    }
}

// ---------------------------------------------------------------------------
// Kernel 6: finalize BN stats
// ---------------------------------------------------------------------------
__global__ void k_statsfin(const float* __restrict__ gamma, const float* __restrict__ beta) {
    int co = threadIdx.x;
    float s = 0.f, q = 0.f;
    for (int j = 0; j < 256; j++) { s += g_psum[co * 256 + j]; q += g_psq[co * 256 + j]; }
    const float inv_n = 1.f / (float)NPIX;
    float mean = s * inv_n;
    float var  = q * inv_n - mean * mean;
    float sc   = gamma[co] * rsqrtf(var + 1e-5f);
    g_scale[co] = sc;
    g_shift[co] = beta[co] - mean * sc;
}

// ---------------------------------------------------------------------------
// Kernel 7: normalize + SiLU (in place)
// ---------------------------------------------------------------------------
__global__ void k_norm(float* __restrict__ out) {
    int idx = blockIdx.x * 256 + threadIdx.x;
    const int n4 = Bn * COUTc * HWn / 4;
    if (idx >= n4) return;
    int co = (idx >> 10) & 127;
    float sc = g_scale[co], sh = g_shift[co];
    float4* o4 = (float4*)out;
    float4 v = o4[idx];
    float u;
    u = v.x * sc + sh; v.x = u / (1.f + expf(-u));
    u = v.y * sc + sh; v.y = u / (1.f + expf(-u));
    u = v.z * sc + sh; v.z = u / (1.f + expf(-u));
    u = v.w * sc + sh; v.w = u / (1.f + expf(-u));
    o4[idx] = v;
}

// ---------------------------------------------------------------------------
extern "C" void kernel_launch(void* const* d_in, const int* in_sizes, int n_in,
                              void* d_out, int out_size) {
    const float* x     = (const float*)d_in[0];
    const float* w_off = (const float*)d_in[1];
    const float* w_def = (const float*)d_in[2];
    // d_in[3] = b_def: exactly absorbed by batch-norm mean subtraction
    const float* gamma = (const float*)d_in[4];
    const float* beta  = (const float*)d_in[5];
    float* out = (float*)d_out;

    cudaFuncSetAttribute(k_gemm, cudaFuncAttributeMaxDynamicSharedMemorySize, GEMM_SMEM);
    cudaFuncSetAttribute(k_offset2, cudaFuncAttributeMaxDynamicSharedMemorySize, OFF_SMEM);

    dim3 tb(32, 8);
    dim3 tg(HWn / 32, CINc / 32, Bn);
    k_transpose<<<tg, tb>>>(x);

    k_wprep<<<(NCH64 * 8192 + 255) / 256, 256>>>(w_def);
    k_wprep2<<<(NCH64 * 2048 + 255) / 256, 256>>>(w_off);

    k_offset2<<<256, 256, OFF_SMEM>>>();

    k_gather<<<NPIX / 32, 256>>>();

    k_gemm<<<NPIX / TILE_N, 512, GEMM_SMEM>>>(out);

    k_statsfin<<<1, 128>>>(gamma, beta);

    k_norm<<<(Bn * COUTc * HWn / 4 + 255) / 256, 256>>>(out);
}

// round 7
// speedup vs baseline: 4.6944x; 1.0724x over previous
#include <cuda_runtime.h>
#include <cuda_fp16.h>
#include <math.h>
#include <stdint.h>

#define Bn 8
#define CINc 128
#define COUTc 128
#define Hh 64
#define Ww 64
#define HWn 4096
#define KKn 9
#define OFFC 18
#define Kdim 1152            // CIN * KK
#define NPIX 32768           // B * HW
#define TILE_N 128           // pixels per fused-GEMM CTA
#define NCH64 18             // Kdim / 64
#define SRH 72               // smem row stride in halves (64 + pad 8)

// fused gemm smem: 2 stages of (A 128x72 + B 128x72) halves + meta
#define GA_H (128 * SRH)             // 9216 halves
#define GB_H (128 * SRH)             // 9216
#define GSTG_H (GA_H + GB_H)         // 18432
#define META_BYTES (KKn * 128 * 32)  // 36864
#define GEMM_SMEM (2 * GSTG_H * 2 + META_BYTES)   // 110592 B

// offset gemm smem (halves): A 32x72, B 128x72 per stage, 2 stages
#define OA_H (32 * SRH)
#define OB_H (128 * SRH)
#define OSTG_H (OA_H + OB_H)
#define OFF_SMEM (2 * OSTG_H * 2)    // 46080 B

// ---------------- static scratch ----------------
__device__ __half g_xh[Bn * HWn * CINc];     // x NHWC fp16 (8.4 MB)
__device__ float  g_off[Bn * OFFC * HWn];    // offset conv out fp32
__device__ __half g_wtp[NCH64 * 8192];       // w_def packed [ch64][co][64k]
__device__ __half g_woffp[NCH64 * 2048];     // w_off packed [ch64][oc32][64k]
__device__ float  g_psum[COUTc * 256];
__device__ float  g_psq [COUTc * 256];
__device__ float  g_scale[COUTc];
__device__ float  g_shift[COUTc];

// ---------------- helpers ----------------
__device__ __forceinline__ void mma_f16(float* d, const uint32_t* a,
                                        uint32_t b0, uint32_t b1) {
    asm volatile(
        "mma.sync.aligned.m16n8k16.row.col.f32.f16.f16.f32 "
        "{%0,%1,%2,%3}, {%4,%5,%6,%7}, {%8,%9}, {%0,%1,%2,%3};"
        : "+f"(d[0]), "+f"(d[1]), "+f"(d[2]), "+f"(d[3])
        : "r"(a[0]), "r"(a[1]), "r"(a[2]), "r"(a[3]), "r"(b0), "r"(b1));
}
__device__ __forceinline__ uint32_t pkh2(float a, float b) {
    __half2 h = __floats2half2_rn(a, b);
    return *(uint32_t*)&h;
}
__device__ __forceinline__ uint32_t blend4(uint32_t a, uint32_t b,
                                           uint32_t c, uint32_t d, float4 w) {
    float2 fa = __half22float2(*(__half2*)&a);
    float2 fb = __half22float2(*(__half2*)&b);
    float2 fc = __half22float2(*(__half2*)&c);
    float2 fd = __half22float2(*(__half2*)&d);
    return pkh2(w.x * fa.x + w.y * fb.x + w.z * fc.x + w.w * fd.x,
                w.x * fa.y + w.y * fb.y + w.z * fc.y + w.w * fd.y);
}

struct __align__(16) MetaF {
    int   i0, i1, i2, i3;
    float w0, w1, w2, w3;
};

// ---------------------------------------------------------------------------
// Kernel 1: NCHW fp32 -> NHWC fp16 transpose
// ---------------------------------------------------------------------------
__global__ void k_transpose(const float* __restrict__ x) {
    __shared__ float tile[32][33];   // [channel_local][pixel_local]
    int b = blockIdx.z, p0 = blockIdx.x * 32, c0 = blockIdx.y * 32;
    const float* xb = x + (size_t)b * CINc * HWn;
    __half* xtb = g_xh + (size_t)b * HWn * CINc;
    int tx = threadIdx.x, ty = threadIdx.y;
    int tid = ty * 32 + tx;
    #pragma unroll
    for (int j = 0; j < 32; j += 8)
        tile[ty + j][tx] = xb[(size_t)(c0 + ty + j) * HWn + p0 + tx];
    __syncthreads();
    #pragma unroll
    for (int m = 0; m < 2; m++) {
        int u = tid + m * 256;
        int pl = u >> 4, cp = u & 15;
        __half2 v = __floats2half2_rn(tile[cp * 2][pl], tile[cp * 2 + 1][pl]);
        *(__half2*)(xtb + (size_t)(p0 + pl) * CINc + c0 + cp * 2) = v;
    }
}

// ---------------------------------------------------------------------------
// Kernel 2a: pack w_def -> g_wtp[ch64][co][kloc64]; k = ch*64+kloc,
//            kk = k>>7, c = k&127
// ---------------------------------------------------------------------------
__global__ void k_wprep(const float* __restrict__ w_def) {
    int idx = blockIdx.x * 256 + threadIdx.x;
    if (idx >= NCH64 * 8192) return;
    int chunk = idx >> 13, r = idx & 8191;
    int co = r >> 6, kloc = r & 63;
    int k = chunk * 64 + kloc;
    int kk = k >> 7, c = k & 127;
    g_wtp[idx] = __float2half(w_def[(size_t)(co * CINc + c) * KKn + kk]);
}

// Kernel 2b: pack w_off -> g_woffp[ch64][oc32][kloc64];
//            kk = chunk>>1, c = (chunk&1)*64 + kloc; oc >= 18 zero
__global__ void k_wprep2(const float* __restrict__ w_off) {
    int idx = blockIdx.x * 256 + threadIdx.x;
    if (idx >= NCH64 * 2048) return;
    int chunk = idx >> 11, r = idx & 2047;
    int oc = r >> 6, kloc = r & 63;
    int kk = chunk >> 1, c = (chunk & 1) * 64 + kloc;
    g_woffp[idx] = (oc < OFFC)
        ? __float2half(w_off[(size_t)(oc * CINc + c) * KKn + kk])
        : __float2half(0.f);
}

// ---------------------------------------------------------------------------
// Kernel 3: offset conv, fp16 implicit GEMM. 256 CTAs, 256 thr (8 warps).
// CTA tile 32oc x 128pix, warp 32oc x 16pix, 64-k chunks (18 iters).
// ---------------------------------------------------------------------------
__global__ __launch_bounds__(256) void k_offset2() {
    extern __shared__ __half smh[];
    const int tid = threadIdx.x;
    const int wid = tid >> 5, lane = tid & 31;
    const int g = lane >> 2, tc = lane & 3;
    const int wn = wid;

    const int tile = blockIdx.x;          // 0..255
    const int b = tile >> 5;
    const int hw0 = (tile & 31) * 128;
    const int y0 = hw0 >> 6;
    const __half* xhb = g_xh + (size_t)b * HWn * CINc;

    uint4 bufA;
    uint4 bufB[4];

    float acc[2][2][4];
    #pragma unroll
    for (int mt = 0; mt < 2; mt++)
        #pragma unroll
        for (int nt = 0; nt < 2; nt++)
            #pragma unroll
            for (int r = 0; r < 4; r++) acc[mt][nt][r] = 0.f;

    auto ldg_chunk = [&](int i) {
        int kk = i >> 1, c0 = (i & 1) * 64;
        int ky = kk / 3 - 1, kx = kk % 3 - 1;
        #pragma unroll
        for (int m = 0; m < 4; m++) {
            int e = tid + m * 256;
            int pix = e >> 3, j = e & 7;
            int y = y0 + (pix >> 6), xx = pix & 63;
            int ys = y + ky, xs = xx + kx;
            bool valid = ((unsigned)ys < Hh) && ((unsigned)xs < Ww);
            bufB[m] = valid
                ? *(const uint4*)(xhb + (size_t)(ys * Ww + xs) * CINc + c0 + j * 8)
                : make_uint4(0u, 0u, 0u, 0u);
        }
        bufA = *(const uint4*)(g_woffp + (size_t)i * 2048 + tid * 8);
    };
    auto sts_chunk = [&](int st) {
        __half* As = smh + st * OSTG_H;
        __half* Bs = As + OA_H;
        #pragma unroll
        for (int m = 0; m < 4; m++) {
            int e = tid + m * 256;
            int pix = e >> 3, j = e & 7;
            *(uint4*)(Bs + pix * SRH + j * 8) = bufB[m];
        }
        *(uint4*)(As + (tid >> 3) * SRH + (tid & 7) * 8) = bufA;
    };

    ldg_chunk(0); sts_chunk(0);
    ldg_chunk(1);
    __syncthreads();

    for (int i = 0; i < NCH64; i++) {
        if (i + 1 < NCH64) sts_chunk((i + 1) & 1);
        if (i + 2 < NCH64) ldg_chunk(i + 2);
        const __half* As = smh + (i & 1) * OSTG_H;
        const __half* Bs = As + OA_H;
        #pragma unroll
        for (int ks = 0; ks < 4; ks++) {
            uint32_t a[2][4];
            #pragma unroll
            for (int mt = 0; mt < 2; mt++) {
                const __half* ap = As + (mt * 16 + g) * SRH + ks * 16 + tc * 2;
                a[mt][0] = *(const uint32_t*)(ap);
                a[mt][1] = *(const uint32_t*)(ap + 8 * SRH);
                a[mt][2] = *(const uint32_t*)(ap + 8);
                a[mt][3] = *(const uint32_t*)(ap + 8 * SRH + 8);
            }
            #pragma unroll
            for (int nt = 0; nt < 2; nt++) {
                const __half* bp = Bs + (wn * 16 + nt * 8 + g) * SRH + ks * 16 + tc * 2;
                uint32_t b0 = *(const uint32_t*)(bp);
                uint32_t b1 = *(const uint32_t*)(bp + 8);
                #pragma unroll
                for (int mt = 0; mt < 2; mt++)
                    mma_f16(acc[mt][nt], a[mt], b0, b1);
            }
        }
        __syncthreads();
    }

    float* ob = g_off + (size_t)b * OFFC * HWn;
    #pragma unroll
    for (int mt = 0; mt < 2; mt++) {
        #pragma unroll
        for (int nt = 0; nt < 2; nt++) {
            int pix = hw0 + wn * 16 + nt * 8 + tc * 2;
            int r0 = mt * 16 + g, r1 = r0 + 8;
            if (r0 < OFFC)
                *(float2*)&ob[(size_t)r0 * HWn + pix] =
                    make_float2(acc[mt][nt][0], acc[mt][nt][1]);
            if (r1 < OFFC)
                *(float2*)&ob[(size_t)r1 * HWn + pix] =
                    make_float2(acc[mt][nt][2], acc[mt][nt][3]);
        }
    }
}

// ---------------------------------------------------------------------------
// Kernel 4: FUSED bilinear-gather + fp16 mma GEMM.
// D[128co, 128pix] per CTA, 256 CTAs, 512 thr (16 warps 2m x 8n).
// B tile is built in-kernel: meta (idx+fp32 weights) in smem, corners
// loaded fp16 from g_xh, blended fp32, packed half2, STS to stage buffer.
// ---------------------------------------------------------------------------
__global__ __launch_bounds__(512, 1) void k_gemm(float* __restrict__ out) {
    extern __shared__ char smraw[];
    __half* smh  = (__half*)smraw;                       // 2 stages
    MetaF*  meta = (MetaF*)(smraw + 2 * GSTG_H * 2);     // [kk][pix]

    const int tid = threadIdx.x;
    const int wid = tid >> 5, lane = tid & 31;
    const int wm = wid >> 3, wn = wid & 7;
    const int g = lane >> 2, tc = lane & 3;
    const int tilebase = blockIdx.x * TILE_N;
    const int b = tilebase >> 12, hw0 = tilebase & 4095;
    const int ybase = hw0 >> 6;
    const __half* xhb = g_xh + (size_t)b * HWn * CINc;

    // ---- phase 0: bilinear metadata for 9 kk x 128 pix ----
    const float* offb = g_off + (size_t)b * OFFC * HWn;
    for (int t = tid; t < KKn * 128; t += 512) {
        int kk = t >> 7, p = t & 127;
        int hw = hw0 + p, xx = hw & 63;
        int y = ybase + (p >> 6);
        float dy = offb[(size_t)(kk * 2 + 0) * HWn + hw];
        float dx = offb[(size_t)(kk * 2 + 1) * HWn + hw];
        float ys = (float)(y - 1 + kk / 3) + dy;
        float xs = (float)(xx - 1 + kk % 3) + dx;
        float y0f = floorf(ys), x0f = floorf(xs);
        float wy = ys - y0f, wx = xs - x0f;
        int y0 = (int)y0f, x0 = (int)x0f;
        bool vy0 = (y0 >= 0) && (y0 < Hh);
        bool vy1 = (y0 + 1 >= 0) && (y0 + 1 < Hh);
        bool vx0 = (x0 >= 0) && (x0 < Ww);
        bool vx1 = (x0 + 1 >= 0) && (x0 + 1 < Ww);
        MetaF m;
        m.w0 = (vy0 && vx0) ? (1.f - wy) * (1.f - wx) : 0.f;
        m.w1 = (vy0 && vx1) ? (1.f - wy) * wx : 0.f;
        m.w2 = (vy1 && vx0) ? wy * (1.f - wx) : 0.f;
        m.w3 = (vy1 && vx1) ? wy * wx : 0.f;
        m.i0 = (vy0 && vx0) ? (y0 * Ww + x0) * CINc : 0;
        m.i1 = (vy0 && vx1) ? (y0 * Ww + x0 + 1) * CINc : 0;
        m.i2 = (vy1 && vx0) ? ((y0 + 1) * Ww + x0) * CINc : 0;
        m.i3 = (vy1 && vx1) ? ((y0 + 1) * Ww + x0 + 1) * CINc : 0;
        meta[t] = m;
    }
    __syncthreads();

    float acc[4][2][4];
    #pragma unroll
    for (int mt = 0; mt < 4; mt++)
        #pragma unroll
        for (int nt = 0; nt < 2; nt++)
            #pragma unroll
            for (int r = 0; r < 4; r++) acc[mt][nt][r] = 0.f;

    // per-thread B build: pix = tid>>2, chq = tid&3 (16 channels)
    const int bpix = tid >> 2, bchq = tid & 3;

    uint4 bufA[2];
    uint4 cb[4][2];
    float4 wv;

    auto ldg_chunk = [&](int i) {
        #pragma unroll
        for (int m = 0; m < 2; m++) {
            int e = tid + m * 512;
            bufA[m] = *(const uint4*)(g_wtp + (size_t)i * 8192 + e * 8);
        }
        int kk = i >> 1;
        MetaF m = meta[kk * 128 + bpix];
        wv = make_float4(m.w0, m.w1, m.w2, m.w3);
        const __half* base = xhb + (i & 1) * 64 + bchq * 16;
        cb[0][0] = *(const uint4*)(base + m.i0);
        cb[0][1] = *(const uint4*)(base + m.i0 + 8);
        cb[1][0] = *(const uint4*)(base + m.i1);
        cb[1][1] = *(const uint4*)(base + m.i1 + 8);
        cb[2][0] = *(const uint4*)(base + m.i2);
        cb[2][1] = *(const uint4*)(base + m.i2 + 8);
        cb[3][0] = *(const uint4*)(base + m.i3);
        cb[3][1] = *(const uint4*)(base + m.i3 + 8);
    };
    auto sts_chunk = [&](int st) {
        __half* As = smh + st * GSTG_H;
        __half* Bs = As + GA_H;
        #pragma unroll
        for (int m = 0; m < 2; m++) {
            int e = tid + m * 512;
            *(uint4*)(As + (e >> 3) * SRH + (e & 7) * 8) = bufA[m];
        }
        uint4 o0, o1;
        o0.x = blend4(cb[0][0].x, cb[1][0].x, cb[2][0].x, cb[3][0].x, wv);
        o0.y = blend4(cb[0][0].y, cb[1][0].y, cb[2][0].y, cb[3][0].y, wv);
        o0.z = blend4(cb[0][0].z, cb[1][0].z, cb[2][0].z, cb[3][0].z, wv);
        o0.w = blend4(cb[0][0].w, cb[1][0].w, cb[2][0].w, cb[3][0].w, wv);
        o1.x = blend4(cb[0][1].x, cb[1][1].x, cb[2][1].x, cb[3][1].x, wv);
        o1.y = blend4(cb[0][1].y, cb[1][1].y, cb[2][1].y, cb[3][1].y, wv);
        o1.z = blend4(cb[0][1].z, cb[1][1].z, cb[2][1].z, cb[3][1].z, wv);
        o1.w = blend4(cb[0][1].w, cb[1][1].w, cb[2][1].w, cb[3][1].w, wv);
        *(uint4*)(Bs + bpix * SRH + bchq * 16) = o0;
        *(uint4*)(Bs + bpix * SRH + bchq * 16 + 8) = o1;
    };

    ldg_chunk(0); sts_chunk(0);
    ldg_chunk(1);
    __syncthreads();

    for (int i = 0; i < NCH64; i++) {
        if (i + 1 < NCH64) sts_chunk((i + 1) & 1);
        if (i + 2 < NCH64) ldg_chunk(i + 2);

        const __half* As = smh + (i & 1) * GSTG_H;
        const __half* Bs = As + GA_H;
        #pragma unroll
        for (int ks = 0; ks < 4; ks++) {
            uint32_t a[4][4];
            #pragma unroll
            for (int mt = 0; mt < 4; mt++) {
                const __half* ap = As + (wm * 64 + mt * 16 + g) * SRH + ks * 16 + tc * 2;
                a[mt][0] = *(const uint32_t*)(ap);
                a[mt][1] = *(const uint32_t*)(ap + 8 * SRH);
                a[mt][2] = *(const uint32_t*)(ap + 8);
                a[mt][3] = *(const uint32_t*)(ap + 8 * SRH + 8);
            }
            #pragma unroll
            for (int nt = 0; nt < 2; nt++) {
                const __half* bp = Bs + (wn * 16 + nt * 8 + g) * SRH + ks * 16 + tc * 2;
                uint32_t b0 = *(const uint32_t*)(bp);
                uint32_t b1 = *(const uint32_t*)(bp + 8);
                #pragma unroll
                for (int mt = 0; mt < 4; mt++)
                    mma_f16(acc[mt][nt], a[mt], b0, b1);
            }
        }
        __syncthreads();
    }

    // ---- store results ----
    #pragma unroll
    for (int mt = 0; mt < 4; mt++) {
        #pragma unroll
        for (int nt = 0; nt < 2; nt++) {
            int pix = hw0 + wn * 16 + nt * 8 + tc * 2;
            int co0 = wm * 64 + mt * 16 + g;
            *(float2*)&out[((size_t)b * COUTc + co0) * HWn + pix] =
                make_float2(acc[mt][nt][0], acc[mt][nt][1]);
            *(float2*)&out[((size_t)b * COUTc + co0 + 8) * HWn + pix] =
                make_float2(acc[mt][nt][2], acc[mt][nt][3]);
        }
    }

    // ---- deterministic BN partials ----
    float s[8], q[8];
    #pragma unroll
    for (int i = 0; i < 8; i++) { s[i] = 0.f; q[i] = 0.f; }
    #pragma unroll
    for (int mt = 0; mt < 4; mt++)
        #pragma unroll
        for (int r = 0; r < 2; r++) {
            int sl = mt * 2 + r;
            #pragma unroll
            for (int nt = 0; nt < 2; nt++) {
                float v0 = acc[mt][nt][r * 2], v1 = acc[mt][nt][r * 2 + 1];
                s[sl] += v0 + v1;
                q[sl] += v0 * v0 + v1 * v1;
            }
        }
    #pragma unroll
    for (int m = 1; m <= 2; m <<= 1)
        #pragma unroll
        for (int i = 0; i < 8; i++) {
            s[i] += __shfl_xor_sync(0xFFFFFFFF, s[i], m);
            q[i] += __shfl_xor_sync(0xFFFFFFFF, q[i], m);
        }

    __syncthreads();
    float* sb = (float*)smraw;
    float* qb = sb + 1024;
    if (tc == 0) {
        #pragma unroll
        for (int mt = 0; mt < 4; mt++)
            #pragma unroll
            for (int r = 0; r < 2; r++) {
                int cl = mt * 16 + r * 8 + g;
                sb[wid * 64 + cl] = s[mt * 2 + r];
                qb[wid * 64 + cl] = q[mt * 2 + r];
            }
    }
    __syncthreads();
    if (tid < COUTc) {
        int co = tid;
        float ss = 0.f, qq = 0.f;
        #pragma unroll
        for (int w = 0; w < 8; w++) {
            ss += sb[((co >> 6) * 8 + w) * 64 + (co & 63)];
            qq += qb[((co >> 6) * 8 + w) * 64 + (co & 63)];
        }
        g_psum[co * 256 + blockIdx.x] = ss;
        g_psq [co * 256 + blockIdx.x] = qq;
    }
}

// ---------------------------------------------------------------------------
// Kernel 5: finalize BN stats
// ---------------------------------------------------------------------------
__global__ void k_statsfin(const float* __restrict__ gamma, const float* __restrict__ beta) {
    int co = threadIdx.x;
    float s = 0.f, q = 0.f;
    for (int j = 0; j < 256; j++) { s += g_psum[co * 256 + j]; q += g_psq[co * 256 + j]; }
    const float inv_n = 1.f / (float)NPIX;
    float mean = s * inv_n;
    float var  = q * inv_n - mean * mean;
    float sc   = gamma[co] * rsqrtf(var + 1e-5f);
    g_scale[co] = sc;
    g_shift[co] = beta[co] - mean * sc;
}

// ---------------------------------------------------------------------------
// Kernel 6: normalize + SiLU (in place)
// ---------------------------------------------------------------------------
__global__ void k_norm(float* __restrict__ out) {
    int idx = blockIdx.x * 256 + threadIdx.x;
    const int n4 = Bn * COUTc * HWn / 4;
    if (idx >= n4) return;
    int co = (idx >> 10) & 127;
    float sc = g_scale[co], sh = g_shift[co];
    float4* o4 = (float4*)out;
    float4 v = o4[idx];
    float u;
    u = v.x * sc + sh; v.x = u / (1.f + expf(-u));
    u = v.y * sc + sh; v.y = u / (1.f + expf(-u));
    u = v.z * sc + sh; v.z = u / (1.f + expf(-u));
    u = v.w * sc + sh; v.w = u / (1.f + expf(-u));
    o4[idx] = v;
}

// ---------------------------------------------------------------------------
extern "C" void kernel_launch(void* const* d_in, const int* in_sizes, int n_in,
                              void* d_out, int out_size) {
    const float* x     = (const float*)d_in[0];
    const float* w_off = (const float*)d_in[1];
    const float* w_def = (const float*)d_in[2];
    // d_in[3] = b_def: exactly absorbed by batch-norm mean subtraction
    const float* gamma = (const float*)d_in[4];
    const float* beta  = (const float*)d_in[5];
    float* out = (float*)d_out;

    cudaFuncSetAttribute(k_gemm, cudaFuncAttributeMaxDynamicSharedMemorySize, GEMM_SMEM);
    cudaFuncSetAttribute(k_offset2, cudaFuncAttributeMaxDynamicSharedMemorySize, OFF_SMEM);

    dim3 tb(32, 8);
    dim3 tg(HWn / 32, CINc / 32, Bn);
    k_transpose<<<tg, tb>>>(x);

    k_wprep<<<(NCH64 * 8192 + 255) / 256, 256>>>(w_def);
    k_wprep2<<<(NCH64 * 2048 + 255) / 256, 256>>>(w_off);

    k_offset2<<<256, 256, OFF_SMEM>>>();

    k_gemm<<<NPIX / TILE_N, 512, GEMM_SMEM>>>(out);

    k_statsfin<<<1, 128>>>(gamma, beta);

    k_norm<<<(Bn * COUTc * HWn / 4 + 255) / 256, 256>>>(out);
}

// round 8
// speedup vs baseline: 5.7797x; 1.2312x over previous
#include <cuda_runtime.h>
#include <cuda_fp16.h>
#include <math.h>
#include <stdint.h>

#define Bn 8
#define CINc 128
#define COUTc 128
#define Hh 64
#define Ww 64
#define HWn 4096
#define KKn 9
#define OFFC 18
#define Kdim 1152            // CIN * KK
#define NPIX 32768           // B * HW
#define TILE_N 128           // pixels per fused-GEMM CTA
#define NCH64 18             // Kdim / 64
#define SRH 72               // smem row stride in halves (64 + pad 8)

// fused gemm smem: 2 stages of (A 128x72 + B 128x72) halves + meta
#define GA_H (128 * SRH)             // 9216 halves
#define GB_H (128 * SRH)             // 9216
#define GSTG_H (GA_H + GB_H)         // 18432
#define META_BYTES (KKn * 128 * 32)  // 36864
#define GEMM_SMEM (2 * GSTG_H * 2 + META_BYTES)   // 110592 B

// offset gemm smem (halves): A 32x72, B 128x72 per stage, 2 stages
#define OA_H (32 * SRH)
#define OB_H (128 * SRH)
#define OSTG_H (OA_H + OB_H)
#define OFF_SMEM (2 * OSTG_H * 2)    // 46080 B

// ---------------- static scratch ----------------
__device__ __half g_xh[Bn * HWn * CINc];     // x NHWC fp16 (8.4 MB)
__device__ float  g_off[Bn * OFFC * HWn];    // offset conv out fp32
__device__ __half g_wtp[NCH64 * 8192];       // w_def packed [ch64][co][64k]
__device__ __half g_woffp[NCH64 * 2048];     // w_off packed [ch64][oc32][64k]
__device__ float  g_psum[COUTc * 256];
__device__ float  g_psq [COUTc * 256];
__device__ float  g_scale[COUTc];
__device__ float  g_shift[COUTc];

// ---------------- helpers ----------------
__device__ __forceinline__ void mma_f16(float* d, const uint32_t* a,
                                        uint32_t b0, uint32_t b1) {
    asm volatile(
        "mma.sync.aligned.m16n8k16.row.col.f32.f16.f16.f32 "
        "{%0,%1,%2,%3}, {%4,%5,%6,%7}, {%8,%9}, {%0,%1,%2,%3};"
        : "+f"(d[0]), "+f"(d[1]), "+f"(d[2]), "+f"(d[3])
        : "r"(a[0]), "r"(a[1]), "r"(a[2]), "r"(a[3]), "r"(b0), "r"(b1));
}
__device__ __forceinline__ void ldsm_x4(uint32_t* r, uint32_t addr) {
    asm volatile("ldmatrix.sync.aligned.m8n8.x4.shared.b16 {%0,%1,%2,%3}, [%4];"
                 : "=r"(r[0]), "=r"(r[1]), "=r"(r[2]), "=r"(r[3]) : "r"(addr));
}
__device__ __forceinline__ void ldsm_x2(uint32_t& r0, uint32_t& r1, uint32_t addr) {
    asm volatile("ldmatrix.sync.aligned.m8n8.x2.shared.b16 {%0,%1}, [%2];"
                 : "=r"(r0), "=r"(r1) : "r"(addr));
}
__device__ __forceinline__ uint32_t s2u(const void* p) {
    return (uint32_t)__cvta_generic_to_shared(p);
}
__device__ __forceinline__ uint32_t pkh2(float a, float b) {
    __half2 h = __floats2half2_rn(a, b);
    return *(uint32_t*)&h;
}
__device__ __forceinline__ uint32_t blend4(uint32_t a, uint32_t b,
                                           uint32_t c, uint32_t d, float4 w) {
    float2 fa = __half22float2(*(__half2*)&a);
    float2 fb = __half22float2(*(__half2*)&b);
    float2 fc = __half22float2(*(__half2*)&c);
    float2 fd = __half22float2(*(__half2*)&d);
    return pkh2(w.x * fa.x + w.y * fb.x + w.z * fc.x + w.w * fd.x,
                w.x * fa.y + w.y * fb.y + w.z * fc.y + w.w * fd.y);
}

struct __align__(16) MetaF {
    int   i0, i1, i2, i3;
    float w0, w1, w2, w3;
};

// lane offsets for ldmatrix source rows (in BYTES)
// A x4: tiles (r0,k0),(r8,k0),(r0,k8),(r8,k8): row += lane&15, koff = (lane>>4)*8
#define LANE_OFF_A(lane) ((((lane) & 15) * SRH + (((lane) >> 4) << 3)) * 2)
// B x2: tiles (n0,k0),(n0,k8): row += lane&7, koff = ((lane>>3)&1)*8
#define LANE_OFF_B(lane) ((((lane) & 7) * SRH + ((((lane) >> 3) & 1) << 3)) * 2)

// ---------------------------------------------------------------------------
// Kernel 1: NCHW fp32 -> NHWC fp16 transpose
// ---------------------------------------------------------------------------
__global__ void k_transpose(const float* __restrict__ x) {
    __shared__ float tile[32][33];
    int b = blockIdx.z, p0 = blockIdx.x * 32, c0 = blockIdx.y * 32;
    const float* xb = x + (size_t)b * CINc * HWn;
    __half* xtb = g_xh + (size_t)b * HWn * CINc;
    int tx = threadIdx.x, ty = threadIdx.y;
    int tid = ty * 32 + tx;
    #pragma unroll
    for (int j = 0; j < 32; j += 8)
        tile[ty + j][tx] = xb[(size_t)(c0 + ty + j) * HWn + p0 + tx];
    __syncthreads();
    #pragma unroll
    for (int m = 0; m < 2; m++) {
        int u = tid + m * 256;
        int pl = u >> 4, cp = u & 15;
        __half2 v = __floats2half2_rn(tile[cp * 2][pl], tile[cp * 2 + 1][pl]);
        *(__half2*)(xtb + (size_t)(p0 + pl) * CINc + c0 + cp * 2) = v;
    }
}

// ---------------------------------------------------------------------------
// Kernel 2a/2b: weight packs
// ---------------------------------------------------------------------------
__global__ void k_wprep(const float* __restrict__ w_def) {
    int idx = blockIdx.x * 256 + threadIdx.x;
    if (idx >= NCH64 * 8192) return;
    int chunk = idx >> 13, r = idx & 8191;
    int co = r >> 6, kloc = r & 63;
    int k = chunk * 64 + kloc;
    int kk = k >> 7, c = k & 127;
    g_wtp[idx] = __float2half(w_def[(size_t)(co * CINc + c) * KKn + kk]);
}
__global__ void k_wprep2(const float* __restrict__ w_off) {
    int idx = blockIdx.x * 256 + threadIdx.x;
    if (idx >= NCH64 * 2048) return;
    int chunk = idx >> 11, r = idx & 2047;
    int oc = r >> 6, kloc = r & 63;
    int kk = chunk >> 1, c = (chunk & 1) * 64 + kloc;
    g_woffp[idx] = (oc < OFFC)
        ? __float2half(w_off[(size_t)(oc * CINc + c) * KKn + kk])
        : __float2half(0.f);
}

// ---------------------------------------------------------------------------
// Kernel 3: offset conv, fp16 implicit GEMM with ldmatrix fragments.
// ---------------------------------------------------------------------------
__global__ __launch_bounds__(256) void k_offset2() {
    extern __shared__ __half smh[];
    const int tid = threadIdx.x;
    const int wid = tid >> 5, lane = tid & 31;
    const int g = lane >> 2, tc = lane & 3;
    const int wn = wid;

    const int tile = blockIdx.x;
    const int b = tile >> 5;
    const int hw0 = (tile & 31) * 128;
    const int y0 = hw0 >> 6;
    const __half* xhb = g_xh + (size_t)b * HWn * CINc;

    const uint32_t sbase = s2u(smh);
    const uint32_t laneA = LANE_OFF_A(lane);
    const uint32_t laneB = LANE_OFF_B(lane);

    uint4 bufA;
    uint4 bufB[4];

    float acc[2][2][4];
    #pragma unroll
    for (int mt = 0; mt < 2; mt++)
        #pragma unroll
        for (int nt = 0; nt < 2; nt++)
            #pragma unroll
            for (int r = 0; r < 4; r++) acc[mt][nt][r] = 0.f;

    auto ldg_chunk = [&](int i) {
        int kk = i >> 1, c0 = (i & 1) * 64;
        int ky = kk / 3 - 1, kx = kk % 3 - 1;
        #pragma unroll
        for (int m = 0; m < 4; m++) {
            int e = tid + m * 256;
            int pix = e >> 3, j = e & 7;
            int y = y0 + (pix >> 6), xx = pix & 63;
            int ys = y + ky, xs = xx + kx;
            bool valid = ((unsigned)ys < Hh) && ((unsigned)xs < Ww);
            bufB[m] = valid
                ? *(const uint4*)(xhb + (size_t)(ys * Ww + xs) * CINc + c0 + j * 8)
                : make_uint4(0u, 0u, 0u, 0u);
        }
        bufA = *(const uint4*)(g_woffp + (size_t)i * 2048 + tid * 8);
    };
    auto sts_chunk = [&](int st) {
        __half* As = smh + st * OSTG_H;
        __half* Bs = As + OA_H;
        #pragma unroll
        for (int m = 0; m < 4; m++) {
            int e = tid + m * 256;
            int pix = e >> 3, j = e & 7;
            *(uint4*)(Bs + pix * SRH + j * 8) = bufB[m];
        }
        *(uint4*)(As + (tid >> 3) * SRH + (tid & 7) * 8) = bufA;
    };

    ldg_chunk(0); sts_chunk(0);
    ldg_chunk(1);
    __syncthreads();

    for (int i = 0; i < NCH64; i++) {
        if (i + 1 < NCH64) sts_chunk((i + 1) & 1);
        if (i + 2 < NCH64) ldg_chunk(i + 2);
        const uint32_t aAs = sbase + (uint32_t)((i & 1) * OSTG_H) * 2;
        const uint32_t aBs = aAs + OA_H * 2;
        #pragma unroll
        for (int ks = 0; ks < 4; ks++) {
            uint32_t a[2][4];
            #pragma unroll
            for (int mt = 0; mt < 2; mt++)
                ldsm_x4(a[mt], aAs + (uint32_t)((mt * 16) * SRH + ks * 16) * 2 + laneA);
            #pragma unroll
            for (int nt = 0; nt < 2; nt++) {
                uint32_t b0, b1;
                ldsm_x2(b0, b1, aBs + (uint32_t)((wn * 16 + nt * 8) * SRH + ks * 16) * 2 + laneB);
                #pragma unroll
                for (int mt = 0; mt < 2; mt++)
                    mma_f16(acc[mt][nt], a[mt], b0, b1);
            }
        }
        __syncthreads();
    }

    float* ob = g_off + (size_t)b * OFFC * HWn;
    #pragma unroll
    for (int mt = 0; mt < 2; mt++) {
        #pragma unroll
        for (int nt = 0; nt < 2; nt++) {
            int pix = hw0 + wn * 16 + nt * 8 + tc * 2;
            int r0 = mt * 16 + g, r1 = r0 + 8;
            if (r0 < OFFC)
                *(float2*)&ob[(size_t)r0 * HWn + pix] =
                    make_float2(acc[mt][nt][0], acc[mt][nt][1]);
            if (r1 < OFFC)
                *(float2*)&ob[(size_t)r1 * HWn + pix] =
                    make_float2(acc[mt][nt][2], acc[mt][nt][3]);
        }
    }
}

// ---------------------------------------------------------------------------
// Kernel 4: FUSED bilinear-gather + fp16 mma GEMM (ldmatrix fragments).
// ---------------------------------------------------------------------------
__global__ __launch_bounds__(512, 1) void k_gemm(float* __restrict__ out) {
    extern __shared__ char smraw[];
    __half* smh  = (__half*)smraw;
    MetaF*  meta = (MetaF*)(smraw + 2 * GSTG_H * 2);

    const int tid = threadIdx.x;
    const int wid = tid >> 5, lane = tid & 31;
    const int wm = wid >> 3, wn = wid & 7;
    const int g = lane >> 2, tc = lane & 3;
    const int tilebase = blockIdx.x * TILE_N;
    const int b = tilebase >> 12, hw0 = tilebase & 4095;
    const int ybase = hw0 >> 6;
    const __half* xhb = g_xh + (size_t)b * HWn * CINc;

    const uint32_t sbase = s2u(smh);
    const uint32_t laneA = LANE_OFF_A(lane);
    const uint32_t laneB = LANE_OFF_B(lane);

    // ---- phase 0: bilinear metadata ----
    const float* offb = g_off + (size_t)b * OFFC * HWn;
    for (int t = tid; t < KKn * 128; t += 512) {
        int kk = t >> 7, p = t & 127;
        int hw = hw0 + p, xx = hw & 63;
        int y = ybase + (p >> 6);
        float dy = offb[(size_t)(kk * 2 + 0) * HWn + hw];
        float dx = offb[(size_t)(kk * 2 + 1) * HWn + hw];
        float ys = (float)(y - 1 + kk / 3) + dy;
        float xs = (float)(xx - 1 + kk % 3) + dx;
        float y0f = floorf(ys), x0f = floorf(xs);
        float wy = ys - y0f, wx = xs - x0f;
        int y0 = (int)y0f, x0 = (int)x0f;
        bool vy0 = (y0 >= 0) && (y0 < Hh);
        bool vy1 = (y0 + 1 >= 0) && (y0 + 1 < Hh);
        bool vx0 = (x0 >= 0) && (x0 < Ww);
        bool vx1 = (x0 + 1 >= 0) && (x0 + 1 < Ww);
        MetaF m;
        m.w0 = (vy0 && vx0) ? (1.f - wy) * (1.f - wx) : 0.f;
        m.w1 = (vy0 && vx1) ? (1.f - wy) * wx : 0.f;
        m.w2 = (vy1 && vx0) ? wy * (1.f - wx) : 0.f;
        m.w3 = (vy1 && vx1) ? wy * wx : 0.f;
        m.i0 = (vy0 && vx0) ? (y0 * Ww + x0) * CINc : 0;
        m.i1 = (vy0 && vx1) ? (y0 * Ww + x0 + 1) * CINc : 0;
        m.i2 = (vy1 && vx0) ? ((y0 + 1) * Ww + x0) * CINc : 0;
        m.i3 = (vy1 && vx1) ? ((y0 + 1) * Ww + x0 + 1) * CINc : 0;
        meta[t] = m;
    }
    __syncthreads();

    float acc[4][2][4];
    #pragma unroll
    for (int mt = 0; mt < 4; mt++)
        #pragma unroll
        for (int nt = 0; nt < 2; nt++)
            #pragma unroll
            for (int r = 0; r < 4; r++) acc[mt][nt][r] = 0.f;

    const int bpix = tid >> 2, bchq = tid & 3;

    uint4 bufA[2];
    uint4 cb[4][2];
    float4 wv;

    auto ldg_chunk = [&](int i) {
        #pragma unroll
        for (int m = 0; m < 2; m++) {
            int e = tid + m * 512;
            bufA[m] = *(const uint4*)(g_wtp + (size_t)i * 8192 + e * 8);
        }
        int kk = i >> 1;
        MetaF m = meta[kk * 128 + bpix];
        wv = make_float4(m.w0, m.w1, m.w2, m.w3);
        const __half* base = xhb + (i & 1) * 64 + bchq * 16;
        cb[0][0] = *(const uint4*)(base + m.i0);
        cb[0][1] = *(const uint4*)(base + m.i0 + 8);
        cb[1][0] = *(const uint4*)(base + m.i1);
        cb[1][1] = *(const uint4*)(base + m.i1 + 8);
        cb[2][0] = *(const uint4*)(base + m.i2);
        cb[2][1] = *(const uint4*)(base + m.i2 + 8);
        cb[3][0] = *(const uint4*)(base + m.i3);
        cb[3][1] = *(const uint4*)(base + m.i3 + 8);
    };
    auto sts_chunk = [&](int st) {
        __half* As = smh + st * GSTG_H;
        __half* Bs = As + GA_H;
        #pragma unroll
        for (int m = 0; m < 2; m++) {
            int e = tid + m * 512;
            *(uint4*)(As + (e >> 3) * SRH + (e & 7) * 8) = bufA[m];
        }
        uint4 o0, o1;
        o0.x = blend4(cb[0][0].x, cb[1][0].x, cb[2][0].x, cb[3][0].x, wv);
        o0.y = blend4(cb[0][0].y, cb[1][0].y, cb[2][0].y, cb[3][0].y, wv);
        o0.z = blend4(cb[0][0].z, cb[1][0].z, cb[2][0].z, cb[3][0].z, wv);
        o0.w = blend4(cb[0][0].w, cb[1][0].w, cb[2][0].w, cb[3][0].w, wv);
        o1.x = blend4(cb[0][1].x, cb[1][1].x, cb[2][1].x, cb[3][1].x, wv);
        o1.y = blend4(cb[0][1].y, cb[1][1].y, cb[2][1].y, cb[3][1].y, wv);
        o1.z = blend4(cb[0][1].z, cb[1][1].z, cb[2][1].z, cb[3][1].z, wv);
        o1.w = blend4(cb[0][1].w, cb[1][1].w, cb[2][1].w, cb[3][1].w, wv);
        *(uint4*)(Bs + bpix * SRH + bchq * 16) = o0;
        *(uint4*)(Bs + bpix * SRH + bchq * 16 + 8) = o1;
    };

    ldg_chunk(0); sts_chunk(0);
    ldg_chunk(1);
    __syncthreads();

    for (int i = 0; i < NCH64; i++) {
        if (i + 1 < NCH64) sts_chunk((i + 1) & 1);
        if (i + 2 < NCH64) ldg_chunk(i + 2);

        const uint32_t aAs = sbase + (uint32_t)((i & 1) * GSTG_H) * 2;
        const uint32_t aBs = aAs + GA_H * 2;
        #pragma unroll
        for (int ks = 0; ks < 4; ks++) {
            uint32_t a[4][4];
            #pragma unroll
            for (int mt = 0; mt < 4; mt++)
                ldsm_x4(a[mt], aAs + (uint32_t)((wm * 64 + mt * 16) * SRH + ks * 16) * 2 + laneA);
            #pragma unroll
            for (int nt = 0; nt < 2; nt++) {
                uint32_t b0, b1;
                ldsm_x2(b0, b1, aBs + (uint32_t)((wn * 16 + nt * 8) * SRH + ks * 16) * 2 + laneB);
                #pragma unroll
                for (int mt = 0; mt < 4; mt++)
                    mma_f16(acc[mt][nt], a[mt], b0, b1);
            }
        }
        __syncthreads();
    }

    // ---- store results ----
    #pragma unroll
    for (int mt = 0; mt < 4; mt++) {
        #pragma unroll
        for (int nt = 0; nt < 2; nt++) {
            int pix = hw0 + wn * 16 + nt * 8 + tc * 2;
            int co0 = wm * 64 + mt * 16 + g;
            *(float2*)&out[((size_t)b * COUTc + co0) * HWn + pix] =
                make_float2(acc[mt][nt][0], acc[mt][nt][1]);
            *(float2*)&out[((size_t)b * COUTc + co0 + 8) * HWn + pix] =
                make_float2(acc[mt][nt][2], acc[mt][nt][3]);
        }
    }

    // ---- deterministic BN partials ----
    float s[8], q[8];
    #pragma unroll
    for (int i = 0; i < 8; i++) { s[i] = 0.f; q[i] = 0.f; }
    #pragma unroll
    for (int mt = 0; mt < 4; mt++)
        #pragma unroll
        for (int r = 0; r < 2; r++) {
            int sl = mt * 2 + r;
            #pragma unroll
            for (int nt = 0; nt < 2; nt++) {
                float v0 = acc[mt][nt][r * 2], v1 = acc[mt][nt][r * 2 + 1];
                s[sl] += v0 + v1;
                q[sl] += v0 * v0 + v1 * v1;
            }
        }
    #pragma unroll
    for (int m = 1; m <= 2; m <<= 1)
        #pragma unroll
        for (int i = 0; i < 8; i++) {
            s[i] += __shfl_xor_sync(0xFFFFFFFF, s[i], m);
            q[i] += __shfl_xor_sync(0xFFFFFFFF, q[i], m);
        }

    __syncthreads();
    float* sb = (float*)smraw;
    float* qb = sb + 1024;
    if (tc == 0) {
        #pragma unroll
        for (int mt = 0; mt < 4; mt++)
            #pragma unroll
            for (int r = 0; r < 2; r++) {
                int cl = mt * 16 + r * 8 + g;
                sb[wid * 64 + cl] = s[mt * 2 + r];
                qb[wid * 64 + cl] = q[mt * 2 + r];
            }
    }
    __syncthreads();
    if (tid < COUTc) {
        int co = tid;
        float ss = 0.f, qq = 0.f;
        #pragma unroll
        for (int w = 0; w < 8; w++) {
            ss += sb[((co >> 6) * 8 + w) * 64 + (co & 63)];
            qq += qb[((co >> 6) * 8 + w) * 64 + (co & 63)];
        }
        g_psum[co * 256 + blockIdx.x] = ss;
        g_psq [co * 256 + blockIdx.x] = qq;
    }
}

// ---------------------------------------------------------------------------
// Kernel 5: finalize BN stats (float4 reads)
// ---------------------------------------------------------------------------
__global__ void k_statsfin(const float* __restrict__ gamma, const float* __restrict__ beta) {
    int co = threadIdx.x;
    float s = 0.f, q = 0.f;
    const float4* ps = (const float4*)(g_psum + co * 256);
    const float4* pq = (const float4*)(g_psq  + co * 256);
    #pragma unroll 8
    for (int j = 0; j < 64; j++) {
        float4 a = ps[j], c = pq[j];
        s += (a.x + a.y) + (a.z + a.w);
        q += (c.x + c.y) + (c.z + c.w);
    }
    const float inv_n = 1.f / (float)NPIX;
    float mean = s * inv_n;
    float var  = q * inv_n - mean * mean;
    float sc   = gamma[co] * rsqrtf(var + 1e-5f);
    g_scale[co] = sc;
    g_shift[co] = beta[co] - mean * sc;
}

// ---------------------------------------------------------------------------
// Kernel 6: normalize + SiLU (in place, fast exp)
// ---------------------------------------------------------------------------
__global__ void k_norm(float* __restrict__ out) {
    int idx = blockIdx.x * 256 + threadIdx.x;
    const int n4 = Bn * COUTc * HWn / 4;
    if (idx >= n4) return;
    int co = (idx >> 10) & 127;
    float sc = g_scale[co], sh = g_shift[co];
    float4* o4 = (float4*)out;
    float4 v = o4[idx];
    float u;
    u = v.x * sc + sh; v.x = u / (1.f + __expf(-u));
    u = v.y * sc + sh; v.y = u / (1.f + __expf(-u));
    u = v.z * sc + sh; v.z = u / (1.f + __expf(-u));
    u = v.w * sc + sh; v.w = u / (1.f + __expf(-u));
    o4[idx] = v;
}

// ---------------------------------------------------------------------------
extern "C" void kernel_launch(void* const* d_in, const int* in_sizes, int n_in,
                              void* d_out, int out_size) {
    const float* x     = (const float*)d_in[0];
    const float* w_off = (const float*)d_in[1];
    const float* w_def = (const float*)d_in[2];
    // d_in[3] = b_def: exactly absorbed by batch-norm mean subtraction
    const float* gamma = (const float*)d_in[4];
    const float* beta  = (const float*)d_in[5];
    float* out = (float*)d_out;

    cudaFuncSetAttribute(k_gemm, cudaFuncAttributeMaxDynamicSharedMemorySize, GEMM_SMEM);
    cudaFuncSetAttribute(k_offset2, cudaFuncAttributeMaxDynamicSharedMemorySize, OFF_SMEM);

    dim3 tb(32, 8);
    dim3 tg(HWn / 32, CINc / 32, Bn);
    k_transpose<<<tg, tb>>>(x);

    k_wprep<<<(NCH64 * 8192 + 255) / 256, 256>>>(w_def);
    k_wprep2<<<(NCH64 * 2048 + 255) / 256, 256>>>(w_off);

    k_offset2<<<256, 256, OFF_SMEM>>>();

    k_gemm<<<NPIX / TILE_N, 512, GEMM_SMEM>>>(out);

    k_statsfin<<<1, 128>>>(gamma, beta);

    k_norm<<<(Bn * COUTc * HWn / 4 + 255) / 256, 256>>>(out);
}

// round 9
// speedup vs baseline: 5.8843x; 1.0181x over previous
#include <cuda_runtime.h>
#include <cuda_fp16.h>
#include <math.h>
#include <stdint.h>

#define Bn 8
#define CINc 128
#define COUTc 128
#define Hh 64
#define Ww 64
#define HWn 4096
#define KKn 9
#define OFFC 18
#define Kdim 1152            // CIN * KK
#define NPIX 32768           // B * HW
#define TILE_N 128           // pixels per fused-GEMM CTA
#define NCH64 18             // Kdim / 64
#define SRH 72               // smem row stride in halves (64 + pad 8)

// fused gemm smem: 2 stages of (A 128x72 + B 128x72) halves + meta
#define GA_H (128 * SRH)             // 9216 halves
#define GB_H (128 * SRH)             // 9216
#define GSTG_H (GA_H + GB_H)         // 18432
#define META_BYTES (KKn * 128 * 32)  // 36864
#define GEMM_SMEM (2 * GSTG_H * 2 + META_BYTES)   // 110592 B

// offset gemm smem: A 32x72, B 64x72 per stage, 2 stages
#define OA_H (32 * SRH)              // 2304
#define OB_H (64 * SRH)              // 4608
#define OSTG_H (OA_H + OB_H)         // 6912
#define OFF_SMEM (2 * OSTG_H * 2)    // 27648 B

// ---------------- static scratch ----------------
__device__ __half g_xh[Bn * HWn * CINc];     // x NHWC fp16 (8.4 MB)
__device__ float  g_off[Bn * OFFC * HWn];    // offset conv out fp32
__device__ __half g_wtp[NCH64 * 8192];       // w_def packed [ch64][co][64k]
__device__ __half g_woffp[NCH64 * 2048];     // w_off packed [ch64][oc32][64k]
__device__ float  g_psum[COUTc * 256];
__device__ float  g_psq [COUTc * 256];
__device__ float  g_scale[COUTc];
__device__ float  g_shift[COUTc];

// ---------------- helpers ----------------
__device__ __forceinline__ void mma_f16(float* d, const uint32_t* a,
                                        uint32_t b0, uint32_t b1) {
    asm volatile(
        "mma.sync.aligned.m16n8k16.row.col.f32.f16.f16.f32 "
        "{%0,%1,%2,%3}, {%4,%5,%6,%7}, {%8,%9}, {%0,%1,%2,%3};"
        : "+f"(d[0]), "+f"(d[1]), "+f"(d[2]), "+f"(d[3])
        : "r"(a[0]), "r"(a[1]), "r"(a[2]), "r"(a[3]), "r"(b0), "r"(b1));
}
__device__ __forceinline__ void ldsm_x4(uint32_t* r, uint32_t addr) {
    asm volatile("ldmatrix.sync.aligned.m8n8.x4.shared.b16 {%0,%1,%2,%3}, [%4];"
                 : "=r"(r[0]), "=r"(r[1]), "=r"(r[2]), "=r"(r[3]) : "r"(addr));
}
__device__ __forceinline__ void ldsm_x2(uint32_t& r0, uint32_t& r1, uint32_t addr) {
    asm volatile("ldmatrix.sync.aligned.m8n8.x2.shared.b16 {%0,%1}, [%2];"
                 : "=r"(r0), "=r"(r1) : "r"(addr));
}
__device__ __forceinline__ uint32_t s2u(const void* p) {
    return (uint32_t)__cvta_generic_to_shared(p);
}
// pure-fp16 bilinear blend (HMUL2/HFMA2, no cvts)
__device__ __forceinline__ uint32_t blend4h(uint32_t a, uint32_t b,
                                            uint32_t c, uint32_t d,
                                            __half2 w0, __half2 w1,
                                            __half2 w2, __half2 w3) {
    __half2 r = __hmul2(*(__half2*)&a, w0);
    r = __hfma2(*(__half2*)&b, w1, r);
    r = __hfma2(*(__half2*)&c, w2, r);
    r = __hfma2(*(__half2*)&d, w3, r);
    return *(uint32_t*)&r;
}

struct __align__(16) MetaF {
    int   i0, i1, i2, i3;
    float w0, w1, w2, w3;
};

// lane offsets for ldmatrix source rows (in BYTES)
#define LANE_OFF_A(lane) ((((lane) & 15) * SRH + (((lane) >> 4) << 3)) * 2)
#define LANE_OFF_B(lane) ((((lane) & 7) * SRH + ((((lane) >> 3) & 1) << 3)) * 2)

// ---------------------------------------------------------------------------
// Kernel 1: merged prep — blocks [0,4096): NCHW->NHWC fp16 transpose,
//           blocks [4096,4816): weight packs
// ---------------------------------------------------------------------------
__global__ __launch_bounds__(256) void k_prep(const float* __restrict__ x,
                                              const float* __restrict__ w_def,
                                              const float* __restrict__ w_off) {
    int bid = blockIdx.x;
    int tid = threadIdx.x;
    if (bid < 4096) {
        __shared__ float tile[32][33];
        int p0 = (bid & 127) * 32;
        int c0 = ((bid >> 7) & 3) * 32;
        int b  = bid >> 9;
        const float* xb = x + (size_t)b * CINc * HWn;
        __half* xtb = g_xh + (size_t)b * HWn * CINc;
        int tx = tid & 31, ty = tid >> 5;
        #pragma unroll
        for (int j = 0; j < 32; j += 8)
            tile[ty + j][tx] = xb[(size_t)(c0 + ty + j) * HWn + p0 + tx];
        __syncthreads();
        #pragma unroll
        for (int m = 0; m < 2; m++) {
            int u = tid + m * 256;
            int pl = u >> 4, cp = u & 15;
            __half2 v = __floats2half2_rn(tile[cp * 2][pl], tile[cp * 2 + 1][pl]);
            *(__half2*)(xtb + (size_t)(p0 + pl) * CINc + c0 + cp * 2) = v;
        }
    } else {
        int idx = (bid - 4096) * 256 + tid;
        if (idx < NCH64 * 8192) {
            int chunk = idx >> 13, r = idx & 8191;
            int co = r >> 6, kloc = r & 63;
            int k = chunk * 64 + kloc;
            int kk = k >> 7, c = k & 127;
            g_wtp[idx] = __float2half(w_def[(size_t)(co * CINc + c) * KKn + kk]);
        } else {
            int j = idx - NCH64 * 8192;
            if (j < NCH64 * 2048) {
                int chunk = j >> 11, r = j & 2047;
                int oc = r >> 6, kloc = r & 63;
                int kk = chunk >> 1, c = (chunk & 1) * 64 + kloc;
                g_woffp[j] = (oc < OFFC)
                    ? __float2half(w_off[(size_t)(oc * CINc + c) * KKn + kk])
                    : __float2half(0.f);
            }
        }
    }
}

// ---------------------------------------------------------------------------
// Kernel 2: offset conv, fp16 implicit GEMM. 512 CTAs (64-pix row tiles),
// 256 thr (8 warps), warp tile 32oc x 8pix, 64-k chunks.
// ---------------------------------------------------------------------------
__global__ __launch_bounds__(256) void k_offset2() {
    extern __shared__ __half smh[];
    const int tid = threadIdx.x;
    const int wid = tid >> 5, lane = tid & 31;
    const int g = lane >> 2, tc = lane & 3;
    const int wn = wid;

    const int tile = blockIdx.x;          // 0..511
    const int b = tile >> 6;
    const int y0 = tile & 63;
    const int hw0 = y0 * 64;
    const __half* xhb = g_xh + (size_t)b * HWn * CINc;

    const uint32_t sbase = s2u(smh);
    const uint32_t laneA = LANE_OFF_A(lane);
    const uint32_t laneB = LANE_OFF_B(lane);

    uint4 bufA;
    uint4 bufB[2];

    float acc[2][4];
    #pragma unroll
    for (int mt = 0; mt < 2; mt++)
        #pragma unroll
        for (int r = 0; r < 4; r++) acc[mt][r] = 0.f;

    auto ldg_chunk = [&](int i) {
        int kk = i >> 1, c0 = (i & 1) * 64;
        int ky = kk / 3 - 1, kx = kk % 3 - 1;
        int ys = y0 + ky;
        bool vy = (unsigned)ys < Hh;
        #pragma unroll
        for (int m = 0; m < 2; m++) {
            int e = tid + m * 256;
            int pix = e >> 3, j = e & 7;
            int xs = pix + kx;
            bool valid = vy && ((unsigned)xs < Ww);
            bufB[m] = valid
                ? *(const uint4*)(xhb + (size_t)(ys * Ww + xs) * CINc + c0 + j * 8)
                : make_uint4(0u, 0u, 0u, 0u);
        }
        bufA = *(const uint4*)(g_woffp + (size_t)i * 2048 + tid * 8);
    };
    auto sts_chunk = [&](int st) {
        __half* As = smh + st * OSTG_H;
        __half* Bs = As + OA_H;
        #pragma unroll
        for (int m = 0; m < 2; m++) {
            int e = tid + m * 256;
            int pix = e >> 3, j = e & 7;
            *(uint4*)(Bs + pix * SRH + j * 8) = bufB[m];
        }
        *(uint4*)(As + (tid >> 3) * SRH + (tid & 7) * 8) = bufA;
    };

    ldg_chunk(0); sts_chunk(0);
    ldg_chunk(1);
    __syncthreads();

    for (int i = 0; i < NCH64; i++) {
        if (i + 1 < NCH64) sts_chunk((i + 1) & 1);
        if (i + 2 < NCH64) ldg_chunk(i + 2);
        const uint32_t aAs = sbase + (uint32_t)((i & 1) * OSTG_H) * 2;
        const uint32_t aBs = aAs + OA_H * 2;
        #pragma unroll
        for (int ks = 0; ks < 4; ks++) {
            uint32_t a[2][4];
            #pragma unroll
            for (int mt = 0; mt < 2; mt++)
                ldsm_x4(a[mt], aAs + (uint32_t)((mt * 16) * SRH + ks * 16) * 2 + laneA);
            uint32_t b0, b1;
            ldsm_x2(b0, b1, aBs + (uint32_t)((wn * 8) * SRH + ks * 16) * 2 + laneB);
            #pragma unroll
            for (int mt = 0; mt < 2; mt++)
                mma_f16(acc[mt], a[mt], b0, b1);
        }
        __syncthreads();
    }

    float* ob = g_off + (size_t)b * OFFC * HWn;
    #pragma unroll
    for (int mt = 0; mt < 2; mt++) {
        int pix = hw0 + wn * 8 + tc * 2;
        int r0 = mt * 16 + g, r1 = r0 + 8;
        if (r0 < OFFC)
            *(float2*)&ob[(size_t)r0 * HWn + pix] = make_float2(acc[mt][0], acc[mt][1]);
        if (r1 < OFFC)
            *(float2*)&ob[(size_t)r1 * HWn + pix] = make_float2(acc[mt][2], acc[mt][3]);
    }
}

// ---------------------------------------------------------------------------
// Kernel 3: FUSED bilinear-gather + fp16 mma GEMM (ldmatrix + half2 blend).
// ---------------------------------------------------------------------------
__global__ __launch_bounds__(512, 1) void k_gemm(float* __restrict__ out) {
    extern __shared__ char smraw[];
    __half* smh  = (__half*)smraw;
    MetaF*  meta = (MetaF*)(smraw + 2 * GSTG_H * 2);

    const int tid = threadIdx.x;
    const int wid = tid >> 5, lane = tid & 31;
    const int wm = wid >> 3, wn = wid & 7;
    const int g = lane >> 2, tc = lane & 3;
    const int tilebase = blockIdx.x * TILE_N;
    const int b = tilebase >> 12, hw0 = tilebase & 4095;
    const int ybase = hw0 >> 6;
    const __half* xhb = g_xh + (size_t)b * HWn * CINc;

    const uint32_t sbase = s2u(smh);
    const uint32_t laneA = LANE_OFF_A(lane);
    const uint32_t laneB = LANE_OFF_B(lane);

    // ---- phase 0: bilinear metadata ----
    const float* offb = g_off + (size_t)b * OFFC * HWn;
    for (int t = tid; t < KKn * 128; t += 512) {
        int kk = t >> 7, p = t & 127;
        int hw = hw0 + p, xx = hw & 63;
        int y = ybase + (p >> 6);
        float dy = offb[(size_t)(kk * 2 + 0) * HWn + hw];
        float dx = offb[(size_t)(kk * 2 + 1) * HWn + hw];
        float ys = (float)(y - 1 + kk / 3) + dy;
        float xs = (float)(xx - 1 + kk % 3) + dx;
        float y0f = floorf(ys), x0f = floorf(xs);
        float wy = ys - y0f, wx = xs - x0f;
        int y0 = (int)y0f, x0 = (int)x0f;
        bool vy0 = (y0 >= 0) && (y0 < Hh);
        bool vy1 = (y0 + 1 >= 0) && (y0 + 1 < Hh);
        bool vx0 = (x0 >= 0) && (x0 < Ww);
        bool vx1 = (x0 + 1 >= 0) && (x0 + 1 < Ww);
        MetaF m;
        m.w0 = (vy0 && vx0) ? (1.f - wy) * (1.f - wx) : 0.f;
        m.w1 = (vy0 && vx1) ? (1.f - wy) * wx : 0.f;
        m.w2 = (vy1 && vx0) ? wy * (1.f - wx) : 0.f;
        m.w3 = (vy1 && vx1) ? wy * wx : 0.f;
        m.i0 = (vy0 && vx0) ? (y0 * Ww + x0) * CINc : 0;
        m.i1 = (vy0 && vx1) ? (y0 * Ww + x0 + 1) * CINc : 0;
        m.i2 = (vy1 && vx0) ? ((y0 + 1) * Ww + x0) * CINc : 0;
        m.i3 = (vy1 && vx1) ? ((y0 + 1) * Ww + x0 + 1) * CINc : 0;
        meta[t] = m;
    }
    __syncthreads();

    float acc[4][2][4];
    #pragma unroll
    for (int mt = 0; mt < 4; mt++)
        #pragma unroll
        for (int nt = 0; nt < 2; nt++)
            #pragma unroll
            for (int r = 0; r < 4; r++) acc[mt][nt][r] = 0.f;

    const int bpix = tid >> 2, bchq = tid & 3;

    uint4 bufA[2];
    uint4 cb[4][2];
    __half2 w0h, w1h, w2h, w3h;

    auto ldg_chunk = [&](int i) {
        #pragma unroll
        for (int m = 0; m < 2; m++) {
            int e = tid + m * 512;
            bufA[m] = *(const uint4*)(g_wtp + (size_t)i * 8192 + e * 8);
        }
        int kk = i >> 1;
        MetaF m = meta[kk * 128 + bpix];
        w0h = __float2half2_rn(m.w0);
        w1h = __float2half2_rn(m.w1);
        w2h = __float2half2_rn(m.w2);
        w3h = __float2half2_rn(m.w3);
        const __half* base = xhb + (i & 1) * 64 + bchq * 16;
        cb[0][0] = *(const uint4*)(base + m.i0);
        cb[0][1] = *(const uint4*)(base + m.i0 + 8);
        cb[1][0] = *(const uint4*)(base + m.i1);
        cb[1][1] = *(const uint4*)(base + m.i1 + 8);
        cb[2][0] = *(const uint4*)(base + m.i2);
        cb[2][1] = *(const uint4*)(base + m.i2 + 8);
        cb[3][0] = *(const uint4*)(base + m.i3);
        cb[3][1] = *(const uint4*)(base + m.i3 + 8);
    };
    auto sts_chunk = [&](int st) {
        __half* As = smh + st * GSTG_H;
        __half* Bs = As + GA_H;
        #pragma unroll
        for (int m = 0; m < 2; m++) {
            int e = tid + m * 512;
            *(uint4*)(As + (e >> 3) * SRH + (e & 7) * 8) = bufA[m];
        }
        uint4 o0, o1;
        o0.x = blend4h(cb[0][0].x, cb[1][0].x, cb[2][0].x, cb[3][0].x, w0h, w1h, w2h, w3h);
        o0.y = blend4h(cb[0][0].y, cb[1][0].y, cb[2][0].y, cb[3][0].y, w0h, w1h, w2h, w3h);
        o0.z = blend4h(cb[0][0].z, cb[1][0].z, cb[2][0].z, cb[3][0].z, w0h, w1h, w2h, w3h);
        o0.w = blend4h(cb[0][0].w, cb[1][0].w, cb[2][0].w, cb[3][0].w, w0h, w1h, w2h, w3h);
        o1.x = blend4h(cb[0][1].x, cb[1][1].x, cb[2][1].x, cb[3][1].x, w0h, w1h, w2h, w3h);
        o1.y = blend4h(cb[0][1].y, cb[1][1].y, cb[2][1].y, cb[3][1].y, w0h, w1h, w2h, w3h);
        o1.z = blend4h(cb[0][1].z, cb[1][1].z, cb[2][1].z, cb[3][1].z, w0h, w1h, w2h, w3h);
        o1.w = blend4h(cb[0][1].w, cb[1][1].w, cb[2][1].w, cb[3][1].w, w0h, w1h, w2h, w3h);
        *(uint4*)(Bs + bpix * SRH + bchq * 16) = o0;
        *(uint4*)(Bs + bpix * SRH + bchq * 16 + 8) = o1;
    };

    ldg_chunk(0); sts_chunk(0);
    ldg_chunk(1);
    __syncthreads();

    for (int i = 0; i < NCH64; i++) {
        if (i + 1 < NCH64) sts_chunk((i + 1) & 1);
        if (i + 2 < NCH64) ldg_chunk(i + 2);

        const uint32_t aAs = sbase + (uint32_t)((i & 1) * GSTG_H) * 2;
        const uint32_t aBs = aAs + GA_H * 2;
        #pragma unroll
        for (int ks = 0; ks < 4; ks++) {
            uint32_t a[4][4];
            #pragma unroll
            for (int mt = 0; mt < 4; mt++)
                ldsm_x4(a[mt], aAs + (uint32_t)((wm * 64 + mt * 16) * SRH + ks * 16) * 2 + laneA);
            #pragma unroll
            for (int nt = 0; nt < 2; nt++) {
                uint32_t b0, b1;
                ldsm_x2(b0, b1, aBs + (uint32_t)((wn * 16 + nt * 8) * SRH + ks * 16) * 2 + laneB);
                #pragma unroll
                for (int mt = 0; mt < 4; mt++)
                    mma_f16(acc[mt][nt], a[mt], b0, b1);
            }
        }
        __syncthreads();
    }

    // ---- store results ----
    #pragma unroll
    for (int mt = 0; mt < 4; mt++) {
        #pragma unroll
        for (int nt = 0; nt < 2; nt++) {
            int pix = hw0 + wn * 16 + nt * 8 + tc * 2;
            int co0 = wm * 64 + mt * 16 + g;
            *(float2*)&out[((size_t)b * COUTc + co0) * HWn + pix] =
                make_float2(acc[mt][nt][0], acc[mt][nt][1]);
            *(float2*)&out[((size_t)b * COUTc + co0 + 8) * HWn + pix] =
                make_float2(acc[mt][nt][2], acc[mt][nt][3]);
        }
    }

    // ---- deterministic BN partials ----
    float s[8], q[8];
    #pragma unroll
    for (int i = 0; i < 8; i++) { s[i] = 0.f; q[i] = 0.f; }
    #pragma unroll
    for (int mt = 0; mt < 4; mt++)
        #pragma unroll
        for (int r = 0; r < 2; r++) {
            int sl = mt * 2 + r;
            #pragma unroll
            for (int nt = 0; nt < 2; nt++) {
                float v0 = acc[mt][nt][r * 2], v1 = acc[mt][nt][r * 2 + 1];
                s[sl] += v0 + v1;
                q[sl] += v0 * v0 + v1 * v1;
            }
        }
    #pragma unroll
    for (int m = 1; m <= 2; m <<= 1)
        #pragma unroll
        for (int i = 0; i < 8; i++) {
            s[i] += __shfl_xor_sync(0xFFFFFFFF, s[i], m);
            q[i] += __shfl_xor_sync(0xFFFFFFFF, q[i], m);
        }

    __syncthreads();
    float* sb = (float*)smraw;
    float* qb = sb + 1024;
    if (tc == 0) {
        #pragma unroll
        for (int mt = 0; mt < 4; mt++)
            #pragma unroll
            for (int r = 0; r < 2; r++) {
                int cl = mt * 16 + r * 8 + g;
                sb[wid * 64 + cl] = s[mt * 2 + r];
                qb[wid * 64 + cl] = q[mt * 2 + r];
            }
    }
    __syncthreads();
    if (tid < COUTc) {
        int co = tid;
        float ss = 0.f, qq = 0.f;
        #pragma unroll
        for (int w = 0; w < 8; w++) {
            ss += sb[((co >> 6) * 8 + w) * 64 + (co & 63)];
            qq += qb[((co >> 6) * 8 + w) * 64 + (co & 63)];
        }
        g_psum[co * 256 + blockIdx.x] = ss;
        g_psq [co * 256 + blockIdx.x] = qq;
    }
}

// ---------------------------------------------------------------------------
// Kernel 4: finalize BN stats
// ---------------------------------------------------------------------------
__global__ void k_statsfin(const float* __restrict__ gamma, const float* __restrict__ beta) {
    int co = threadIdx.x;
    float s = 0.f, q = 0.f;
    const float4* ps = (const float4*)(g_psum + co * 256);
    const float4* pq = (const float4*)(g_psq  + co * 256);
    #pragma unroll 8
    for (int j = 0; j < 64; j++) {
        float4 a = ps[j], c = pq[j];
        s += (a.x + a.y) + (a.z + a.w);
        q += (c.x + c.y) + (c.z + c.w);
    }
    const float inv_n = 1.f / (float)NPIX;
    float mean = s * inv_n;
    float var  = q * inv_n - mean * mean;
    float sc   = gamma[co] * rsqrtf(var + 1e-5f);
    g_scale[co] = sc;
    g_shift[co] = beta[co] - mean * sc;
}

// ---------------------------------------------------------------------------
// Kernel 5: normalize + SiLU (in place, 2 float4 per thread)
// ---------------------------------------------------------------------------
__global__ __launch_bounds__(256) void k_norm(float* __restrict__ out) {
    const int n4 = Bn * COUTc * HWn / 4;   // 1048576
    int idx = blockIdx.x * 256 + threadIdx.x;
    float4* o4 = (float4*)out;
    #pragma unroll
    for (int m = 0; m < 2; m++) {
        int i2 = idx + m * (n4 / 2);
        int co = (i2 >> 10) & 127;
        float sc = g_scale[co], sh = g_shift[co];
        float4 v = o4[i2];
        float u;
        u = v.x * sc + sh; v.x = u / (1.f + __expf(-u));
        u = v.y * sc + sh; v.y = u / (1.f + __expf(-u));
        u = v.z * sc + sh; v.z = u / (1.f + __expf(-u));
        u = v.w * sc + sh; v.w = u / (1.f + __expf(-u));
        o4[i2] = v;
    }
}

// ---------------------------------------------------------------------------
extern "C" void kernel_launch(void* const* d_in, const int* in_sizes, int n_in,
                              void* d_out, int out_size) {
    const float* x     = (const float*)d_in[0];
    const float* w_off = (const float*)d_in[1];
    const float* w_def = (const float*)d_in[2];
    // d_in[3] = b_def: exactly absorbed by batch-norm mean subtraction
    const float* gamma = (const float*)d_in[4];
    const float* beta  = (const float*)d_in[5];
    float* out = (float*)d_out;

    cudaFuncSetAttribute(k_gemm, cudaFuncAttributeMaxDynamicSharedMemorySize, GEMM_SMEM);
    cudaFuncSetAttribute(k_offset2, cudaFuncAttributeMaxDynamicSharedMemorySize, OFF_SMEM);

    k_prep<<<4096 + (NCH64 * 10240 + 255) / 256, 256>>>(x, w_def, w_off);

    k_offset2<<<512, 256, OFF_SMEM>>>();

    k_gemm<<<NPIX / TILE_N, 512, GEMM_SMEM>>>(out);

    k_statsfin<<<1, 128>>>(gamma, beta);

    k_norm<<<(Bn * COUTc * HWn / 4) / 512, 256>>>(out);
}

// round 10
// speedup vs baseline: 6.3964x; 1.0870x over previous
#include <cuda_runtime.h>
#include <cuda_fp16.h>
#include <math.h>
#include <stdint.h>

#define Bn 8
#define CINc 128
#define COUTc 128
#define Hh 64
#define Ww 64
#define HWn 4096
#define KKn 9
#define OFFC 18
#define Kdim 1152            // CIN * KK
#define NPIX 32768           // B * HW
#define TILE_N 128           // pixels per fused-GEMM CTA
#define NCH64 18             // Kdim / 64
#define SRH 72               // smem row stride in halves (64 + pad 8)

// fused gemm smem: 2 stages of (A 128x72 + B 128x72) halves + meta
#define GA_H (128 * SRH)             // 9216 halves
#define GB_H (128 * SRH)             // 9216
#define GSTG_H (GA_H + GB_H)         // 18432
#define META_BYTES (KKn * 128 * 32)  // 36864
#define GEMM_SMEM (2 * GSTG_H * 2 + META_BYTES)   // 110592 B

// offset gemm smem: A 32x72, B 64x72 per stage, 2 stages
#define OA_H (32 * SRH)              // 2304
#define OB_H (64 * SRH)              // 4608
#define OSTG_H (OA_H + OB_H)         // 6912
#define OFF_SMEM (2 * OSTG_H * 2)    // 27648 B

// ---------------- static scratch ----------------
__device__ __half g_xh[Bn * HWn * CINc];     // x NHWC fp16 (8.4 MB)
__device__ float  g_off[Bn * OFFC * HWn];    // offset conv out fp32
__device__ __half g_wtp[NCH64 * 8192];       // w_def packed [ch64][co][64k]
__device__ __half g_woffp[NCH64 * 2048];     // w_off packed [ch64][oc32][64k]
__device__ float  g_psum[COUTc * 256];
__device__ float  g_psq [COUTc * 256];
__device__ float  g_scale[COUTc];
__device__ float  g_shift[COUTc];

// ---------------- helpers ----------------
__device__ __forceinline__ void mma_f16(float* d, const uint32_t* a,
                                        uint32_t b0, uint32_t b1) {
    asm volatile(
        "mma.sync.aligned.m16n8k16.row.col.f32.f16.f16.f32 "
        "{%0,%1,%2,%3}, {%4,%5,%6,%7}, {%8,%9}, {%0,%1,%2,%3};"
        : "+f"(d[0]), "+f"(d[1]), "+f"(d[2]), "+f"(d[3])
        : "r"(a[0]), "r"(a[1]), "r"(a[2]), "r"(a[3]), "r"(b0), "r"(b1));
}
__device__ __forceinline__ void ldsm_x4(uint32_t* r, uint32_t addr) {
    asm volatile("ldmatrix.sync.aligned.m8n8.x4.shared.b16 {%0,%1,%2,%3}, [%4];"
                 : "=r"(r[0]), "=r"(r[1]), "=r"(r[2]), "=r"(r[3]) : "r"(addr));
}
__device__ __forceinline__ void ldsm_x2(uint32_t& r0, uint32_t& r1, uint32_t addr) {
    asm volatile("ldmatrix.sync.aligned.m8n8.x2.shared.b16 {%0,%1}, [%2];"
                 : "=r"(r0), "=r"(r1) : "r"(addr));
}
__device__ __forceinline__ uint32_t s2u(const void* p) {
    return (uint32_t)__cvta_generic_to_shared(p);
}
// pure-fp16 bilinear blend (HMUL2/HFMA2, no cvts)
__device__ __forceinline__ uint32_t blend4h(uint32_t a, uint32_t b,
                                            uint32_t c, uint32_t d,
                                            __half2 w0, __half2 w1,
                                            __half2 w2, __half2 w3) {
    __half2 r = __hmul2(*(__half2*)&a, w0);
    r = __hfma2(*(__half2*)&b, w1, r);
    r = __hfma2(*(__half2*)&c, w2, r);
    r = __hfma2(*(__half2*)&d, w3, r);
    return *(uint32_t*)&r;
}

struct __align__(16) MetaF {
    int   i0, i1, i2, i3;
    float w0, w1, w2, w3;
};

// lane offsets for ldmatrix source rows (in BYTES)
#define LANE_OFF_A(lane) ((((lane) & 15) * SRH + (((lane) >> 4) << 3)) * 2)
#define LANE_OFF_B(lane) ((((lane) & 7) * SRH + ((((lane) >> 3) & 1) << 3)) * 2)

// ---------------------------------------------------------------------------
// Kernel 1: merged prep — blocks [0,4096): NCHW->NHWC fp16 transpose,
//           blocks [4096,4816): weight packs
// ---------------------------------------------------------------------------
__global__ __launch_bounds__(256) void k_prep(const float* __restrict__ x,
                                              const float* __restrict__ w_def,
                                              const float* __restrict__ w_off) {
    int bid = blockIdx.x;
    int tid = threadIdx.x;
    if (bid < 4096) {
        __shared__ float tile[32][33];
        int p0 = (bid & 127) * 32;
        int c0 = ((bid >> 7) & 3) * 32;
        int b  = bid >> 9;
        const float* xb = x + (size_t)b * CINc * HWn;
        __half* xtb = g_xh + (size_t)b * HWn * CINc;
        int tx = tid & 31, ty = tid >> 5;
        #pragma unroll
        for (int j = 0; j < 32; j += 8)
            tile[ty + j][tx] = xb[(size_t)(c0 + ty + j) * HWn + p0 + tx];
        __syncthreads();
        #pragma unroll
        for (int m = 0; m < 2; m++) {
            int u = tid + m * 256;
            int pl = u >> 4, cp = u & 15;
            __half2 v = __floats2half2_rn(tile[cp * 2][pl], tile[cp * 2 + 1][pl]);
            *(__half2*)(xtb + (size_t)(p0 + pl) * CINc + c0 + cp * 2) = v;
        }
    } else {
        int idx = (bid - 4096) * 256 + tid;
        if (idx < NCH64 * 8192) {
            int chunk = idx >> 13, r = idx & 8191;
            int co = r >> 6, kloc = r & 63;
            int k = chunk * 64 + kloc;
            int kk = k >> 7, c = k & 127;
            g_wtp[idx] = __float2half(w_def[(size_t)(co * CINc + c) * KKn + kk]);
        } else {
            int j = idx - NCH64 * 8192;
            if (j < NCH64 * 2048) {
                int chunk = j >> 11, r = j & 2047;
                int oc = r >> 6, kloc = r & 63;
                int kk = chunk >> 1, c = (chunk & 1) * 64 + kloc;
                g_woffp[j] = (oc < OFFC)
                    ? __float2half(w_off[(size_t)(oc * CINc + c) * KKn + kk])
                    : __float2half(0.f);
            }
        }
    }
}

// ---------------------------------------------------------------------------
// Kernel 2: offset conv, fp16 implicit GEMM. 512 CTAs (64-pix row tiles),
// 256 thr (8 warps), warp tile 32oc x 8pix, 64-k chunks.
// ---------------------------------------------------------------------------
__global__ __launch_bounds__(256) void k_offset2() {
    extern __shared__ __half smh[];
    const int tid = threadIdx.x;
    const int wid = tid >> 5, lane = tid & 31;
    const int g = lane >> 2, tc = lane & 3;
    const int wn = wid;

    const int tile = blockIdx.x;          // 0..511
    const int b = tile >> 6;
    const int y0 = tile & 63;
    const int hw0 = y0 * 64;
    const __half* xhb = g_xh + (size_t)b * HWn * CINc;

    const uint32_t sbase = s2u(smh);
    const uint32_t laneA = LANE_OFF_A(lane);
    const uint32_t laneB = LANE_OFF_B(lane);

    uint4 bufA;
    uint4 bufB[2];

    float acc[2][4];
    #pragma unroll
    for (int mt = 0; mt < 2; mt++)
        #pragma unroll
        for (int r = 0; r < 4; r++) acc[mt][r] = 0.f;

    auto ldg_chunk = [&](int i) {
        int kk = i >> 1, c0 = (i & 1) * 64;
        int ky = kk / 3 - 1, kx = kk % 3 - 1;
        int ys = y0 + ky;
        bool vy = (unsigned)ys < Hh;
        #pragma unroll
        for (int m = 0; m < 2; m++) {
            int e = tid + m * 256;
            int pix = e >> 3, j = e & 7;
            int xs = pix + kx;
            bool valid = vy && ((unsigned)xs < Ww);
            bufB[m] = valid
                ? *(const uint4*)(xhb + (size_t)(ys * Ww + xs) * CINc + c0 + j * 8)
                : make_uint4(0u, 0u, 0u, 0u);
        }
        bufA = *(const uint4*)(g_woffp + (size_t)i * 2048 + tid * 8);
    };
    auto sts_chunk = [&](int st) {
        __half* As = smh + st * OSTG_H;
        __half* Bs = As + OA_H;
        #pragma unroll
        for (int m = 0; m < 2; m++) {
            int e = tid + m * 256;
            int pix = e >> 3, j = e & 7;
            *(uint4*)(Bs + pix * SRH + j * 8) = bufB[m];
        }
        *(uint4*)(As + (tid >> 3) * SRH + (tid & 7) * 8) = bufA;
    };

    ldg_chunk(0); sts_chunk(0);
    ldg_chunk(1);
    __syncthreads();

    for (int i = 0; i < NCH64; i++) {
        if (i + 1 < NCH64) sts_chunk((i + 1) & 1);
        if (i + 2 < NCH64) ldg_chunk(i + 2);
        const uint32_t aAs = sbase + (uint32_t)((i & 1) * OSTG_H) * 2;
        const uint32_t aBs = aAs + OA_H * 2;
        #pragma unroll
        for (int ks = 0; ks < 4; ks++) {
            uint32_t a[2][4];
            #pragma unroll
            for (int mt = 0; mt < 2; mt++)
                ldsm_x4(a[mt], aAs + (uint32_t)((mt * 16) * SRH + ks * 16) * 2 + laneA);
            uint32_t b0, b1;
            ldsm_x2(b0, b1, aBs + (uint32_t)((wn * 8) * SRH + ks * 16) * 2 + laneB);
            #pragma unroll
            for (int mt = 0; mt < 2; mt++)
                mma_f16(acc[mt], a[mt], b0, b1);
        }
        __syncthreads();
    }

    float* ob = g_off + (size_t)b * OFFC * HWn;
    #pragma unroll
    for (int mt = 0; mt < 2; mt++) {
        int pix = hw0 + wn * 8 + tc * 2;
        int r0 = mt * 16 + g, r1 = r0 + 8;
        if (r0 < OFFC)
            *(float2*)&ob[(size_t)r0 * HWn + pix] = make_float2(acc[mt][0], acc[mt][1]);
        if (r1 < OFFC)
            *(float2*)&ob[(size_t)r1 * HWn + pix] = make_float2(acc[mt][2], acc[mt][3]);
    }
}

// ---------------------------------------------------------------------------
// Kernel 3: FUSED bilinear-gather + fp16 mma GEMM (ldmatrix + half2 blend).
// ---------------------------------------------------------------------------
__global__ __launch_bounds__(512, 1) void k_gemm(float* __restrict__ out) {
    extern __shared__ char smraw[];
    __half* smh  = (__half*)smraw;
    MetaF*  meta = (MetaF*)(smraw + 2 * GSTG_H * 2);

    const int tid = threadIdx.x;
    const int wid = tid >> 5, lane = tid & 31;
    const int wm = wid >> 3, wn = wid & 7;
    const int g = lane >> 2, tc = lane & 3;
    const int tilebase = blockIdx.x * TILE_N;
    const int b = tilebase >> 12, hw0 = tilebase & 4095;
    const int ybase = hw0 >> 6;
    const __half* xhb = g_xh + (size_t)b * HWn * CINc;

    const uint32_t sbase = s2u(smh);
    const uint32_t laneA = LANE_OFF_A(lane);
    const uint32_t laneB = LANE_OFF_B(lane);

    // ---- phase 0: bilinear metadata ----
    const float* offb = g_off + (size_t)b * OFFC * HWn;
    for (int t = tid; t < KKn * 128; t += 512) {
        int kk = t >> 7, p = t & 127;
        int hw = hw0 + p, xx = hw & 63;
        int y = ybase + (p >> 6);
        float dy = offb[(size_t)(kk * 2 + 0) * HWn + hw];
        float dx = offb[(size_t)(kk * 2 + 1) * HWn + hw];
        float ys = (float)(y - 1 + kk / 3) + dy;
        float xs = (float)(xx - 1 + kk % 3) + dx;
        float y0f = floorf(ys), x0f = floorf(xs);
        float wy = ys - y0f, wx = xs - x0f;
        int y0 = (int)y0f, x0 = (int)x0f;
        bool vy0 = (y0 >= 0) && (y0 < Hh);
        bool vy1 = (y0 + 1 >= 0) && (y0 + 1 < Hh);
        bool vx0 = (x0 >= 0) && (x0 < Ww);
        bool vx1 = (x0 + 1 >= 0) && (x0 + 1 < Ww);
        MetaF m;
        m.w0 = (vy0 && vx0) ? (1.f - wy) * (1.f - wx) : 0.f;
        m.w1 = (vy0 && vx1) ? (1.f - wy) * wx : 0.f;
        m.w2 = (vy1 && vx0) ? wy * (1.f - wx) : 0.f;
        m.w3 = (vy1 && vx1) ? wy * wx : 0.f;
        m.i0 = (vy0 && vx0) ? (y0 * Ww + x0) * CINc : 0;
        m.i1 = (vy0 && vx1) ? (y0 * Ww + x0 + 1) * CINc : 0;
        m.i2 = (vy1 && vx0) ? ((y0 + 1) * Ww + x0) * CINc : 0;
        m.i3 = (vy1 && vx1) ? ((y0 + 1) * Ww + x0 + 1) * CINc : 0;
        meta[t] = m;
    }
    __syncthreads();

    float acc[4][2][4];
    #pragma unroll
    for (int mt = 0; mt < 4; mt++)
        #pragma unroll
        for (int nt = 0; nt < 2; nt++)
            #pragma unroll
            for (int r = 0; r < 4; r++) acc[mt][nt][r] = 0.f;

    const int bpix = tid >> 2, bchq = tid & 3;

    uint4 bufA[2];
    uint4 cb[4][2];
    __half2 w0h, w1h, w2h, w3h;

    auto ldg_chunk = [&](int i) {
        #pragma unroll
        for (int m = 0; m < 2; m++) {
            int e = tid + m * 512;
            bufA[m] = *(const uint4*)(g_wtp + (size_t)i * 8192 + e * 8);
        }
        int kk = i >> 1;
        MetaF m = meta[kk * 128 + bpix];
        w0h = __float2half2_rn(m.w0);
        w1h = __float2half2_rn(m.w1);
        w2h = __float2half2_rn(m.w2);
        w3h = __float2half2_rn(m.w3);
        const __half* base = xhb + (i & 1) * 64 + bchq * 16;
        cb[0][0] = *(const uint4*)(base + m.i0);
        cb[0][1] = *(const uint4*)(base + m.i0 + 8);
        cb[1][0] = *(const uint4*)(base + m.i1);
        cb[1][1] = *(const uint4*)(base + m.i1 + 8);
        cb[2][0] = *(const uint4*)(base + m.i2);
        cb[2][1] = *(const uint4*)(base + m.i2 + 8);
        cb[3][0] = *(const uint4*)(base + m.i3);
        cb[3][1] = *(const uint4*)(base + m.i3 + 8);
    };
    auto sts_chunk = [&](int st) {
        __half* As = smh + st * GSTG_H;
        __half* Bs = As + GA_H;
        #pragma unroll
        for (int m = 0; m < 2; m++) {
            int e = tid + m * 512;
            *(uint4*)(As + (e >> 3) * SRH + (e & 7) * 8) = bufA[m];
        }
        uint4 o0, o1;
        o0.x = blend4h(cb[0][0].x, cb[1][0].x, cb[2][0].x, cb[3][0].x, w0h, w1h, w2h, w3h);
        o0.y = blend4h(cb[0][0].y, cb[1][0].y, cb[2][0].y, cb[3][0].y, w0h, w1h, w2h, w3h);
        o0.z = blend4h(cb[0][0].z, cb[1][0].z, cb[2][0].z, cb[3][0].z, w0h, w1h, w2h, w3h);
        o0.w = blend4h(cb[0][0].w, cb[1][0].w, cb[2][0].w, cb[3][0].w, w0h, w1h, w2h, w3h);
        o1.x = blend4h(cb[0][1].x, cb[1][1].x, cb[2][1].x, cb[3][1].x, w0h, w1h, w2h, w3h);
        o1.y = blend4h(cb[0][1].y, cb[1][1].y, cb[2][1].y, cb[3][1].y, w0h, w1h, w2h, w3h);
        o1.z = blend4h(cb[0][1].z, cb[1][1].z, cb[2][1].z, cb[3][1].z, w0h, w1h, w2h, w3h);
        o1.w = blend4h(cb[0][1].w, cb[1][1].w, cb[2][1].w, cb[3][1].w, w0h, w1h, w2h, w3h);
        *(uint4*)(Bs + bpix * SRH + bchq * 16) = o0;
        *(uint4*)(Bs + bpix * SRH + bchq * 16 + 8) = o1;
    };

    ldg_chunk(0); sts_chunk(0);
    ldg_chunk(1);
    __syncthreads();

    for (int i = 0; i < NCH64; i++) {
        if (i + 1 < NCH64) sts_chunk((i + 1) & 1);
        if (i + 2 < NCH64) ldg_chunk(i + 2);

        const uint32_t aAs = sbase + (uint32_t)((i & 1) * GSTG_H) * 2;
        const uint32_t aBs = aAs + GA_H * 2;
        #pragma unroll
        for (int ks = 0; ks < 4; ks++) {
            uint32_t a[4][4];
            #pragma unroll
            for (int mt = 0; mt < 4; mt++)
                ldsm_x4(a[mt], aAs + (uint32_t)((wm * 64 + mt * 16) * SRH + ks * 16) * 2 + laneA);
            #pragma unroll
            for (int nt = 0; nt < 2; nt++) {
                uint32_t b0, b1;
                ldsm_x2(b0, b1, aBs + (uint32_t)((wn * 16 + nt * 8) * SRH + ks * 16) * 2 + laneB);
                #pragma unroll
                for (int mt = 0; mt < 4; mt++)
                    mma_f16(acc[mt][nt], a[mt], b0, b1);
            }
        }
        __syncthreads();
    }

    // ---- store results ----
    #pragma unroll
    for (int mt = 0; mt < 4; mt++) {
        #pragma unroll
        for (int nt = 0; nt < 2; nt++) {
            int pix = hw0 + wn * 16 + nt * 8 + tc * 2;
            int co0 = wm * 64 + mt * 16 + g;
            *(float2*)&out[((size_t)b * COUTc + co0) * HWn + pix] =
                make_float2(acc[mt][nt][0], acc[mt][nt][1]);
            *(float2*)&out[((size_t)b * COUTc + co0 + 8) * HWn + pix] =
                make_float2(acc[mt][nt][2], acc[mt][nt][3]);
        }
    }

    // ---- deterministic BN partials ----
    float s[8], q[8];
    #pragma unroll
    for (int i = 0; i < 8; i++) { s[i] = 0.f; q[i] = 0.f; }
    #pragma unroll
    for (int mt = 0; mt < 4; mt++)
        #pragma unroll
        for (int r = 0; r < 2; r++) {
            int sl = mt * 2 + r;
            #pragma unroll
            for (int nt = 0; nt < 2; nt++) {
                float v0 = acc[mt][nt][r * 2], v1 = acc[mt][nt][r * 2 + 1];
                s[sl] += v0 + v1;
                q[sl] += v0 * v0 + v1 * v1;
            }
        }
    #pragma unroll
    for (int m = 1; m <= 2; m <<= 1)
        #pragma unroll
        for (int i = 0; i < 8; i++) {
            s[i] += __shfl_xor_sync(0xFFFFFFFF, s[i], m);
            q[i] += __shfl_xor_sync(0xFFFFFFFF, q[i], m);
        }

    __syncthreads();
    float* sb = (float*)smraw;
    float* qb = sb + 1024;
    if (tc == 0) {
        #pragma unroll
        for (int mt = 0; mt < 4; mt++)
            #pragma unroll
            for (int r = 0; r < 2; r++) {
                int cl = mt * 16 + r * 8 + g;
                sb[wid * 64 + cl] = s[mt * 2 + r];
                qb[wid * 64 + cl] = q[mt * 2 + r];
            }
    }
    __syncthreads();
    if (tid < COUTc) {
        int co = tid;
        float ss = 0.f, qq = 0.f;
        #pragma unroll
        for (int w = 0; w < 8; w++) {
            ss += sb[((co >> 6) * 8 + w) * 64 + (co & 63)];
            qq += qb[((co >> 6) * 8 + w) * 64 + (co & 63)];
        }
        g_psum[co * 256 + blockIdx.x] = ss;
        g_psq [co * 256 + blockIdx.x] = qq;
    }
}

// ---------------------------------------------------------------------------
// Kernel 4: finalize BN stats — one CTA per channel, parallel reduce.
// ---------------------------------------------------------------------------
__global__ __launch_bounds__(256) void k_statsfin(const float* __restrict__ gamma,
                                                  const float* __restrict__ beta) {
    __shared__ float rs[8], rq[8];
    const int co = blockIdx.x;
    const int tid = threadIdx.x;
    float s = g_psum[co * 256 + tid];
    float q = g_psq [co * 256 + tid];
    #pragma unroll
    for (int m = 16; m > 0; m >>= 1) {
        s += __shfl_xor_sync(0xFFFFFFFF, s, m);
        q += __shfl_xor_sync(0xFFFFFFFF, q, m);
    }
    if ((tid & 31) == 0) { rs[tid >> 5] = s; rq[tid >> 5] = q; }
    __syncthreads();
    if (tid == 0) {
        float ss = 0.f, qq = 0.f;
        #pragma unroll
        for (int w = 0; w < 8; w++) { ss += rs[w]; qq += rq[w]; }
        const float inv_n = 1.f / (float)NPIX;
        float mean = ss * inv_n;
        float var  = qq * inv_n - mean * mean;
        float sc   = gamma[co] * rsqrtf(var + 1e-5f);
        g_scale[co] = sc;
        g_shift[co] = beta[co] - mean * sc;
    }
}

// ---------------------------------------------------------------------------
// Kernel 5: normalize + SiLU (in place, 2 float4 per thread)
// ---------------------------------------------------------------------------
__global__ __launch_bounds__(256) void k_norm(float* __restrict__ out) {
    const int n4 = Bn * COUTc * HWn / 4;   // 1048576
    int idx = blockIdx.x * 256 + threadIdx.x;
    float4* o4 = (float4*)out;
    #pragma unroll
    for (int m = 0; m < 2; m++) {
        int i2 = idx + m * (n4 / 2);
        int co = (i2 >> 10) & 127;
        float sc = g_scale[co], sh = g_shift[co];
        float4 v = o4[i2];
        float u;
        u = v.x * sc + sh; v.x = u / (1.f + __expf(-u));
        u = v.y * sc + sh; v.y = u / (1.f + __expf(-u));
        u = v.z * sc + sh; v.z = u / (1.f + __expf(-u));
        u = v.w * sc + sh; v.w = u / (1.f + __expf(-u));
        o4[i2] = v;
    }
}

// ---------------------------------------------------------------------------
extern "C" void kernel_launch(void* const* d_in, const int* in_sizes, int n_in,
                              void* d_out, int out_size) {
    const float* x     = (const float*)d_in[0];
    const float* w_off = (const float*)d_in[1];
    const float* w_def = (const float*)d_in[2];
    // d_in[3] = b_def: exactly absorbed by batch-norm mean subtraction
    const float* gamma = (const float*)d_in[4];
    const float* beta  = (const float*)d_in[5];
    float* out = (float*)d_out;

    cudaFuncSetAttribute(k_gemm, cudaFuncAttributeMaxDynamicSharedMemorySize, GEMM_SMEM);
    cudaFuncSetAttribute(k_offset2, cudaFuncAttributeMaxDynamicSharedMemorySize, OFF_SMEM);

    k_prep<<<4096 + (NCH64 * 10240 + 255) / 256, 256>>>(x, w_def, w_off);

    k_offset2<<<512, 256, OFF_SMEM>>>();

    k_gemm<<<NPIX / TILE_N, 512, GEMM_SMEM>>>(out);

    k_statsfin<<<COUTc, 256>>>(gamma, beta);

    k_norm<<<(Bn * COUTc * HWn / 4) / 512, 256>>>(out);
}

// round 11
// speedup vs baseline: 6.6014x; 1.0321x over previous
#include <cuda_runtime.h>
#include <cuda_fp16.h>
#include <math.h>
#include <stdint.h>

#define Bn 8
#define CINc 128
#define COUTc 128
#define Hh 64
#define Ww 64
#define HWn 4096
#define KKn 9
#define OFFC 18
#define Kdim 1152            // CIN * KK
#define NPIX 32768           // B * HW
#define TILE_N 128           // pixels per fused-GEMM CTA
#define NCH64 18             // Kdim / 64
#define SRH 72               // smem row stride in halves (64 + pad 8)

// fused gemm smem: 2 stages of (A 128x72 + B 128x72) halves + meta
#define GA_H (128 * SRH)             // 9216 halves
#define GB_H (128 * SRH)             // 9216
#define GSTG_H (GA_H + GB_H)         // 18432
#define META_BYTES (KKn * 128 * 32)  // 36864
#define GEMM_SMEM (2 * GSTG_H * 2 + META_BYTES)   // 110592 B

// offset gemm smem: A 32x72, B 64x72 per stage, 2 stages
#define OA_H (32 * SRH)              // 2304
#define OB_H (64 * SRH)              // 4608
#define OSTG_H (OA_H + OB_H)         // 6912
#define OFF_SMEM (2 * OSTG_H * 2)    // 27648 B

// ---------------- static scratch ----------------
__device__ __half g_xh[Bn * HWn * CINc];     // x NHWC fp16 (8.4 MB)
__device__ float  g_off[Bn * OFFC * HWn];    // offset conv out fp32
__device__ __half g_wtp[NCH64 * 8192];       // w_def packed [ch64][co][64k]
__device__ __half g_woffp[NCH64 * 2048];     // w_off packed [ch64][oc32][64k]
__device__ float  g_psum[COUTc * 256];
__device__ float  g_psq [COUTc * 256];

// ---------------- helpers ----------------
__device__ __forceinline__ void mma_f16(float* d, const uint32_t* a,
                                        uint32_t b0, uint32_t b1) {
    asm volatile(
        "mma.sync.aligned.m16n8k16.row.col.f32.f16.f16.f32 "
        "{%0,%1,%2,%3}, {%4,%5,%6,%7}, {%8,%9}, {%0,%1,%2,%3};"
        : "+f"(d[0]), "+f"(d[1]), "+f"(d[2]), "+f"(d[3])
        : "r"(a[0]), "r"(a[1]), "r"(a[2]), "r"(a[3]), "r"(b0), "r"(b1));
}
__device__ __forceinline__ void ldsm_x4(uint32_t* r, uint32_t addr) {
    asm volatile("ldmatrix.sync.aligned.m8n8.x4.shared.b16 {%0,%1,%2,%3}, [%4];"
                 : "=r"(r[0]), "=r"(r[1]), "=r"(r[2]), "=r"(r[3]) : "r"(addr));
}
__device__ __forceinline__ void ldsm_x2(uint32_t& r0, uint32_t& r1, uint32_t addr) {
    asm volatile("ldmatrix.sync.aligned.m8n8.x2.shared.b16 {%0,%1}, [%2];"
                 : "=r"(r0), "=r"(r1) : "r"(addr));
}
__device__ __forceinline__ uint32_t s2u(const void* p) {
    return (uint32_t)__cvta_generic_to_shared(p);
}
// pure-fp16 bilinear blend (HMUL2/HFMA2, no cvts)
__device__ __forceinline__ uint32_t blend4h(uint32_t a, uint32_t b,
                                            uint32_t c, uint32_t d,
                                            __half2 w0, __half2 w1,
                                            __half2 w2, __half2 w3) {
    __half2 r = __hmul2(*(__half2*)&a, w0);
    r = __hfma2(*(__half2*)&b, w1, r);
    r = __hfma2(*(__half2*)&c, w2, r);
    r = __hfma2(*(__half2*)&d, w3, r);
    return *(uint32_t*)&r;
}

struct __align__(16) MetaF {
    int   i0, i1, i2, i3;
    float w0, w1, w2, w3;
};

// lane offsets for ldmatrix source rows (in BYTES)
#define LANE_OFF_A(lane) ((((lane) & 15) * SRH + (((lane) >> 4) << 3)) * 2)
#define LANE_OFF_B(lane) ((((lane) & 7) * SRH + ((((lane) >> 3) & 1) << 3)) * 2)

// ---------------------------------------------------------------------------
// Kernel 1: merged prep — blocks [0,4096): NCHW->NHWC fp16 transpose,
//           blocks [4096,4816): weight packs
// ---------------------------------------------------------------------------
__global__ __launch_bounds__(256) void k_prep(const float* __restrict__ x,
                                              const float* __restrict__ w_def,
                                              const float* __restrict__ w_off) {
    int bid = blockIdx.x;
    int tid = threadIdx.x;
    if (bid < 4096) {
        __shared__ float tile[32][33];
        int p0 = (bid & 127) * 32;
        int c0 = ((bid >> 7) & 3) * 32;
        int b  = bid >> 9;
        const float* xb = x + (size_t)b * CINc * HWn;
        __half* xtb = g_xh + (size_t)b * HWn * CINc;
        int tx = tid & 31, ty = tid >> 5;
        #pragma unroll
        for (int j = 0; j < 32; j += 8)
            tile[ty + j][tx] = xb[(size_t)(c0 + ty + j) * HWn + p0 + tx];
        __syncthreads();
        #pragma unroll
        for (int m = 0; m < 2; m++) {
            int u = tid + m * 256;
            int pl = u >> 4, cp = u & 15;
            __half2 v = __floats2half2_rn(tile[cp * 2][pl], tile[cp * 2 + 1][pl]);
            *(__half2*)(xtb + (size_t)(p0 + pl) * CINc + c0 + cp * 2) = v;
        }
    } else {
        int idx = (bid - 4096) * 256 + tid;
        if (idx < NCH64 * 8192) {
            int chunk = idx >> 13, r = idx & 8191;
            int co = r >> 6, kloc = r & 63;
            int k = chunk * 64 + kloc;
            int kk = k >> 7, c = k & 127;
            g_wtp[idx] = __float2half(w_def[(size_t)(co * CINc + c) * KKn + kk]);
        } else {
            int j = idx - NCH64 * 8192;
            if (j < NCH64 * 2048) {
                int chunk = j >> 11, r = j & 2047;
                int oc = r >> 6, kloc = r & 63;
                int kk = chunk >> 1, c = (chunk & 1) * 64 + kloc;
                g_woffp[j] = (oc < OFFC)
                    ? __float2half(w_off[(size_t)(oc * CINc + c) * KKn + kk])
                    : __float2half(0.f);
            }
        }
    }
}

// ---------------------------------------------------------------------------
// Kernel 2: offset conv, fp16 implicit GEMM. 512 CTAs (64-pix row tiles),
// 256 thr (8 warps), warp tile 32oc x 8pix, 64-k chunks.
// ---------------------------------------------------------------------------
__global__ __launch_bounds__(256) void k_offset2() {
    extern __shared__ __half smh[];
    const int tid = threadIdx.x;
    const int wid = tid >> 5, lane = tid & 31;
    const int g = lane >> 2, tc = lane & 3;
    const int wn = wid;

    const int tile = blockIdx.x;          // 0..511
    const int b = tile >> 6;
    const int y0 = tile & 63;
    const int hw0 = y0 * 64;
    const __half* xhb = g_xh + (size_t)b * HWn * CINc;

    const uint32_t sbase = s2u(smh);
    const uint32_t laneA = LANE_OFF_A(lane);
    const uint32_t laneB = LANE_OFF_B(lane);

    uint4 bufA;
    uint4 bufB[2];

    float acc[2][4];
    #pragma unroll
    for (int mt = 0; mt < 2; mt++)
        #pragma unroll
        for (int r = 0; r < 4; r++) acc[mt][r] = 0.f;

    auto ldg_chunk = [&](int i) {
        int kk = i >> 1, c0 = (i & 1) * 64;
        int ky = kk / 3 - 1, kx = kk % 3 - 1;
        int ys = y0 + ky;
        bool vy = (unsigned)ys < Hh;
        #pragma unroll
        for (int m = 0; m < 2; m++) {
            int e = tid + m * 256;
            int pix = e >> 3, j = e & 7;
            int xs = pix + kx;
            bool valid = vy && ((unsigned)xs < Ww);
            bufB[m] = valid
                ? *(const uint4*)(xhb + (size_t)(ys * Ww + xs) * CINc + c0 + j * 8)
                : make_uint4(0u, 0u, 0u, 0u);
        }
        bufA = *(const uint4*)(g_woffp + (size_t)i * 2048 + tid * 8);
    };
    auto sts_chunk = [&](int st) {
        __half* As = smh + st * OSTG_H;
        __half* Bs = As + OA_H;
        #pragma unroll
        for (int m = 0; m < 2; m++) {
            int e = tid + m * 256;
            int pix = e >> 3, j = e & 7;
            *(uint4*)(Bs + pix * SRH + j * 8) = bufB[m];
        }
        *(uint4*)(As + (tid >> 3) * SRH + (tid & 7) * 8) = bufA;
    };

    ldg_chunk(0); sts_chunk(0);
    ldg_chunk(1);
    __syncthreads();

    for (int i = 0; i < NCH64; i++) {
        if (i + 1 < NCH64) sts_chunk((i + 1) & 1);
        if (i + 2 < NCH64) ldg_chunk(i + 2);
        const uint32_t aAs = sbase + (uint32_t)((i & 1) * OSTG_H) * 2;
        const uint32_t aBs = aAs + OA_H * 2;
        #pragma unroll
        for (int ks = 0; ks < 4; ks++) {
            uint32_t a[2][4];
            #pragma unroll
            for (int mt = 0; mt < 2; mt++)
                ldsm_x4(a[mt], aAs + (uint32_t)((mt * 16) * SRH + ks * 16) * 2 + laneA);
            uint32_t b0, b1;
            ldsm_x2(b0, b1, aBs + (uint32_t)((wn * 8) * SRH + ks * 16) * 2 + laneB);
            #pragma unroll
            for (int mt = 0; mt < 2; mt++)
                mma_f16(acc[mt], a[mt], b0, b1);
        }
        __syncthreads();
    }

    float* ob = g_off + (size_t)b * OFFC * HWn;
    #pragma unroll
    for (int mt = 0; mt < 2; mt++) {
        int pix = hw0 + wn * 8 + tc * 2;
        int r0 = mt * 16 + g, r1 = r0 + 8;
        if (r0 < OFFC)
            *(float2*)&ob[(size_t)r0 * HWn + pix] = make_float2(acc[mt][0], acc[mt][1]);
        if (r1 < OFFC)
            *(float2*)&ob[(size_t)r1 * HWn + pix] = make_float2(acc[mt][2], acc[mt][3]);
    }
}

// ---------------------------------------------------------------------------
// Kernel 3: FUSED bilinear-gather + fp16 mma GEMM (ldmatrix + half2 blend).
// ---------------------------------------------------------------------------
__global__ __launch_bounds__(512, 1) void k_gemm(float* __restrict__ out) {
    extern __shared__ char smraw[];
    __half* smh  = (__half*)smraw;
    MetaF*  meta = (MetaF*)(smraw + 2 * GSTG_H * 2);

    const int tid = threadIdx.x;
    const int wid = tid >> 5, lane = tid & 31;
    const int wm = wid >> 3, wn = wid & 7;
    const int g = lane >> 2, tc = lane & 3;
    const int tilebase = blockIdx.x * TILE_N;
    const int b = tilebase >> 12, hw0 = tilebase & 4095;
    const int ybase = hw0 >> 6;
    const __half* xhb = g_xh + (size_t)b * HWn * CINc;

    const uint32_t sbase = s2u(smh);
    const uint32_t laneA = LANE_OFF_A(lane);
    const uint32_t laneB = LANE_OFF_B(lane);

    // ---- phase 0: bilinear metadata ----
    const float* offb = g_off + (size_t)b * OFFC * HWn;
    for (int t = tid; t < KKn * 128; t += 512) {
        int kk = t >> 7, p = t & 127;
        int hw = hw0 + p, xx = hw & 63;
        int y = ybase + (p >> 6);
        float dy = offb[(size_t)(kk * 2 + 0) * HWn + hw];
        float dx = offb[(size_t)(kk * 2 + 1) * HWn + hw];
        float ys = (float)(y - 1 + kk / 3) + dy;
        float xs = (float)(xx - 1 + kk % 3) + dx;
        float y0f = floorf(ys), x0f = floorf(xs);
        float wy = ys - y0f, wx = xs - x0f;
        int y0 = (int)y0f, x0 = (int)x0f;
        bool vy0 = (y0 >= 0) && (y0 < Hh);
        bool vy1 = (y0 + 1 >= 0) && (y0 + 1 < Hh);
        bool vx0 = (x0 >= 0) && (x0 < Ww);
        bool vx1 = (x0 + 1 >= 0) && (x0 + 1 < Ww);
        MetaF m;
        m.w0 = (vy0 && vx0) ? (1.f - wy) * (1.f - wx) : 0.f;
        m.w1 = (vy0 && vx1) ? (1.f - wy) * wx : 0.f;
        m.w2 = (vy1 && vx0) ? wy * (1.f - wx) : 0.f;
        m.w3 = (vy1 && vx1) ? wy * wx : 0.f;
        m.i0 = (vy0 && vx0) ? (y0 * Ww + x0) * CINc : 0;
        m.i1 = (vy0 && vx1) ? (y0 * Ww + x0 + 1) * CINc : 0;
        m.i2 = (vy1 && vx0) ? ((y0 + 1) * Ww + x0) * CINc : 0;
        m.i3 = (vy1 && vx1) ? ((y0 + 1) * Ww + x0 + 1) * CINc : 0;
        meta[t] = m;
    }
    __syncthreads();

    float acc[4][2][4];
    #pragma unroll
    for (int mt = 0; mt < 4; mt++)
        #pragma unroll
        for (int nt = 0; nt < 2; nt++)
            #pragma unroll
            for (int r = 0; r < 4; r++) acc[mt][nt][r] = 0.f;

    const int bpix = tid >> 2, bchq = tid & 3;

    uint4 bufA[2];
    uint4 cb[4][2];
    __half2 w0h, w1h, w2h, w3h;

    auto ldg_chunk = [&](int i) {
        #pragma unroll
        for (int m = 0; m < 2; m++) {
            int e = tid + m * 512;
            bufA[m] = *(const uint4*)(g_wtp + (size_t)i * 8192 + e * 8);
        }
        int kk = i >> 1;
        MetaF m = meta[kk * 128 + bpix];
        w0h = __float2half2_rn(m.w0);
        w1h = __float2half2_rn(m.w1);
        w2h = __float2half2_rn(m.w2);
        w3h = __float2half2_rn(m.w3);
        const __half* base = xhb + (i & 1) * 64 + bchq * 16;
        cb[0][0] = *(const uint4*)(base + m.i0);
        cb[0][1] = *(const uint4*)(base + m.i0 + 8);
        cb[1][0] = *(const uint4*)(base + m.i1);
        cb[1][1] = *(const uint4*)(base + m.i1 + 8);
        cb[2][0] = *(const uint4*)(base + m.i2);
        cb[2][1] = *(const uint4*)(base + m.i2 + 8);
        cb[3][0] = *(const uint4*)(base + m.i3);
        cb[3][1] = *(const uint4*)(base + m.i3 + 8);
    };
    auto sts_chunk = [&](int st) {
        __half* As = smh + st * GSTG_H;
        __half* Bs = As + GA_H;
        #pragma unroll
        for (int m = 0; m < 2; m++) {
            int e = tid + m * 512;
            *(uint4*)(As + (e >> 3) * SRH + (e & 7) * 8) = bufA[m];
        }
        uint4 o0, o1;
        o0.x = blend4h(cb[0][0].x, cb[1][0].x, cb[2][0].x, cb[3][0].x, w0h, w1h, w2h, w3h);
        o0.y = blend4h(cb[0][0].y, cb[1][0].y, cb[2][0].y, cb[3][0].y, w0h, w1h, w2h, w3h);
        o0.z = blend4h(cb[0][0].z, cb[1][0].z, cb[2][0].z, cb[3][0].z, w0h, w1h, w2h, w3h);
        o0.w = blend4h(cb[0][0].w, cb[1][0].w, cb[2][0].w, cb[3][0].w, w0h, w1h, w2h, w3h);
        o1.x = blend4h(cb[0][1].x, cb[1][1].x, cb[2][1].x, cb[3][1].x, w0h, w1h, w2h, w3h);
        o1.y = blend4h(cb[0][1].y, cb[1][1].y, cb[2][1].y, cb[3][1].y, w0h, w1h, w2h, w3h);
        o1.z = blend4h(cb[0][1].z, cb[1][1].z, cb[2][1].z, cb[3][1].z, w0h, w1h, w2h, w3h);
        o1.w = blend4h(cb[0][1].w, cb[1][1].w, cb[2][1].w, cb[3][1].w, w0h, w1h, w2h, w3h);
        *(uint4*)(Bs + bpix * SRH + bchq * 16) = o0;
        *(uint4*)(Bs + bpix * SRH + bchq * 16 + 8) = o1;
    };

    ldg_chunk(0); sts_chunk(0);
    ldg_chunk(1);
    __syncthreads();

    for (int i = 0; i < NCH64; i++) {
        if (i + 1 < NCH64) sts_chunk((i + 1) & 1);
        if (i + 2 < NCH64) ldg_chunk(i + 2);

        const uint32_t aAs = sbase + (uint32_t)((i & 1) * GSTG_H) * 2;
        const uint32_t aBs = aAs + GA_H * 2;
        #pragma unroll
        for (int ks = 0; ks < 4; ks++) {
            uint32_t a[4][4];
            #pragma unroll
            for (int mt = 0; mt < 4; mt++)
                ldsm_x4(a[mt], aAs + (uint32_t)((wm * 64 + mt * 16) * SRH + ks * 16) * 2 + laneA);
            #pragma unroll
            for (int nt = 0; nt < 2; nt++) {
                uint32_t b0, b1;
                ldsm_x2(b0, b1, aBs + (uint32_t)((wn * 16 + nt * 8) * SRH + ks * 16) * 2 + laneB);
                #pragma unroll
                for (int mt = 0; mt < 4; mt++)
                    mma_f16(acc[mt][nt], a[mt], b0, b1);
            }
        }
        __syncthreads();
    }

    // ---- store results ----
    #pragma unroll
    for (int mt = 0; mt < 4; mt++) {
        #pragma unroll
        for (int nt = 0; nt < 2; nt++) {
            int pix = hw0 + wn * 16 + nt * 8 + tc * 2;
            int co0 = wm * 64 + mt * 16 + g;
            *(float2*)&out[((size_t)b * COUTc + co0) * HWn + pix] =
                make_float2(acc[mt][nt][0], acc[mt][nt][1]);
            *(float2*)&out[((size_t)b * COUTc + co0 + 8) * HWn + pix] =
                make_float2(acc[mt][nt][2], acc[mt][nt][3]);
        }
    }

    // ---- deterministic BN partials ----
    float s[8], q[8];
    #pragma unroll
    for (int i = 0; i < 8; i++) { s[i] = 0.f; q[i] = 0.f; }
    #pragma unroll
    for (int mt = 0; mt < 4; mt++)
        #pragma unroll
        for (int r = 0; r < 2; r++) {
            int sl = mt * 2 + r;
            #pragma unroll
            for (int nt = 0; nt < 2; nt++) {
                float v0 = acc[mt][nt][r * 2], v1 = acc[mt][nt][r * 2 + 1];
                s[sl] += v0 + v1;
                q[sl] += v0 * v0 + v1 * v1;
            }
        }
    #pragma unroll
    for (int m = 1; m <= 2; m <<= 1)
        #pragma unroll
        for (int i = 0; i < 8; i++) {
            s[i] += __shfl_xor_sync(0xFFFFFFFF, s[i], m);
            q[i] += __shfl_xor_sync(0xFFFFFFFF, q[i], m);
        }

    __syncthreads();
    float* sb = (float*)smraw;
    float* qb = sb + 1024;
    if (tc == 0) {
        #pragma unroll
        for (int mt = 0; mt < 4; mt++)
            #pragma unroll
            for (int r = 0; r < 2; r++) {
                int cl = mt * 16 + r * 8 + g;
                sb[wid * 64 + cl] = s[mt * 2 + r];
                qb[wid * 64 + cl] = q[mt * 2 + r];
            }
    }
    __syncthreads();
    if (tid < COUTc) {
        int co = tid;
        float ss = 0.f, qq = 0.f;
        #pragma unroll
        for (int w = 0; w < 8; w++) {
            ss += sb[((co >> 6) * 8 + w) * 64 + (co & 63)];
            qq += qb[((co >> 6) * 8 + w) * 64 + (co & 63)];
        }
        g_psum[co * 256 + blockIdx.x] = ss;
        g_psq [co * 256 + blockIdx.x] = qq;
    }
}

// ---------------------------------------------------------------------------
// Kernel 4: fused BN-finalize + normalize + SiLU.
// Each CTA's pixels all belong to ONE channel (both halves: n4/2 ≡ 0 mod
// 128*1024), so the CTA block-reduces that channel's 256 partials itself.
// ---------------------------------------------------------------------------
__global__ __launch_bounds__(256) void k_norm(float* __restrict__ out,
                                              const float* __restrict__ gamma,
                                              const float* __restrict__ beta) {
    __shared__ float rs[8], rq[8];
    __shared__ float bc[2];
    const int n4 = Bn * COUTc * HWn / 4;   // 1048576
    const int tid = threadIdx.x;
    const int idx = blockIdx.x * 256 + tid;
    const int co  = (idx >> 10) & 127;     // constant across the CTA
    float4* o4 = (float4*)out;

    // prefetch data (overlaps the reduction below)
    float4 v0 = o4[idx];
    float4 v1 = o4[idx + n4 / 2];

    // block-reduce this channel's partials
    float s = g_psum[co * 256 + tid];
    float q = g_psq [co * 256 + tid];
    #pragma unroll
    for (int m = 16; m > 0; m >>= 1) {
        s += __shfl_xor_sync(0xFFFFFFFF, s, m);
        q += __shfl_xor_sync(0xFFFFFFFF, q, m);
    }
    if ((tid & 31) == 0) { rs[tid >> 5] = s; rq[tid >> 5] = q; }
    __syncthreads();
    if (tid == 0) {
        float ss = 0.f, qq = 0.f;
        #pragma unroll
        for (int w = 0; w < 8; w++) { ss += rs[w]; qq += rq[w]; }
        const float inv_n = 1.f / (float)NPIX;
        float mean = ss * inv_n;
        float var  = qq * inv_n - mean * mean;
        float sc   = gamma[co] * rsqrtf(var + 1e-5f);
        bc[0] = sc;
        bc[1] = beta[co] - mean * sc;
    }
    __syncthreads();
    const float sc = bc[0], sh = bc[1];

    float u;
    u = v0.x * sc + sh; v0.x = u / (1.f + __expf(-u));
    u = v0.y * sc + sh; v0.y = u / (1.f + __expf(-u));
    u = v0.z * sc + sh; v0.z = u / (1.f + __expf(-u));
    u = v0.w * sc + sh; v0.w = u / (1.f + __expf(-u));
    u = v1.x * sc + sh; v1.x = u / (1.f + __expf(-u));
    u = v1.y * sc + sh; v1.y = u / (1.f + __expf(-u));
    u = v1.z * sc + sh; v1.z = u / (1.f + __expf(-u));
    u = v1.w * sc + sh; v1.w = u / (1.f + __expf(-u));
    o4[idx] = v0;
    o4[idx + n4 / 2] = v1;
}

// ---------------------------------------------------------------------------
extern "C" void kernel_launch(void* const* d_in, const int* in_sizes, int n_in,
                              void* d_out, int out_size) {
    const float* x     = (const float*)d_in[0];
    const float* w_off = (const float*)d_in[1];
    const float* w_def = (const float*)d_in[2];
    // d_in[3] = b_def: exactly absorbed by batch-norm mean subtraction
    const float* gamma = (const float*)d_in[4];
    const float* beta  = (const float*)d_in[5];
    float* out = (float*)d_out;

    cudaFuncSetAttribute(k_gemm, cudaFuncAttributeMaxDynamicSharedMemorySize, GEMM_SMEM);
    cudaFuncSetAttribute(k_offset2, cudaFuncAttributeMaxDynamicSharedMemorySize, OFF_SMEM);

    k_prep<<<4096 + (NCH64 * 10240 + 255) / 256, 256>>>(x, w_def, w_off);

    k_offset2<<<512, 256, OFF_SMEM>>>();

    k_gemm<<<NPIX / TILE_N, 512, GEMM_SMEM>>>(out);

    k_norm<<<(Bn * COUTc * HWn / 4) / 512, 256>>>(out, gamma, beta);
}